// round 3
// baseline (speedup 1.0000x reference)
#include <cuda_runtime.h>
#include <math.h>

#define DM   1024
#define NH   16
#define HD   64
#define SEQ  2048
#define BATCH 2
#define MROWS (BATCH*SEQ)   // 4096

// Scratch (static device arrays — no allocation allowed)
__device__ float g_q[MROWS*DM];
__device__ float g_k[MROWS*DM];
__device__ float g_v[MROWS*DM];
__device__ float g_ctx[MROWS*DM];

// ---------------------------------------------------------------------------
// SGEMM (NT): C[M,N] = A[M,K] @ B[N,K]^T (+ bias). M,N mult of 128, K mult of 16.
// ---------------------------------------------------------------------------
template<bool HAS_BIAS>
__global__ void __launch_bounds__(256, 2) gemm_nt_kernel(
    const float* __restrict__ A, const float* __restrict__ B,
    const float* __restrict__ bias, float* __restrict__ C,
    int M, int N, int K)
{
    __shared__ float As[16][132];
    __shared__ float Bs[16][132];
    const int bm = blockIdx.y * 128;
    const int bn = blockIdx.x * 128;
    const int tid = threadIdx.x;
    const int tx = tid & 15, ty = tid >> 4;

    float acc[8][8];
    #pragma unroll
    for (int i = 0; i < 8; i++)
        #pragma unroll
        for (int j = 0; j < 8; j++) acc[i][j] = 0.f;

    for (int k0 = 0; k0 < K; k0 += 16) {
        #pragma unroll
        for (int it = 0; it < 2; it++) {
            int idx = tid + it * 256;          // 0..511
            int m = idx >> 2, kq = idx & 3;
            const float4 va = *reinterpret_cast<const float4*>(
                &A[(size_t)(bm + m) * K + k0 + kq * 4]);
            As[kq*4+0][m] = va.x; As[kq*4+1][m] = va.y;
            As[kq*4+2][m] = va.z; As[kq*4+3][m] = va.w;
            const float4 vb = *reinterpret_cast<const float4*>(
                &B[(size_t)(bn + m) * K + k0 + kq * 4]);
            Bs[kq*4+0][m] = vb.x; Bs[kq*4+1][m] = vb.y;
            Bs[kq*4+2][m] = vb.z; Bs[kq*4+3][m] = vb.w;
        }
        __syncthreads();
        #pragma unroll
        for (int k = 0; k < 16; k++) {
            float a[8], b[8];
            *reinterpret_cast<float4*>(&a[0]) = *reinterpret_cast<float4*>(&As[k][ty*8]);
            *reinterpret_cast<float4*>(&a[4]) = *reinterpret_cast<float4*>(&As[k][ty*8+4]);
            *reinterpret_cast<float4*>(&b[0]) = *reinterpret_cast<float4*>(&Bs[k][tx*8]);
            *reinterpret_cast<float4*>(&b[4]) = *reinterpret_cast<float4*>(&Bs[k][tx*8+4]);
            #pragma unroll
            for (int i = 0; i < 8; i++)
                #pragma unroll
                for (int j = 0; j < 8; j++)
                    acc[i][j] += a[i] * b[j];
        }
        __syncthreads();
    }

    #pragma unroll
    for (int i = 0; i < 8; i++) {
        int row = bm + ty * 8 + i;
        #pragma unroll
        for (int j4 = 0; j4 < 2; j4++) {
            int col = bn + tx * 8 + j4 * 4;
            float4 o;
            o.x = acc[i][j4*4+0]; o.y = acc[i][j4*4+1];
            o.z = acc[i][j4*4+2]; o.w = acc[i][j4*4+3];
            if (HAS_BIAS) {
                o.x += bias[col+0]; o.y += bias[col+1];
                o.z += bias[col+2]; o.w += bias[col+3];
            }
            *reinterpret_cast<float4*>(&C[(size_t)row * N + col]) = o;
        }
    }
}

// ---------------------------------------------------------------------------
// RoPE: interleaved pairs within each head, applied in-place to q and k.
// ---------------------------------------------------------------------------
__global__ void rope_kernel(float* __restrict__ q, float* __restrict__ k, int npairs)
{
    int idx = blockIdx.x * blockDim.x + threadIdx.x;
    if (idx >= npairs) return;
    int row = idx >> 9;          // / (DM/2)
    int pc  = idx & 511;
    int h   = pc >> 5;           // 32 pairs per head
    int i   = pc & 31;
    int s   = row & (SEQ - 1);

    float theta = powf(10000.0f, -(float)(2 * i) * (1.0f / 64.0f));
    float ang = (float)s * theta;
    float sn, cs;
    sincosf(ang, &sn, &cs);

    size_t off = (size_t)row * DM + h * HD + 2 * i;
    float2 vq = *reinterpret_cast<float2*>(q + off);
    float2 rq;
    rq.x = vq.x * cs - vq.y * sn;
    rq.y = vq.y * cs + vq.x * sn;
    *reinterpret_cast<float2*>(q + off) = rq;

    float2 vk = *reinterpret_cast<float2*>(k + off);
    float2 rk;
    rk.x = vk.x * cs - vk.y * sn;
    rk.y = vk.y * cs + vk.x * sn;
    *reinterpret_cast<float2*>(k + off) = rk;
}

// ---------------------------------------------------------------------------
// Flash attention (causal): block = (query tile 64, head, batch).
// Threads 16x16; each thread owns a 4x4 score micro-tile and 4x4 of O.
// ---------------------------------------------------------------------------
__global__ void __launch_bounds__(256, 2) attn_kernel(
    const float* __restrict__ q, const float* __restrict__ k,
    const float* __restrict__ v, const int* __restrict__ mask,
    float* __restrict__ ctx)
{
    extern __shared__ float sm[];
    float (*Qs)[68] = reinterpret_cast<float(*)[68]>(sm);
    float (*Ks)[68] = reinterpret_cast<float(*)[68]>(sm + 64*68);
    float (*Vs)[68] = reinterpret_cast<float(*)[68]>(sm + 2*64*68);
    float (*Ps)[68] = reinterpret_cast<float(*)[68]>(sm + 3*64*68);
    int* msk = reinterpret_cast<int*>(sm + 4*64*68);

    const int qt = blockIdx.x, h = blockIdx.y, b = blockIdx.z;
    const int tid = threadIdx.x;
    const int tx = tid & 15, ty = tid >> 4;

    // Load Q tile (64 rows x 64 dims)
    #pragma unroll
    for (int it = 0; it < 4; it++) {
        int idx = tid + it * 256;          // 0..1023 float4s
        int r = idx >> 4, c4 = idx & 15;
        const float4 vq = *reinterpret_cast<const float4*>(
            &q[(size_t)(b * SEQ + qt * 64 + r) * DM + h * HD + c4 * 4]);
        *reinterpret_cast<float4*>(&Qs[r][c4 * 4]) = vq;
    }

    float o[4][4];
    #pragma unroll
    for (int i = 0; i < 4; i++)
        #pragma unroll
        for (int j = 0; j < 4; j++) o[i][j] = 0.f;
    float mrow[4], lrow[4];
    #pragma unroll
    for (int i = 0; i < 4; i++) { mrow[i] = -1e30f; lrow[i] = 0.f; }

    for (int kt = 0; kt <= qt; kt++) {
        __syncthreads();   // prior PV reads done before overwriting K/V
        #pragma unroll
        for (int it = 0; it < 4; it++) {
            int idx = tid + it * 256;
            int r = idx >> 4, c4 = idx & 15;
            size_t goff = (size_t)(b * SEQ + kt * 64 + r) * DM + h * HD + c4 * 4;
            *reinterpret_cast<float4*>(&Ks[r][c4 * 4]) =
                *reinterpret_cast<const float4*>(&k[goff]);
            *reinterpret_cast<float4*>(&Vs[r][c4 * 4]) =
                *reinterpret_cast<const float4*>(&v[goff]);
        }
        if (tid < 64) msk[tid] = mask[b * SEQ + kt * 64 + tid];
        __syncthreads();

        // S = Q K^T
        float sc[4][4];
        #pragma unroll
        for (int i = 0; i < 4; i++)
            #pragma unroll
            for (int j = 0; j < 4; j++) sc[i][j] = 0.f;
        #pragma unroll
        for (int d4 = 0; d4 < 16; d4++) {
            float4 qv[4], kv[4];
            #pragma unroll
            for (int i = 0; i < 4; i++)
                qv[i] = *reinterpret_cast<float4*>(&Qs[ty*4+i][d4*4]);
            #pragma unroll
            for (int j = 0; j < 4; j++)
                kv[j] = *reinterpret_cast<float4*>(&Ks[tx*4+j][d4*4]);
            #pragma unroll
            for (int i = 0; i < 4; i++)
                #pragma unroll
                for (int j = 0; j < 4; j++)
                    sc[i][j] += qv[i].x*kv[j].x + qv[i].y*kv[j].y
                              + qv[i].z*kv[j].z + qv[i].w*kv[j].w;
        }

        // scale + causal + padding mask
        const int qb = qt * 64 + ty * 4;
        const int kb = kt * 64 + tx * 4;
        #pragma unroll
        for (int i = 0; i < 4; i++)
            #pragma unroll
            for (int j = 0; j < 4; j++) {
                float val = sc[i][j] * 0.125f;   // 1/sqrt(64)
                bool ok = (kb + j <= qb + i) && (msk[tx*4+j] != 0);
                sc[i][j] = ok ? val : -1e30f;
            }

        // Online softmax; 4 threads-per-row groups of 16 lanes
        #pragma unroll
        for (int i = 0; i < 4; i++) {
            float mx = fmaxf(fmaxf(sc[i][0], sc[i][1]), fmaxf(sc[i][2], sc[i][3]));
            #pragma unroll
            for (int off = 8; off >= 1; off >>= 1)
                mx = fmaxf(mx, __shfl_xor_sync(0xffffffffu, mx, off));
            float nm = fmaxf(mrow[i], mx);
            float alpha = __expf(mrow[i] - nm);
            float rs = 0.f;
            #pragma unroll
            for (int j = 0; j < 4; j++) { sc[i][j] = __expf(sc[i][j] - nm); rs += sc[i][j]; }
            #pragma unroll
            for (int off = 8; off >= 1; off >>= 1)
                rs += __shfl_xor_sync(0xffffffffu, rs, off);
            lrow[i] = lrow[i] * alpha + rs;
            mrow[i] = nm;
            #pragma unroll
            for (int j = 0; j < 4; j++) o[i][j] *= alpha;
            *reinterpret_cast<float4*>(&Ps[ty*4+i][tx*4]) =
                make_float4(sc[i][0], sc[i][1], sc[i][2], sc[i][3]);
        }
        __syncthreads();

        // O += P V
        #pragma unroll 8
        for (int kk = 0; kk < 64; kk++) {
            float4 vv = *reinterpret_cast<float4*>(&Vs[kk][tx*4]);
            #pragma unroll
            for (int i = 0; i < 4; i++) {
                float p = Ps[ty*4+i][kk];
                o[i][0] += p * vv.x; o[i][1] += p * vv.y;
                o[i][2] += p * vv.z; o[i][3] += p * vv.w;
            }
        }
    }

    #pragma unroll
    for (int i = 0; i < 4; i++) {
        float inv = (lrow[i] > 0.f) ? 1.0f / lrow[i] : 0.f;
        float4 out = make_float4(o[i][0]*inv, o[i][1]*inv, o[i][2]*inv, o[i][3]*inv);
        size_t row = (size_t)(b * SEQ + qt * 64 + ty * 4 + i);
        *reinterpret_cast<float4*>(&ctx[row * DM + h * HD + tx * 4]) = out;
    }
}

// ---------------------------------------------------------------------------
extern "C" void kernel_launch(void* const* d_in, const int* in_sizes, int n_in,
                              void* d_out, int out_size)
{
    const float* Q  = (const float*)d_in[0];
    const float* K  = (const float*)d_in[1];
    const float* V  = (const float*)d_in[2];
    const int*   am = (const int*)  d_in[3];
    const float* Wq = (const float*)d_in[4];
    const float* Wk = (const float*)d_in[5];
    const float* Wv = (const float*)d_in[6];
    const float* Wo = (const float*)d_in[7];
    const float* bo = (const float*)d_in[8];
    float* out = (float*)d_out;

    float *q, *k, *v, *ctx;
    cudaGetSymbolAddress((void**)&q,   g_q);
    cudaGetSymbolAddress((void**)&k,   g_k);
    cudaGetSymbolAddress((void**)&v,   g_v);
    cudaGetSymbolAddress((void**)&ctx, g_ctx);

    const dim3 gemm_grid(DM / 128, MROWS / 128);   // (8, 32)
    gemm_nt_kernel<false><<<gemm_grid, 256>>>(Q, Wq, nullptr, q, MROWS, DM, DM);
    gemm_nt_kernel<false><<<gemm_grid, 256>>>(K, Wk, nullptr, k, MROWS, DM, DM);
    gemm_nt_kernel<false><<<gemm_grid, 256>>>(V, Wv, nullptr, v, MROWS, DM, DM);

    const int npairs = MROWS * (DM / 2);
    rope_kernel<<<(npairs + 255) / 256, 256>>>(q, k, npairs);

    const int smem_bytes = (4 * 64 * 68) * (int)sizeof(float) + 64 * (int)sizeof(int);
    cudaFuncSetAttribute(attn_kernel,
                         cudaFuncAttributeMaxDynamicSharedMemorySize, smem_bytes);
    attn_kernel<<<dim3(SEQ / 64, NH, BATCH), 256, smem_bytes>>>(q, k, v, am, ctx);

    gemm_nt_kernel<true><<<gemm_grid, 256>>>(ctx, Wo, bo, out, MROWS, DM, DM);
}

// round 4
// speedup vs baseline: 1.2035x; 1.2035x over previous
#include <cuda_runtime.h>
#include <cuda_bf16.h>
#include <math.h>

#define DM   1024
#define NH   16
#define HD   64
#define SEQ  2048
#define BATCH 2
#define MROWS (BATCH*SEQ)   // 4096

// Scratch (static device arrays — no allocation allowed)
__device__ float g_q[MROWS*DM];
__device__ float g_k[MROWS*DM];
__device__ float g_v[MROWS*DM];
__device__ float g_ctx[MROWS*DM];

// ===========================================================================
// bf16x3 tensor-core GEMM (NT): C[M,N] = A[M,K] @ B[N,K]^T (+bias)
// Split each fp32 operand into hi+lo bf16; compute hh + hl + lh (drop ll).
// Block tile 128x128x32, 8 warps (4x2), warp tile 32x64 (2x8 m16n8 tiles).
// ===========================================================================
#define BM 128
#define BN 128
#define BK 32
#define LDS_K 40   // padded stride in bf16 halves (20 words: conflict-free frags)

__device__ __forceinline__ void mma_bf16(float c[4], const unsigned a[4], const unsigned b[2])
{
    asm volatile(
        "mma.sync.aligned.m16n8k16.row.col.f32.bf16.bf16.f32 "
        "{%0,%1,%2,%3}, {%4,%5,%6,%7}, {%8,%9}, {%0,%1,%2,%3};\n"
        : "+f"(c[0]), "+f"(c[1]), "+f"(c[2]), "+f"(c[3])
        : "r"(a[0]), "r"(a[1]), "r"(a[2]), "r"(a[3]), "r"(b[0]), "r"(b[1]));
}

__device__ __forceinline__ void split_pair(float x, float y, unsigned &hi, unsigned &lo)
{
    __nv_bfloat16 hx = __float2bfloat16_rn(x);
    __nv_bfloat16 hy = __float2bfloat16_rn(y);
    float rx = x - __bfloat162float(hx);
    float ry = y - __bfloat162float(hy);
    __nv_bfloat162 h; h.x = hx; h.y = hy;
    __nv_bfloat162 l; l.x = __float2bfloat16_rn(rx); l.y = __float2bfloat16_rn(ry);
    hi = *reinterpret_cast<unsigned*>(&h);
    lo = *reinterpret_cast<unsigned*>(&l);
}

template<bool HAS_BIAS>
__global__ void __launch_bounds__(256) gemm_bf16x3_kernel(
    const float* __restrict__ A, const float* __restrict__ B,
    const float* __restrict__ bias, float* __restrict__ C,
    int M, int N, int K)
{
    __shared__ __nv_bfloat16 Ah[BM * LDS_K];
    __shared__ __nv_bfloat16 Al[BM * LDS_K];
    __shared__ __nv_bfloat16 Bh[BN * LDS_K];
    __shared__ __nv_bfloat16 Bl[BN * LDS_K];

    const int tid  = threadIdx.x;
    const int lane = tid & 31;
    const int warp = tid >> 5;
    const int wm   = warp >> 1;   // 0..3 -> 32-row strip
    const int wn   = warp & 1;    // 0..1 -> 64-col strip
    const int bm   = blockIdx.y * BM;
    const int bn   = blockIdx.x * BN;

    const int lr = lane >> 2;         // 0..7
    const int lc = (lane & 3) * 2;    // 0,2,4,6

    float acc[2][8][4];
    #pragma unroll
    for (int mt = 0; mt < 2; mt++)
        #pragma unroll
        for (int nt = 0; nt < 8; nt++)
            #pragma unroll
            for (int r = 0; r < 4; r++) acc[mt][nt][r] = 0.f;

    for (int k0 = 0; k0 < K; k0 += BK) {
        __syncthreads();
        // Global -> shared with fp32 -> bf16 hi/lo split.
        // A: 128x32 floats = 1024 float4, B same. 256 threads: 4 float4 each.
        #pragma unroll
        for (int it = 0; it < 4; it++) {
            int idx = tid + it * 256;        // 0..1023
            int row = idx >> 3;              // 0..127
            int q   = idx & 7;               // float4 within row (k = q*4)
            int soff = row * LDS_K + q * 4;

            float4 va = *reinterpret_cast<const float4*>(
                &A[(size_t)(bm + row) * K + k0 + q * 4]);
            unsigned h0, l0, h1, l1;
            split_pair(va.x, va.y, h0, l0);
            split_pair(va.z, va.w, h1, l1);
            *reinterpret_cast<unsigned*>(&Ah[soff])     = h0;
            *reinterpret_cast<unsigned*>(&Ah[soff + 2]) = h1;
            *reinterpret_cast<unsigned*>(&Al[soff])     = l0;
            *reinterpret_cast<unsigned*>(&Al[soff + 2]) = l1;

            float4 vb = *reinterpret_cast<const float4*>(
                &B[(size_t)(bn + row) * K + k0 + q * 4]);
            split_pair(vb.x, vb.y, h0, l0);
            split_pair(vb.z, vb.w, h1, l1);
            *reinterpret_cast<unsigned*>(&Bh[soff])     = h0;
            *reinterpret_cast<unsigned*>(&Bh[soff + 2]) = h1;
            *reinterpret_cast<unsigned*>(&Bl[soff])     = l0;
            *reinterpret_cast<unsigned*>(&Bl[soff + 2]) = l1;
        }
        __syncthreads();

        #pragma unroll
        for (int ks = 0; ks < BK; ks += 16) {
            unsigned ah[2][4], al[2][4];
            #pragma unroll
            for (int mt = 0; mt < 2; mt++) {
                int r = wm * 32 + mt * 16 + lr;
                const __nv_bfloat16* pH = &Ah[r * LDS_K + ks + lc];
                const __nv_bfloat16* pL = &Al[r * LDS_K + ks + lc];
                ah[mt][0] = *reinterpret_cast<const unsigned*>(pH);
                ah[mt][1] = *reinterpret_cast<const unsigned*>(pH + 8 * LDS_K);
                ah[mt][2] = *reinterpret_cast<const unsigned*>(pH + 8);
                ah[mt][3] = *reinterpret_cast<const unsigned*>(pH + 8 * LDS_K + 8);
                al[mt][0] = *reinterpret_cast<const unsigned*>(pL);
                al[mt][1] = *reinterpret_cast<const unsigned*>(pL + 8 * LDS_K);
                al[mt][2] = *reinterpret_cast<const unsigned*>(pL + 8);
                al[mt][3] = *reinterpret_cast<const unsigned*>(pL + 8 * LDS_K + 8);
            }
            unsigned bh[8][2], bl[8][2];
            #pragma unroll
            for (int nt = 0; nt < 8; nt++) {
                int c = wn * 64 + nt * 8 + lr;
                const __nv_bfloat16* pH = &Bh[c * LDS_K + ks + lc];
                const __nv_bfloat16* pL = &Bl[c * LDS_K + ks + lc];
                bh[nt][0] = *reinterpret_cast<const unsigned*>(pH);
                bh[nt][1] = *reinterpret_cast<const unsigned*>(pH + 8);
                bl[nt][0] = *reinterpret_cast<const unsigned*>(pL);
                bl[nt][1] = *reinterpret_cast<const unsigned*>(pL + 8);
            }
            #pragma unroll
            for (int mt = 0; mt < 2; mt++)
                #pragma unroll
                for (int nt = 0; nt < 8; nt++) {
                    mma_bf16(acc[mt][nt], ah[mt], bh[nt]);
                    mma_bf16(acc[mt][nt], ah[mt], bl[nt]);
                    mma_bf16(acc[mt][nt], al[mt], bh[nt]);
                }
        }
    }

    // Epilogue: each lane owns (row, col 2c..2c+1) and (row+8, same cols) per tile.
    #pragma unroll
    for (int mt = 0; mt < 2; mt++) {
        #pragma unroll
        for (int nt = 0; nt < 8; nt++) {
            int row = bm + wm * 32 + mt * 16 + lr;
            int col = bn + wn * 64 + nt * 8 + lc;
            float2 v0 = make_float2(acc[mt][nt][0], acc[mt][nt][1]);
            float2 v1 = make_float2(acc[mt][nt][2], acc[mt][nt][3]);
            if (HAS_BIAS) {
                float b0 = bias[col], b1 = bias[col + 1];
                v0.x += b0; v0.y += b1;
                v1.x += b0; v1.y += b1;
            }
            *reinterpret_cast<float2*>(&C[(size_t)row * N + col])       = v0;
            *reinterpret_cast<float2*>(&C[(size_t)(row + 8) * N + col]) = v1;
        }
    }
}

// ---------------------------------------------------------------------------
// RoPE: interleaved pairs within each head, applied in-place to q and k.
// ---------------------------------------------------------------------------
__global__ void rope_kernel(float* __restrict__ q, float* __restrict__ k, int npairs)
{
    int idx = blockIdx.x * blockDim.x + threadIdx.x;
    if (idx >= npairs) return;
    int row = idx >> 9;          // / (DM/2)
    int pc  = idx & 511;
    int h   = pc >> 5;           // 32 pairs per head
    int i   = pc & 31;
    int s   = row & (SEQ - 1);

    float theta = powf(10000.0f, -(float)(2 * i) * (1.0f / 64.0f));
    float ang = (float)s * theta;
    float sn, cs;
    sincosf(ang, &sn, &cs);

    size_t off = (size_t)row * DM + h * HD + 2 * i;
    float2 vq = *reinterpret_cast<float2*>(q + off);
    float2 rq;
    rq.x = vq.x * cs - vq.y * sn;
    rq.y = vq.y * cs + vq.x * sn;
    *reinterpret_cast<float2*>(q + off) = rq;

    float2 vk = *reinterpret_cast<float2*>(k + off);
    float2 rk;
    rk.x = vk.x * cs - vk.y * sn;
    rk.y = vk.y * cs + vk.x * sn;
    *reinterpret_cast<float2*>(k + off) = rk;
}

// ---------------------------------------------------------------------------
// Flash attention (causal): block = (query tile 64, head, batch).
// Threads 16x16; each thread owns a 4x4 score micro-tile and 4x4 of O.
// ---------------------------------------------------------------------------
__global__ void __launch_bounds__(256, 2) attn_kernel(
    const float* __restrict__ q, const float* __restrict__ k,
    const float* __restrict__ v, const int* __restrict__ mask,
    float* __restrict__ ctx)
{
    extern __shared__ float sm[];
    float (*Qs)[68] = reinterpret_cast<float(*)[68]>(sm);
    float (*Ks)[68] = reinterpret_cast<float(*)[68]>(sm + 64*68);
    float (*Vs)[68] = reinterpret_cast<float(*)[68]>(sm + 2*64*68);
    float (*Ps)[68] = reinterpret_cast<float(*)[68]>(sm + 3*64*68);
    int* msk = reinterpret_cast<int*>(sm + 4*64*68);

    const int qt = blockIdx.x, h = blockIdx.y, b = blockIdx.z;
    const int tid = threadIdx.x;
    const int tx = tid & 15, ty = tid >> 4;

    #pragma unroll
    for (int it = 0; it < 4; it++) {
        int idx = tid + it * 256;
        int r = idx >> 4, c4 = idx & 15;
        const float4 vq = *reinterpret_cast<const float4*>(
            &q[(size_t)(b * SEQ + qt * 64 + r) * DM + h * HD + c4 * 4]);
        *reinterpret_cast<float4*>(&Qs[r][c4 * 4]) = vq;
    }

    float o[4][4];
    #pragma unroll
    for (int i = 0; i < 4; i++)
        #pragma unroll
        for (int j = 0; j < 4; j++) o[i][j] = 0.f;
    float mrow[4], lrow[4];
    #pragma unroll
    for (int i = 0; i < 4; i++) { mrow[i] = -1e30f; lrow[i] = 0.f; }

    for (int kt = 0; kt <= qt; kt++) {
        __syncthreads();
        #pragma unroll
        for (int it = 0; it < 4; it++) {
            int idx = tid + it * 256;
            int r = idx >> 4, c4 = idx & 15;
            size_t goff = (size_t)(b * SEQ + kt * 64 + r) * DM + h * HD + c4 * 4;
            *reinterpret_cast<float4*>(&Ks[r][c4 * 4]) =
                *reinterpret_cast<const float4*>(&k[goff]);
            *reinterpret_cast<float4*>(&Vs[r][c4 * 4]) =
                *reinterpret_cast<const float4*>(&v[goff]);
        }
        if (tid < 64) msk[tid] = mask[b * SEQ + kt * 64 + tid];
        __syncthreads();

        float sc[4][4];
        #pragma unroll
        for (int i = 0; i < 4; i++)
            #pragma unroll
            for (int j = 0; j < 4; j++) sc[i][j] = 0.f;
        #pragma unroll
        for (int d4 = 0; d4 < 16; d4++) {
            float4 qv[4], kv[4];
            #pragma unroll
            for (int i = 0; i < 4; i++)
                qv[i] = *reinterpret_cast<float4*>(&Qs[ty*4+i][d4*4]);
            #pragma unroll
            for (int j = 0; j < 4; j++)
                kv[j] = *reinterpret_cast<float4*>(&Ks[tx*4+j][d4*4]);
            #pragma unroll
            for (int i = 0; i < 4; i++)
                #pragma unroll
                for (int j = 0; j < 4; j++)
                    sc[i][j] += qv[i].x*kv[j].x + qv[i].y*kv[j].y
                              + qv[i].z*kv[j].z + qv[i].w*kv[j].w;
        }

        const int qb = qt * 64 + ty * 4;
        const int kb = kt * 64 + tx * 4;
        #pragma unroll
        for (int i = 0; i < 4; i++)
            #pragma unroll
            for (int j = 0; j < 4; j++) {
                float val = sc[i][j] * 0.125f;
                bool ok = (kb + j <= qb + i) && (msk[tx*4+j] != 0);
                sc[i][j] = ok ? val : -1e30f;
            }

        #pragma unroll
        for (int i = 0; i < 4; i++) {
            float mx = fmaxf(fmaxf(sc[i][0], sc[i][1]), fmaxf(sc[i][2], sc[i][3]));
            #pragma unroll
            for (int off = 8; off >= 1; off >>= 1)
                mx = fmaxf(mx, __shfl_xor_sync(0xffffffffu, mx, off));
            float nm = fmaxf(mrow[i], mx);
            float alpha = __expf(mrow[i] - nm);
            float rs = 0.f;
            #pragma unroll
            for (int j = 0; j < 4; j++) { sc[i][j] = __expf(sc[i][j] - nm); rs += sc[i][j]; }
            #pragma unroll
            for (int off = 8; off >= 1; off >>= 1)
                rs += __shfl_xor_sync(0xffffffffu, rs, off);
            lrow[i] = lrow[i] * alpha + rs;
            mrow[i] = nm;
            #pragma unroll
            for (int j = 0; j < 4; j++) o[i][j] *= alpha;
            *reinterpret_cast<float4*>(&Ps[ty*4+i][tx*4]) =
                make_float4(sc[i][0], sc[i][1], sc[i][2], sc[i][3]);
        }
        __syncthreads();

        #pragma unroll 8
        for (int kk = 0; kk < 64; kk++) {
            float4 vv = *reinterpret_cast<float4*>(&Vs[kk][tx*4]);
            #pragma unroll
            for (int i = 0; i < 4; i++) {
                float p = Ps[ty*4+i][kk];
                o[i][0] += p * vv.x; o[i][1] += p * vv.y;
                o[i][2] += p * vv.z; o[i][3] += p * vv.w;
            }
        }
    }

    #pragma unroll
    for (int i = 0; i < 4; i++) {
        float inv = (lrow[i] > 0.f) ? 1.0f / lrow[i] : 0.f;
        float4 out = make_float4(o[i][0]*inv, o[i][1]*inv, o[i][2]*inv, o[i][3]*inv);
        size_t row = (size_t)(b * SEQ + qt * 64 + ty * 4 + i);
        *reinterpret_cast<float4*>(&ctx[row * DM + h * HD + tx * 4]) = out;
    }
}

// ---------------------------------------------------------------------------
extern "C" void kernel_launch(void* const* d_in, const int* in_sizes, int n_in,
                              void* d_out, int out_size)
{
    const float* Q  = (const float*)d_in[0];
    const float* K  = (const float*)d_in[1];
    const float* V  = (const float*)d_in[2];
    const int*   am = (const int*)  d_in[3];
    const float* Wq = (const float*)d_in[4];
    const float* Wk = (const float*)d_in[5];
    const float* Wv = (const float*)d_in[6];
    const float* Wo = (const float*)d_in[7];
    const float* bo = (const float*)d_in[8];
    float* out = (float*)d_out;

    float *q, *k, *v, *ctx;
    cudaGetSymbolAddress((void**)&q,   g_q);
    cudaGetSymbolAddress((void**)&k,   g_k);
    cudaGetSymbolAddress((void**)&v,   g_v);
    cudaGetSymbolAddress((void**)&ctx, g_ctx);

    const dim3 gemm_grid(DM / BN, MROWS / BM);   // (8, 32)
    gemm_bf16x3_kernel<false><<<gemm_grid, 256>>>(Q, Wq, nullptr, q, MROWS, DM, DM);
    gemm_bf16x3_kernel<false><<<gemm_grid, 256>>>(K, Wk, nullptr, k, MROWS, DM, DM);
    gemm_bf16x3_kernel<false><<<gemm_grid, 256>>>(V, Wv, nullptr, v, MROWS, DM, DM);

    const int npairs = MROWS * (DM / 2);
    rope_kernel<<<(npairs + 255) / 256, 256>>>(q, k, npairs);

    const int smem_bytes = (4 * 64 * 68) * (int)sizeof(float) + 64 * (int)sizeof(int);
    cudaFuncSetAttribute(attn_kernel,
                         cudaFuncAttributeMaxDynamicSharedMemorySize, smem_bytes);
    attn_kernel<<<dim3(SEQ / 64, NH, BATCH), 256, smem_bytes>>>(q, k, v, am, ctx);

    gemm_bf16x3_kernel<true><<<gemm_grid, 256>>>(ctx, Wo, bo, out, MROWS, DM, DM);
}

// round 5
// speedup vs baseline: 1.3694x; 1.1378x over previous
#include <cuda_runtime.h>
#include <cuda_bf16.h>
#include <math.h>

#define DM   1024
#define NH   16
#define HD   64
#define SEQ  2048
#define BATCH 2
#define MROWS (BATCH*SEQ)   // 4096

// Scratch (static device arrays — no allocation allowed)
__device__ float g_q[MROWS*DM];
__device__ float g_k[MROWS*DM];
__device__ float g_v[MROWS*DM];
__device__ float g_ctx[MROWS*DM];
// bf16 hi/lo staging (reused across the 4 GEMMs, which run sequentially)
__device__ __nv_bfloat16 g_ah[MROWS*DM];
__device__ __nv_bfloat16 g_al[MROWS*DM];
__device__ __nv_bfloat16 g_bh[DM*DM];
__device__ __nv_bfloat16 g_bl[DM*DM];

// ===========================================================================
// Split: fp32 -> (hi bf16, lo bf16) where lo = bf16(x - fp32(hi))
// ===========================================================================
__global__ void split_kernel(const float* __restrict__ X,
                             __nv_bfloat16* __restrict__ hi,
                             __nv_bfloat16* __restrict__ lo, int n4)
{
    int i = blockIdx.x * blockDim.x + threadIdx.x;
    if (i >= n4) return;
    float4 v = reinterpret_cast<const float4*>(X)[i];
    __nv_bfloat16 h0 = __float2bfloat16_rn(v.x);
    __nv_bfloat16 h1 = __float2bfloat16_rn(v.y);
    __nv_bfloat16 h2 = __float2bfloat16_rn(v.z);
    __nv_bfloat16 h3 = __float2bfloat16_rn(v.w);
    __nv_bfloat16 l0 = __float2bfloat16_rn(v.x - __bfloat162float(h0));
    __nv_bfloat16 l1 = __float2bfloat16_rn(v.y - __bfloat162float(h1));
    __nv_bfloat16 l2 = __float2bfloat16_rn(v.z - __bfloat162float(h2));
    __nv_bfloat16 l3 = __float2bfloat16_rn(v.w - __bfloat162float(h3));
    __nv_bfloat162 hp0; hp0.x = h0; hp0.y = h1;
    __nv_bfloat162 hp1; hp1.x = h2; hp1.y = h3;
    __nv_bfloat162 lp0; lp0.x = l0; lp0.y = l1;
    __nv_bfloat162 lp1; lp1.x = l2; lp1.y = l3;
    uint2 hw, lw;
    hw.x = *reinterpret_cast<unsigned*>(&hp0);
    hw.y = *reinterpret_cast<unsigned*>(&hp1);
    lw.x = *reinterpret_cast<unsigned*>(&lp0);
    lw.y = *reinterpret_cast<unsigned*>(&lp1);
    reinterpret_cast<uint2*>(hi)[i] = hw;
    reinterpret_cast<uint2*>(lo)[i] = lw;
}

// ===========================================================================
// Tensor-core bf16x3 GEMM (NT): C = A @ B^T (+bias), fed from pre-split bf16.
// 3-phase mainloop: (Ah,Bh), (Ah,Bl), (Al,Bh) into shared fp32 accumulators.
// Block 128x128, BK=64 bf16 (128B rows, SW128 swizzle), cp.async 2-stage,
// ldmatrix.x4 fragment loads, 8 warps each 32x64.
// ===========================================================================
__device__ __forceinline__ void mma_bf16(float c[4], const unsigned a[4], const unsigned b0, const unsigned b1)
{
    asm volatile(
        "mma.sync.aligned.m16n8k16.row.col.f32.bf16.bf16.f32 "
        "{%0,%1,%2,%3}, {%4,%5,%6,%7}, {%8,%9}, {%0,%1,%2,%3};\n"
        : "+f"(c[0]), "+f"(c[1]), "+f"(c[2]), "+f"(c[3])
        : "r"(a[0]), "r"(a[1]), "r"(a[2]), "r"(a[3]), "r"(b0), "r"(b1));
}

__device__ __forceinline__ void cp16(unsigned saddr, const void* gptr)
{
    asm volatile("cp.async.cg.shared.global [%0], [%1], 16;\n" :: "r"(saddr), "l"(gptr));
}
#define CP_COMMIT() asm volatile("cp.async.commit_group;\n" ::: "memory")
#define CP_WAIT0()  asm volatile("cp.async.wait_group 0;\n" ::: "memory")
#define LDSM4(r, addr) \
    asm volatile("ldmatrix.sync.aligned.m8n8.x4.shared.b16 {%0,%1,%2,%3}, [%4];" \
        : "=r"((r)[0]), "=r"((r)[1]), "=r"((r)[2]), "=r"((r)[3]) : "r"(addr))

#define STAGE_BYTES 16384   // 128 rows x 128 bytes

template<bool HAS_BIAS>
__global__ void __launch_bounds__(256) gemm_bf16x3_tc(
    const __nv_bfloat16* __restrict__ Ah, const __nv_bfloat16* __restrict__ Al,
    const __nv_bfloat16* __restrict__ Bh, const __nv_bfloat16* __restrict__ Bl,
    const float* __restrict__ bias, float* __restrict__ C,
    int M, int N, int K)
{
    extern __shared__ __align__(16) char smem[];
    const unsigned sA = (unsigned)__cvta_generic_to_shared(smem);   // 2 stages A
    const unsigned sB = sA + 2 * STAGE_BYTES;                       // 2 stages B

    const int tid  = threadIdx.x;
    const int lane = tid & 31;
    const int warp = tid >> 5;
    const int wm   = warp >> 1;      // 0..3
    const int wn   = warp & 1;       // 0..1
    const int bm   = blockIdx.y * 128;
    const int bn   = blockIdx.x * 128;
    const int q    = lane & 7;
    const int g    = lane >> 3;

    const int tpp = K / 64;          // tiles per phase
    const int NT  = 3 * tpp;

    // cp.async: per thread 4 chunks for A + 4 for B per tile
    unsigned dst_off[4];
    size_t   a_off[4], b_off[4];
    #pragma unroll
    for (int it = 0; it < 4; it++) {
        int idx = tid + it * 256;            // 0..1023
        int row = idx >> 3;                  // 0..127
        int ch  = idx & 7;                   // 16B chunk within row
        dst_off[it] = (unsigned)(row * 128 + ((ch * 16) ^ ((row & 7) << 4)));
        a_off[it]   = (size_t)(bm + row) * K + ch * 8;
        b_off[it]   = (size_t)(bn + row) * K + ch * 8;
    }

    // ldmatrix per-lane bases (row terms; swizzle collapses to ^(q<<4))
    // A: tiles per mt: lanes g0: rows +q (khalf0), g1: rows +8+q (khalf0),
    //                  g2: rows +q (khalf1), g3: rows +8+q (khalf1)
    int a_rowterm[2], akb;
    {
        int row_a = (g & 1) * 8 + q;
        akb = (g >> 1) * 16;
        #pragma unroll
        for (int mt = 0; mt < 2; mt++)
            a_rowterm[mt] = (wm * 32 + mt * 16 + row_a) * 128;
    }
    // B: per pair p (n-tiles 2p,2p+1): g0: n=+q kh0, g1: n=+q kh1,
    //                                  g2: n=+8+q kh0, g3: n=+8+q kh1
    int b_rowterm[4], bkb;
    {
        int row_b = (g >> 1) * 8 + q;
        bkb = (g & 1) * 16;
        #pragma unroll
        for (int p = 0; p < 4; p++)
            b_rowterm[p] = (wn * 64 + p * 16 + row_b) * 128;
    }

    float acc[2][8][4];
    #pragma unroll
    for (int mt = 0; mt < 2; mt++)
        #pragma unroll
        for (int nt = 0; nt < 8; nt++)
            #pragma unroll
            for (int r = 0; r < 4; r++) acc[mt][nt][r] = 0.f;

    auto issue = [&](int t, int stage) {
        int ph = t / tpp;
        int kt = t - ph * tpp;
        const __nv_bfloat16* Ap = (ph == 2) ? Al : Ah;
        const __nv_bfloat16* Bp = (ph == 1) ? Bl : Bh;
        unsigned aS = sA + stage * STAGE_BYTES;
        unsigned bS = sB + stage * STAGE_BYTES;
        size_t kofs = (size_t)kt * 64;
        #pragma unroll
        for (int it = 0; it < 4; it++) {
            cp16(aS + dst_off[it], Ap + a_off[it] + kofs);
            cp16(bS + dst_off[it], Bp + b_off[it] + kofs);
        }
        CP_COMMIT();
    };

    issue(0, 0);

    for (int t = 0; t < NT; t++) {
        CP_WAIT0();
        __syncthreads();
        if (t + 1 < NT) issue(t + 1, (t + 1) & 1);

        unsigned aS = sA + (t & 1) * STAGE_BYTES;
        unsigned bS = sB + (t & 1) * STAGE_BYTES;
        #pragma unroll
        for (int ks = 0; ks < 4; ks++) {
            unsigned af[2][4];
            #pragma unroll
            for (int mt = 0; mt < 2; mt++)
                LDSM4(af[mt], aS + a_rowterm[mt] + ((ks * 32 + akb) ^ (q << 4)));
            unsigned bf_[4][4];
            #pragma unroll
            for (int p = 0; p < 4; p++)
                LDSM4(bf_[p], bS + b_rowterm[p] + ((ks * 32 + bkb) ^ (q << 4)));
            #pragma unroll
            for (int mt = 0; mt < 2; mt++)
                #pragma unroll
                for (int nt = 0; nt < 8; nt++) {
                    const unsigned* bp = bf_[nt >> 1];
                    if (nt & 1) mma_bf16(acc[mt][nt], af[mt], bp[2], bp[3]);
                    else        mma_bf16(acc[mt][nt], af[mt], bp[0], bp[1]);
                }
        }
        __syncthreads();
    }

    const int lr = lane >> 2;
    const int lc = (lane & 3) * 2;
    #pragma unroll
    for (int mt = 0; mt < 2; mt++) {
        #pragma unroll
        for (int nt = 0; nt < 8; nt++) {
            int row = bm + wm * 32 + mt * 16 + lr;
            int col = bn + wn * 64 + nt * 8 + lc;
            float2 v0 = make_float2(acc[mt][nt][0], acc[mt][nt][1]);
            float2 v1 = make_float2(acc[mt][nt][2], acc[mt][nt][3]);
            if (HAS_BIAS) {
                float b0 = bias[col], b1 = bias[col + 1];
                v0.x += b0; v0.y += b1;
                v1.x += b0; v1.y += b1;
            }
            *reinterpret_cast<float2*>(&C[(size_t)row * N + col])       = v0;
            *reinterpret_cast<float2*>(&C[(size_t)(row + 8) * N + col]) = v1;
        }
    }
}

// ---------------------------------------------------------------------------
// RoPE: interleaved pairs within each head, applied in-place to q and k.
// ---------------------------------------------------------------------------
__global__ void rope_kernel(float* __restrict__ q, float* __restrict__ k, int npairs)
{
    int idx = blockIdx.x * blockDim.x + threadIdx.x;
    if (idx >= npairs) return;
    int row = idx >> 9;
    int pc  = idx & 511;
    int h   = pc >> 5;
    int i   = pc & 31;
    int s   = row & (SEQ - 1);

    float theta = powf(10000.0f, -(float)(2 * i) * (1.0f / 64.0f));
    float ang = (float)s * theta;
    float sn, cs;
    sincosf(ang, &sn, &cs);

    size_t off = (size_t)row * DM + h * HD + 2 * i;
    float2 vq = *reinterpret_cast<float2*>(q + off);
    float2 rq;
    rq.x = vq.x * cs - vq.y * sn;
    rq.y = vq.y * cs + vq.x * sn;
    *reinterpret_cast<float2*>(q + off) = rq;

    float2 vk = *reinterpret_cast<float2*>(k + off);
    float2 rk;
    rk.x = vk.x * cs - vk.y * sn;
    rk.y = vk.y * cs + vk.x * sn;
    *reinterpret_cast<float2*>(k + off) = rk;
}

// ---------------------------------------------------------------------------
// Flash attention (causal): block = (query tile 64, head, batch).
// ---------------------------------------------------------------------------
__global__ void __launch_bounds__(256, 2) attn_kernel(
    const float* __restrict__ q, const float* __restrict__ k,
    const float* __restrict__ v, const int* __restrict__ mask,
    float* __restrict__ ctx)
{
    extern __shared__ float sm[];
    float (*Qs)[68] = reinterpret_cast<float(*)[68]>(sm);
    float (*Ks)[68] = reinterpret_cast<float(*)[68]>(sm + 64*68);
    float (*Vs)[68] = reinterpret_cast<float(*)[68]>(sm + 2*64*68);
    float (*Ps)[68] = reinterpret_cast<float(*)[68]>(sm + 3*64*68);
    int* msk = reinterpret_cast<int*>(sm + 4*64*68);

    const int qt = blockIdx.x, h = blockIdx.y, b = blockIdx.z;
    const int tid = threadIdx.x;
    const int tx = tid & 15, ty = tid >> 4;

    #pragma unroll
    for (int it = 0; it < 4; it++) {
        int idx = tid + it * 256;
        int r = idx >> 4, c4 = idx & 15;
        const float4 vq = *reinterpret_cast<const float4*>(
            &q[(size_t)(b * SEQ + qt * 64 + r) * DM + h * HD + c4 * 4]);
        *reinterpret_cast<float4*>(&Qs[r][c4 * 4]) = vq;
    }

    float o[4][4];
    #pragma unroll
    for (int i = 0; i < 4; i++)
        #pragma unroll
        for (int j = 0; j < 4; j++) o[i][j] = 0.f;
    float mrow[4], lrow[4];
    #pragma unroll
    for (int i = 0; i < 4; i++) { mrow[i] = -1e30f; lrow[i] = 0.f; }

    for (int kt = 0; kt <= qt; kt++) {
        __syncthreads();
        #pragma unroll
        for (int it = 0; it < 4; it++) {
            int idx = tid + it * 256;
            int r = idx >> 4, c4 = idx & 15;
            size_t goff = (size_t)(b * SEQ + kt * 64 + r) * DM + h * HD + c4 * 4;
            *reinterpret_cast<float4*>(&Ks[r][c4 * 4]) =
                *reinterpret_cast<const float4*>(&k[goff]);
            *reinterpret_cast<float4*>(&Vs[r][c4 * 4]) =
                *reinterpret_cast<const float4*>(&v[goff]);
        }
        if (tid < 64) msk[tid] = mask[b * SEQ + kt * 64 + tid];
        __syncthreads();

        float sc[4][4];
        #pragma unroll
        for (int i = 0; i < 4; i++)
            #pragma unroll
            for (int j = 0; j < 4; j++) sc[i][j] = 0.f;
        #pragma unroll
        for (int d4 = 0; d4 < 16; d4++) {
            float4 qv[4], kv[4];
            #pragma unroll
            for (int i = 0; i < 4; i++)
                qv[i] = *reinterpret_cast<float4*>(&Qs[ty*4+i][d4*4]);
            #pragma unroll
            for (int j = 0; j < 4; j++)
                kv[j] = *reinterpret_cast<float4*>(&Ks[tx*4+j][d4*4]);
            #pragma unroll
            for (int i = 0; i < 4; i++)
                #pragma unroll
                for (int j = 0; j < 4; j++)
                    sc[i][j] += qv[i].x*kv[j].x + qv[i].y*kv[j].y
                              + qv[i].z*kv[j].z + qv[i].w*kv[j].w;
        }

        const int qb = qt * 64 + ty * 4;
        const int kb = kt * 64 + tx * 4;
        #pragma unroll
        for (int i = 0; i < 4; i++)
            #pragma unroll
            for (int j = 0; j < 4; j++) {
                float val = sc[i][j] * 0.125f;
                bool ok = (kb + j <= qb + i) && (msk[tx*4+j] != 0);
                sc[i][j] = ok ? val : -1e30f;
            }

        #pragma unroll
        for (int i = 0; i < 4; i++) {
            float mx = fmaxf(fmaxf(sc[i][0], sc[i][1]), fmaxf(sc[i][2], sc[i][3]));
            #pragma unroll
            for (int off = 8; off >= 1; off >>= 1)
                mx = fmaxf(mx, __shfl_xor_sync(0xffffffffu, mx, off));
            float nm = fmaxf(mrow[i], mx);
            float alpha = __expf(mrow[i] - nm);
            float rs = 0.f;
            #pragma unroll
            for (int j = 0; j < 4; j++) { sc[i][j] = __expf(sc[i][j] - nm); rs += sc[i][j]; }
            #pragma unroll
            for (int off = 8; off >= 1; off >>= 1)
                rs += __shfl_xor_sync(0xffffffffu, rs, off);
            lrow[i] = lrow[i] * alpha + rs;
            mrow[i] = nm;
            #pragma unroll
            for (int j = 0; j < 4; j++) o[i][j] *= alpha;
            *reinterpret_cast<float4*>(&Ps[ty*4+i][tx*4]) =
                make_float4(sc[i][0], sc[i][1], sc[i][2], sc[i][3]);
        }
        __syncthreads();

        #pragma unroll 8
        for (int kk = 0; kk < 64; kk++) {
            float4 vv = *reinterpret_cast<float4*>(&Vs[kk][tx*4]);
            #pragma unroll
            for (int i = 0; i < 4; i++) {
                float p = Ps[ty*4+i][kk];
                o[i][0] += p * vv.x; o[i][1] += p * vv.y;
                o[i][2] += p * vv.z; o[i][3] += p * vv.w;
            }
        }
    }

    #pragma unroll
    for (int i = 0; i < 4; i++) {
        float inv = (lrow[i] > 0.f) ? 1.0f / lrow[i] : 0.f;
        float4 out = make_float4(o[i][0]*inv, o[i][1]*inv, o[i][2]*inv, o[i][3]*inv);
        size_t row = (size_t)(b * SEQ + qt * 64 + ty * 4 + i);
        *reinterpret_cast<float4*>(&ctx[row * DM + h * HD + tx * 4]) = out;
    }
}

// ---------------------------------------------------------------------------
extern "C" void kernel_launch(void* const* d_in, const int* in_sizes, int n_in,
                              void* d_out, int out_size)
{
    const float* Q  = (const float*)d_in[0];
    const float* K  = (const float*)d_in[1];
    const float* V  = (const float*)d_in[2];
    const int*   am = (const int*)  d_in[3];
    const float* Wq = (const float*)d_in[4];
    const float* Wk = (const float*)d_in[5];
    const float* Wv = (const float*)d_in[6];
    const float* Wo = (const float*)d_in[7];
    const float* bo = (const float*)d_in[8];
    float* out = (float*)d_out;

    float *q, *k, *v, *ctx;
    __nv_bfloat16 *ah, *al, *bh, *bl;
    cudaGetSymbolAddress((void**)&q,   g_q);
    cudaGetSymbolAddress((void**)&k,   g_k);
    cudaGetSymbolAddress((void**)&v,   g_v);
    cudaGetSymbolAddress((void**)&ctx, g_ctx);
    cudaGetSymbolAddress((void**)&ah,  g_ah);
    cudaGetSymbolAddress((void**)&al,  g_al);
    cudaGetSymbolAddress((void**)&bh,  g_bh);
    cudaGetSymbolAddress((void**)&bl,  g_bl);

    const int nA4 = MROWS * DM / 4;
    const int nB4 = DM * DM / 4;
    const dim3 gemm_grid(DM / 128, MROWS / 128);   // (8, 32)
    const int gemm_smem = 4 * STAGE_BYTES;          // 64 KB

    cudaFuncSetAttribute(gemm_bf16x3_tc<false>,
                         cudaFuncAttributeMaxDynamicSharedMemorySize, gemm_smem);
    cudaFuncSetAttribute(gemm_bf16x3_tc<true>,
                         cudaFuncAttributeMaxDynamicSharedMemorySize, gemm_smem);

    // Q projection
    split_kernel<<<(nA4 + 255) / 256, 256>>>(Q, ah, al, nA4);
    split_kernel<<<(nB4 + 255) / 256, 256>>>(Wq, bh, bl, nB4);
    gemm_bf16x3_tc<false><<<gemm_grid, 256, gemm_smem>>>(ah, al, bh, bl, nullptr, q, MROWS, DM, DM);
    // K projection
    split_kernel<<<(nA4 + 255) / 256, 256>>>(K, ah, al, nA4);
    split_kernel<<<(nB4 + 255) / 256, 256>>>(Wk, bh, bl, nB4);
    gemm_bf16x3_tc<false><<<gemm_grid, 256, gemm_smem>>>(ah, al, bh, bl, nullptr, k, MROWS, DM, DM);
    // V projection
    split_kernel<<<(nA4 + 255) / 256, 256>>>(V, ah, al, nA4);
    split_kernel<<<(nB4 + 255) / 256, 256>>>(Wv, bh, bl, nB4);
    gemm_bf16x3_tc<false><<<gemm_grid, 256, gemm_smem>>>(ah, al, bh, bl, nullptr, v, MROWS, DM, DM);

    const int npairs = MROWS * (DM / 2);
    rope_kernel<<<(npairs + 255) / 256, 256>>>(q, k, npairs);

    const int smem_bytes = (4 * 64 * 68) * (int)sizeof(float) + 64 * (int)sizeof(int);
    cudaFuncSetAttribute(attn_kernel,
                         cudaFuncAttributeMaxDynamicSharedMemorySize, smem_bytes);
    attn_kernel<<<dim3(SEQ / 64, NH, BATCH), 256, smem_bytes>>>(q, k, v, am, ctx);

    // Output projection
    split_kernel<<<(nA4 + 255) / 256, 256>>>(ctx, ah, al, nA4);
    split_kernel<<<(nB4 + 255) / 256, 256>>>(Wo, bh, bl, nB4);
    gemm_bf16x3_tc<true><<<gemm_grid, 256, gemm_smem>>>(ah, al, bh, bl, bo, out, MROWS, DM, DM);
}

// round 7
// speedup vs baseline: 1.4033x; 1.0248x over previous
#include <cuda_runtime.h>
#include <cuda_bf16.h>
#include <math.h>
#include <stdint.h>

#define DM   1024
#define NH   16
#define HD   64
#define SEQ  2048
#define BATCH 2
#define MROWS (BATCH*SEQ)   // 4096

// Scratch (static device arrays — no allocation allowed)
__device__ float g_q[MROWS*DM];
__device__ float g_k[MROWS*DM];
__device__ float g_v[MROWS*DM];
__device__ float g_ctx[MROWS*DM];
__device__ __nv_bfloat16 g_ah[MROWS*DM];
__device__ __nv_bfloat16 g_al[MROWS*DM];
__device__ __nv_bfloat16 g_bh[DM*DM];
__device__ __nv_bfloat16 g_bl[DM*DM];

// ===========================================================================
// Split: fp32 -> (hi bf16, lo bf16) where lo = bf16(x - fp32(hi))
// ===========================================================================
__global__ void split_kernel(const float* __restrict__ X,
                             __nv_bfloat16* __restrict__ hi,
                             __nv_bfloat16* __restrict__ lo, int n4)
{
    int i = blockIdx.x * blockDim.x + threadIdx.x;
    if (i >= n4) return;
    float4 v = reinterpret_cast<const float4*>(X)[i];
    __nv_bfloat16 h0 = __float2bfloat16_rn(v.x);
    __nv_bfloat16 h1 = __float2bfloat16_rn(v.y);
    __nv_bfloat16 h2 = __float2bfloat16_rn(v.z);
    __nv_bfloat16 h3 = __float2bfloat16_rn(v.w);
    __nv_bfloat16 l0 = __float2bfloat16_rn(v.x - __bfloat162float(h0));
    __nv_bfloat16 l1 = __float2bfloat16_rn(v.y - __bfloat162float(h1));
    __nv_bfloat16 l2 = __float2bfloat16_rn(v.z - __bfloat162float(h2));
    __nv_bfloat16 l3 = __float2bfloat16_rn(v.w - __bfloat162float(h3));
    __nv_bfloat162 hp0; hp0.x = h0; hp0.y = h1;
    __nv_bfloat162 hp1; hp1.x = h2; hp1.y = h3;
    __nv_bfloat162 lp0; lp0.x = l0; lp0.y = l1;
    __nv_bfloat162 lp1; lp1.x = l2; lp1.y = l3;
    uint2 hw, lw;
    hw.x = *reinterpret_cast<unsigned*>(&hp0);
    hw.y = *reinterpret_cast<unsigned*>(&hp1);
    lw.x = *reinterpret_cast<unsigned*>(&lp0);
    lw.y = *reinterpret_cast<unsigned*>(&lp1);
    reinterpret_cast<uint2*>(hi)[i] = hw;
    reinterpret_cast<uint2*>(lo)[i] = lw;
}

// ===========================================================================
// Tensor-core bf16x3 GEMM (NT) over virtual K' = 3K:
//   tile t -> (phase ph = t/16, kt = t%16); phase 0: Ah*Bh, 1: Ah*Bl, 2: Al*Bh
// Block 128x128, BK=64 bf16 (128B SW128 rows), 3-stage cp.async ring
// (32 KB/stage: only the 2 buffers this tile needs), ldmatrix.x4 frags,
// 8 warps each 32x64, 2 CTAs/SM.
// ===========================================================================
__device__ __forceinline__ void mma_bf16(float c[4], const unsigned a[4], const unsigned b0, const unsigned b1)
{
    asm volatile(
        "mma.sync.aligned.m16n8k16.row.col.f32.bf16.bf16.f32 "
        "{%0,%1,%2,%3}, {%4,%5,%6,%7}, {%8,%9}, {%0,%1,%2,%3};\n"
        : "+f"(c[0]), "+f"(c[1]), "+f"(c[2]), "+f"(c[3])
        : "r"(a[0]), "r"(a[1]), "r"(a[2]), "r"(a[3]), "r"(b0), "r"(b1));
}

__device__ __forceinline__ void cp16(unsigned saddr, const void* gptr)
{
    asm volatile("cp.async.cg.shared.global [%0], [%1], 16;\n" :: "r"(saddr), "l"(gptr));
}
#define CP_COMMIT() asm volatile("cp.async.commit_group;\n" ::: "memory")
#define LDSM4(r, addr) \
    asm volatile("ldmatrix.sync.aligned.m8n8.x4.shared.b16 {%0,%1,%2,%3}, [%4];" \
        : "=r"((r)[0]), "=r"((r)[1]), "=r"((r)[2]), "=r"((r)[3]) : "r"(addr))

#define BUF_BYTES   16384      // one 128x64 bf16 buffer (128B rows)
#define STAGE_BYTES 32768      // A buf + B buf
#define NSTAGE      3
#define KCHUNKS     16         // K=1024 / 64
#define NT          (3*KCHUNKS)
#define GEMM_SMEM   (NSTAGE*STAGE_BYTES)

template<bool HAS_BIAS>
__global__ void __launch_bounds__(256, 2) gemm_bf16x3_tc(
    const __nv_bfloat16* __restrict__ Ah, const __nv_bfloat16* __restrict__ Al,
    const __nv_bfloat16* __restrict__ Bh, const __nv_bfloat16* __restrict__ Bl,
    const float* __restrict__ bias, float* __restrict__ C,
    int M, int N, int K)
{
    extern __shared__ __align__(1024) char smem[];
    const unsigned sbase = (unsigned)__cvta_generic_to_shared(smem);

    const int tid  = threadIdx.x;
    const int lane = tid & 31;
    const int warp = tid >> 5;
    const int wm   = warp >> 1;      // 0..3
    const int wn   = warp & 1;       // 0..1
    const int bm   = blockIdx.y * 128;
    const int bn   = blockIdx.x * 128;
    const int q    = lane & 7;
    const int g    = lane >> 3;

    // cp.async per-thread offsets: 4 (row, chunk) pairs covering one buffer
    unsigned dst_off[4];
    size_t   a_off[4], b_off[4];
    #pragma unroll
    for (int i = 0; i < 4; i++) {
        int idx = tid + i * 256;             // 0..1023
        int r   = idx >> 3;                  // 0..127
        int ch  = idx & 7;                   // 16B chunk in 128B row
        dst_off[i] = (unsigned)(r * 128 + ((ch * 16) ^ ((r & 7) << 4)));
        a_off[i]   = (size_t)(bm + r) * K + ch * 8;
        b_off[i]   = (size_t)(bn + r) * K + ch * 8;
    }

    // ldmatrix per-lane bases (row terms; SW swizzle collapses to ^(q<<4))
    int a_rowterm[2], akb;
    {
        int row_a = (g & 1) * 8 + q;
        akb = (g >> 1) * 16;
        #pragma unroll
        for (int mt = 0; mt < 2; mt++)
            a_rowterm[mt] = (wm * 32 + mt * 16 + row_a) * 128;
    }
    int b_rowterm[4], bkb;
    {
        int row_b = (g >> 1) * 8 + q;
        bkb = (g & 1) * 16;
        #pragma unroll
        for (int p = 0; p < 4; p++)
            b_rowterm[p] = (wn * 64 + p * 16 + row_b) * 128;
    }

    float acc[2][8][4];
    #pragma unroll
    for (int mt = 0; mt < 2; mt++)
        #pragma unroll
        for (int nt = 0; nt < 8; nt++)
            #pragma unroll
            for (int r = 0; r < 4; r++) acc[mt][nt][r] = 0.f;

    auto issue = [&](int t, int st) {
        int ph = t >> 4;                 // /16
        int kt = t & 15;
        const __nv_bfloat16* Ap = (ph == 2) ? Al : Ah;
        const __nv_bfloat16* Bp = (ph == 1) ? Bl : Bh;
        unsigned aS = sbase + st * STAGE_BYTES;
        unsigned bS = aS + BUF_BYTES;
        size_t kofs = (size_t)kt * 64;
        #pragma unroll
        for (int i = 0; i < 4; i++) {
            cp16(aS + dst_off[i], Ap + a_off[i] + kofs);
            cp16(bS + dst_off[i], Bp + b_off[i] + kofs);
        }
        CP_COMMIT();
    };

    issue(0, 0);
    issue(1, 1);

    for (int t = 0; t < NT; t++) {
        const int st = t % NSTAGE;
        asm volatile("cp.async.wait_group 1;\n" ::: "memory");
        __syncthreads();
        if (t + NSTAGE - 1 < NT) issue(t + NSTAGE - 1, (t + NSTAGE - 1) % NSTAGE);
        else                     CP_COMMIT();   // empty group keeps count semantics

        unsigned aS = sbase + st * STAGE_BYTES;
        unsigned bS = aS + BUF_BYTES;
        #pragma unroll
        for (int ks = 0; ks < 4; ks++) {
            unsigned af[2][4];
            #pragma unroll
            for (int mt = 0; mt < 2; mt++)
                LDSM4(af[mt], aS + a_rowterm[mt] + ((ks * 32 + akb) ^ (q << 4)));
            unsigned bf_[4][4];
            #pragma unroll
            for (int p = 0; p < 4; p++)
                LDSM4(bf_[p], bS + b_rowterm[p] + ((ks * 32 + bkb) ^ (q << 4)));
            #pragma unroll
            for (int mt = 0; mt < 2; mt++)
                #pragma unroll
                for (int nt = 0; nt < 8; nt++) {
                    const unsigned* bp = bf_[nt >> 1];
                    if (nt & 1) mma_bf16(acc[mt][nt], af[mt], bp[2], bp[3]);
                    else        mma_bf16(acc[mt][nt], af[mt], bp[0], bp[1]);
                }
        }
    }

    const int lr = lane >> 2;
    const int lc = (lane & 3) * 2;
    #pragma unroll
    for (int mt = 0; mt < 2; mt++) {
        #pragma unroll
        for (int nt = 0; nt < 8; nt++) {
            int row = bm + wm * 32 + mt * 16 + lr;
            int col = bn + wn * 64 + nt * 8 + lc;
            float2 v0 = make_float2(acc[mt][nt][0], acc[mt][nt][1]);
            float2 v1 = make_float2(acc[mt][nt][2], acc[mt][nt][3]);
            if (HAS_BIAS) {
                float b0 = bias[col], b1 = bias[col + 1];
                v0.x += b0; v0.y += b1;
                v1.x += b0; v1.y += b1;
            }
            *reinterpret_cast<float2*>(&C[(size_t)row * N + col])       = v0;
            *reinterpret_cast<float2*>(&C[(size_t)(row + 8) * N + col]) = v1;
        }
    }
}

// ---------------------------------------------------------------------------
// RoPE: interleaved pairs within each head, applied in-place to q and k.
// ---------------------------------------------------------------------------
__global__ void rope_kernel(float* __restrict__ q, float* __restrict__ k, int npairs)
{
    int idx = blockIdx.x * blockDim.x + threadIdx.x;
    if (idx >= npairs) return;
    int row = idx >> 9;
    int pc  = idx & 511;
    int h   = pc >> 5;
    int i   = pc & 31;
    int s   = row & (SEQ - 1);

    float theta = powf(10000.0f, -(float)(2 * i) * (1.0f / 64.0f));
    float ang = (float)s * theta;
    float sn, cs;
    sincosf(ang, &sn, &cs);

    size_t off = (size_t)row * DM + h * HD + 2 * i;
    float2 vq = *reinterpret_cast<float2*>(q + off);
    float2 rq;
    rq.x = vq.x * cs - vq.y * sn;
    rq.y = vq.y * cs + vq.x * sn;
    *reinterpret_cast<float2*>(q + off) = rq;

    float2 vk = *reinterpret_cast<float2*>(k + off);
    float2 rk;
    rk.x = vk.x * cs - vk.y * sn;
    rk.y = vk.y * cs + vk.x * sn;
    *reinterpret_cast<float2*>(k + off) = rk;
}

// ---------------------------------------------------------------------------
// Flash attention (causal): block = (query tile 64, head, batch).
// ---------------------------------------------------------------------------
__global__ void __launch_bounds__(256, 2) attn_kernel(
    const float* __restrict__ q, const float* __restrict__ k,
    const float* __restrict__ v, const int* __restrict__ mask,
    float* __restrict__ ctx)
{
    extern __shared__ float sm[];
    float (*Qs)[68] = reinterpret_cast<float(*)[68]>(sm);
    float (*Ks)[68] = reinterpret_cast<float(*)[68]>(sm + 64*68);
    float (*Vs)[68] = reinterpret_cast<float(*)[68]>(sm + 2*64*68);
    float (*Ps)[68] = reinterpret_cast<float(*)[68]>(sm + 3*64*68);
    int* msk = reinterpret_cast<int*>(sm + 4*64*68);

    const int qt = blockIdx.x, h = blockIdx.y, b = blockIdx.z;
    const int tid = threadIdx.x;
    const int tx = tid & 15, ty = tid >> 4;

    #pragma unroll
    for (int it = 0; it < 4; it++) {
        int idx = tid + it * 256;
        int r = idx >> 4, c4 = idx & 15;
        const float4 vq = *reinterpret_cast<const float4*>(
            &q[(size_t)(b * SEQ + qt * 64 + r) * DM + h * HD + c4 * 4]);
        *reinterpret_cast<float4*>(&Qs[r][c4 * 4]) = vq;
    }

    float o[4][4];
    #pragma unroll
    for (int i = 0; i < 4; i++)
        #pragma unroll
        for (int j = 0; j < 4; j++) o[i][j] = 0.f;
    float mrow[4], lrow[4];
    #pragma unroll
    for (int i = 0; i < 4; i++) { mrow[i] = -1e30f; lrow[i] = 0.f; }

    for (int kt = 0; kt <= qt; kt++) {
        __syncthreads();
        #pragma unroll
        for (int it = 0; it < 4; it++) {
            int idx = tid + it * 256;
            int r = idx >> 4, c4 = idx & 15;
            size_t goff = (size_t)(b * SEQ + kt * 64 + r) * DM + h * HD + c4 * 4;
            *reinterpret_cast<float4*>(&Ks[r][c4 * 4]) =
                *reinterpret_cast<const float4*>(&k[goff]);
            *reinterpret_cast<float4*>(&Vs[r][c4 * 4]) =
                *reinterpret_cast<const float4*>(&v[goff]);
        }
        if (tid < 64) msk[tid] = mask[b * SEQ + kt * 64 + tid];
        __syncthreads();

        float sc[4][4];
        #pragma unroll
        for (int i = 0; i < 4; i++)
            #pragma unroll
            for (int j = 0; j < 4; j++) sc[i][j] = 0.f;
        #pragma unroll
        for (int d4 = 0; d4 < 16; d4++) {
            float4 qv[4], kv[4];
            #pragma unroll
            for (int i = 0; i < 4; i++)
                qv[i] = *reinterpret_cast<float4*>(&Qs[ty*4+i][d4*4]);
            #pragma unroll
            for (int j = 0; j < 4; j++)
                kv[j] = *reinterpret_cast<float4*>(&Ks[tx*4+j][d4*4]);
            #pragma unroll
            for (int i = 0; i < 4; i++)
                #pragma unroll
                for (int j = 0; j < 4; j++)
                    sc[i][j] += qv[i].x*kv[j].x + qv[i].y*kv[j].y
                              + qv[i].z*kv[j].z + qv[i].w*kv[j].w;
        }

        const int qb = qt * 64 + ty * 4;
        const int kb = kt * 64 + tx * 4;
        #pragma unroll
        for (int i = 0; i < 4; i++)
            #pragma unroll
            for (int j = 0; j < 4; j++) {
                float val = sc[i][j] * 0.125f;
                bool ok = (kb + j <= qb + i) && (msk[tx*4+j] != 0);
                sc[i][j] = ok ? val : -1e30f;
            }

        #pragma unroll
        for (int i = 0; i < 4; i++) {
            float mx = fmaxf(fmaxf(sc[i][0], sc[i][1]), fmaxf(sc[i][2], sc[i][3]));
            #pragma unroll
            for (int off = 8; off >= 1; off >>= 1)
                mx = fmaxf(mx, __shfl_xor_sync(0xffffffffu, mx, off));
            float nm = fmaxf(mrow[i], mx);
            float alpha = __expf(mrow[i] - nm);
            float rs = 0.f;
            #pragma unroll
            for (int j = 0; j < 4; j++) { sc[i][j] = __expf(sc[i][j] - nm); rs += sc[i][j]; }
            #pragma unroll
            for (int off = 8; off >= 1; off >>= 1)
                rs += __shfl_xor_sync(0xffffffffu, rs, off);
            lrow[i] = lrow[i] * alpha + rs;
            mrow[i] = nm;
            #pragma unroll
            for (int j = 0; j < 4; j++) o[i][j] *= alpha;
            *reinterpret_cast<float4*>(&Ps[ty*4+i][tx*4]) =
                make_float4(sc[i][0], sc[i][1], sc[i][2], sc[i][3]);
        }
        __syncthreads();

        #pragma unroll 8
        for (int kk = 0; kk < 64; kk++) {
            float4 vv = *reinterpret_cast<float4*>(&Vs[kk][tx*4]);
            #pragma unroll
            for (int i = 0; i < 4; i++) {
                float p = Ps[ty*4+i][kk];
                o[i][0] += p * vv.x; o[i][1] += p * vv.y;
                o[i][2] += p * vv.z; o[i][3] += p * vv.w;
            }
        }
    }

    #pragma unroll
    for (int i = 0; i < 4; i++) {
        float inv = (lrow[i] > 0.f) ? 1.0f / lrow[i] : 0.f;
        float4 out = make_float4(o[i][0]*inv, o[i][1]*inv, o[i][2]*inv, o[i][3]*inv);
        size_t row = (size_t)(b * SEQ + qt * 64 + ty * 4 + i);
        *reinterpret_cast<float4*>(&ctx[row * DM + h * HD + tx * 4]) = out;
    }
}

// ---------------------------------------------------------------------------
extern "C" void kernel_launch(void* const* d_in, const int* in_sizes, int n_in,
                              void* d_out, int out_size)
{
    const float* Q  = (const float*)d_in[0];
    const float* K  = (const float*)d_in[1];
    const float* V  = (const float*)d_in[2];
    const int*   am = (const int*)  d_in[3];
    const float* Wq = (const float*)d_in[4];
    const float* Wk = (const float*)d_in[5];
    const float* Wv = (const float*)d_in[6];
    const float* Wo = (const float*)d_in[7];
    const float* bo = (const float*)d_in[8];
    float* out = (float*)d_out;

    float *q, *k, *v, *ctx;
    __nv_bfloat16 *ah, *al, *bh, *bl;
    cudaGetSymbolAddress((void**)&q,   g_q);
    cudaGetSymbolAddress((void**)&k,   g_k);
    cudaGetSymbolAddress((void**)&v,   g_v);
    cudaGetSymbolAddress((void**)&ctx, g_ctx);
    cudaGetSymbolAddress((void**)&ah,  g_ah);
    cudaGetSymbolAddress((void**)&al,  g_al);
    cudaGetSymbolAddress((void**)&bh,  g_bh);
    cudaGetSymbolAddress((void**)&bl,  g_bl);

    const int nA4 = MROWS * DM / 4;
    const int nB4 = DM * DM / 4;
    const dim3 gemm_grid(DM / 128, MROWS / 128);   // (8, 32)

    cudaFuncSetAttribute(gemm_bf16x3_tc<false>,
                         cudaFuncAttributeMaxDynamicSharedMemorySize, GEMM_SMEM);
    cudaFuncSetAttribute(gemm_bf16x3_tc<true>,
                         cudaFuncAttributeMaxDynamicSharedMemorySize, GEMM_SMEM);

    // Q projection
    split_kernel<<<(nA4 + 255) / 256, 256>>>(Q, ah, al, nA4);
    split_kernel<<<(nB4 + 255) / 256, 256>>>(Wq, bh, bl, nB4);
    gemm_bf16x3_tc<false><<<gemm_grid, 256, GEMM_SMEM>>>(ah, al, bh, bl, nullptr, q, MROWS, DM, DM);
    // K projection
    split_kernel<<<(nA4 + 255) / 256, 256>>>(K, ah, al, nA4);
    split_kernel<<<(nB4 + 255) / 256, 256>>>(Wk, bh, bl, nB4);
    gemm_bf16x3_tc<false><<<gemm_grid, 256, GEMM_SMEM>>>(ah, al, bh, bl, nullptr, k, MROWS, DM, DM);
    // V projection
    split_kernel<<<(nA4 + 255) / 256, 256>>>(V, ah, al, nA4);
    split_kernel<<<(nB4 + 255) / 256, 256>>>(Wv, bh, bl, nB4);
    gemm_bf16x3_tc<false><<<gemm_grid, 256, GEMM_SMEM>>>(ah, al, bh, bl, nullptr, v, MROWS, DM, DM);

    const int npairs = MROWS * (DM / 2);
    rope_kernel<<<(npairs + 255) / 256, 256>>>(q, k, npairs);

    const int smem_bytes = (4 * 64 * 68) * (int)sizeof(float) + 64 * (int)sizeof(int);
    cudaFuncSetAttribute(attn_kernel,
                         cudaFuncAttributeMaxDynamicSharedMemorySize, smem_bytes);
    attn_kernel<<<dim3(SEQ / 64, NH, BATCH), 256, smem_bytes>>>(q, k, v, am, ctx);

    // Output projection
    split_kernel<<<(nA4 + 255) / 256, 256>>>(ctx, ah, al, nA4);
    split_kernel<<<(nB4 + 255) / 256, 256>>>(Wo, bh, bl, nB4);
    gemm_bf16x3_tc<true><<<gemm_grid, 256, GEMM_SMEM>>>(ah, al, bh, bl, bo, out, MROWS, DM, DM);
}

// round 11
// speedup vs baseline: 3.1239x; 2.2261x over previous
#include <cuda_runtime.h>
#include <cuda_bf16.h>
#include <math.h>
#include <stdint.h>

#define DM   1024
#define NH   16
#define HD   64
#define SEQ  2048
#define BATCH 2
#define MROWS (BATCH*SEQ)   // 4096

// Scratch (static device arrays — no allocation allowed)
__device__ float g_q[MROWS*DM];
__device__ float g_k[MROWS*DM];
__device__ float g_v[MROWS*DM];
__device__ float g_ctx[MROWS*DM];
__device__ __nv_bfloat16 g_ah[MROWS*DM];   // GEMM A hi  / reused as Q-hi (head-major)
__device__ __nv_bfloat16 g_al[MROWS*DM];   // GEMM A lo  / reused as Q-lo (head-major)
__device__ __nv_bfloat16 g_bh[DM*DM];
__device__ __nv_bfloat16 g_bl[DM*DM];
__device__ __nv_bfloat16 g_kh[MROWS*DM];   // K-hi head-major
__device__ __nv_bfloat16 g_kl[MROWS*DM];   // K-lo head-major
__device__ __nv_bfloat16 g_vh[MROWS*DM];   // V-hi head-major
__device__ __nv_bfloat16 g_vl[MROWS*DM];   // V-lo head-major

// ===========================================================================
// Common PTX helpers
// ===========================================================================
__device__ __forceinline__ void mma_bf16(float c[4], const unsigned a[4], unsigned b0, unsigned b1)
{
    asm volatile(
        "mma.sync.aligned.m16n8k16.row.col.f32.bf16.bf16.f32 "
        "{%0,%1,%2,%3}, {%4,%5,%6,%7}, {%8,%9}, {%0,%1,%2,%3};\n"
        : "+f"(c[0]), "+f"(c[1]), "+f"(c[2]), "+f"(c[3])
        : "r"(a[0]), "r"(a[1]), "r"(a[2]), "r"(a[3]), "r"(b0), "r"(b1));
}
__device__ __forceinline__ void cp16(unsigned saddr, const void* gptr)
{
    asm volatile("cp.async.cg.shared.global [%0], [%1], 16;\n" :: "r"(saddr), "l"(gptr));
}
#define CP_COMMIT() asm volatile("cp.async.commit_group;\n" ::: "memory")
#define LDSM4(r, addr) \
    asm volatile("ldmatrix.sync.aligned.m8n8.x4.shared.b16 {%0,%1,%2,%3}, [%4];" \
        : "=r"((r)[0]), "=r"((r)[1]), "=r"((r)[2]), "=r"((r)[3]) : "r"(addr))
#define LDSM4T(r, addr) \
    asm volatile("ldmatrix.sync.aligned.m8n8.x4.trans.shared.b16 {%0,%1,%2,%3}, [%4];" \
        : "=r"((r)[0]), "=r"((r)[1]), "=r"((r)[2]), "=r"((r)[3]) : "r"(addr))

__device__ __forceinline__ unsigned pack_bf16x2(float lo, float hi)
{
    __nv_bfloat162 p = __float22bfloat162_rn(make_float2(lo, hi));
    return *reinterpret_cast<unsigned*>(&p);
}

// ===========================================================================
// Split: fp32 -> (hi bf16, lo bf16) where lo = bf16(x - fp32(hi))
// ===========================================================================
__global__ void split_kernel(const float* __restrict__ X,
                             __nv_bfloat16* __restrict__ hi,
                             __nv_bfloat16* __restrict__ lo, int n4)
{
    int i = blockIdx.x * blockDim.x + threadIdx.x;
    if (i >= n4) return;
    float4 v = reinterpret_cast<const float4*>(X)[i];
    float h0 = __bfloat162float(__float2bfloat16_rn(v.x));
    float h1 = __bfloat162float(__float2bfloat16_rn(v.y));
    float h2 = __bfloat162float(__float2bfloat16_rn(v.z));
    float h3 = __bfloat162float(__float2bfloat16_rn(v.w));
    uint2 hw, lw;
    hw.x = pack_bf16x2(h0, h1);
    hw.y = pack_bf16x2(h2, h3);
    lw.x = pack_bf16x2(v.x - h0, v.y - h1);
    lw.y = pack_bf16x2(v.z - h2, v.w - h3);
    reinterpret_cast<uint2*>(hi)[i] = hw;
    reinterpret_cast<uint2*>(lo)[i] = lw;
}

// ===========================================================================
// Tensor-core bf16x3 GEMM (NT) over virtual K' = 3K, 4-stage cp.async ring.
// Block 128x128, BK=64 (128B SW rows), ldmatrix.x4 frags, 8 warps each 32x64.
// ===========================================================================
#define BUF_BYTES   16384
#define STAGE_BYTES 32768
#define KCHUNKS     16
#define NT          (3*KCHUNKS)
#define GEMM_SMEM   (4*STAGE_BYTES)

template<bool HAS_BIAS>
__global__ void __launch_bounds__(256) gemm_bf16x3_tc(
    const __nv_bfloat16* __restrict__ Ah, const __nv_bfloat16* __restrict__ Al,
    const __nv_bfloat16* __restrict__ Bh, const __nv_bfloat16* __restrict__ Bl,
    const float* __restrict__ bias, float* __restrict__ C,
    int M, int N, int K)
{
    extern __shared__ __align__(1024) char smem[];
    const unsigned sbase = (unsigned)__cvta_generic_to_shared(smem);

    const int tid  = threadIdx.x;
    const int lane = tid & 31;
    const int warp = tid >> 5;
    const int wm   = warp >> 1;
    const int wn   = warp & 1;
    const int bm   = blockIdx.y * 128;
    const int bn   = blockIdx.x * 128;
    const int q    = lane & 7;
    const int g    = lane >> 3;

    unsigned dst_off[4];
    size_t   a_off[4], b_off[4];
    #pragma unroll
    for (int i = 0; i < 4; i++) {
        int idx = tid + i * 256;
        int r   = idx >> 3;
        int ch  = idx & 7;
        dst_off[i] = (unsigned)(r * 128 + ((ch * 16) ^ ((r & 7) << 4)));
        a_off[i]   = (size_t)(bm + r) * K + ch * 8;
        b_off[i]   = (size_t)(bn + r) * K + ch * 8;
    }

    int a_rowterm[2], akb;
    {
        int row_a = (g & 1) * 8 + q;
        akb = (g >> 1) * 16;
        #pragma unroll
        for (int mt = 0; mt < 2; mt++)
            a_rowterm[mt] = (wm * 32 + mt * 16 + row_a) * 128;
    }
    int b_rowterm[4], bkb;
    {
        int row_b = (g >> 1) * 8 + q;
        bkb = (g & 1) * 16;
        #pragma unroll
        for (int p = 0; p < 4; p++)
            b_rowterm[p] = (wn * 64 + p * 16 + row_b) * 128;
    }

    float acc[2][8][4];
    #pragma unroll
    for (int mt = 0; mt < 2; mt++)
        #pragma unroll
        for (int nt = 0; nt < 8; nt++)
            #pragma unroll
            for (int r = 0; r < 4; r++) acc[mt][nt][r] = 0.f;

    auto issue = [&](int t, int st) {
        int ph = t >> 4;
        int kt = t & 15;
        const __nv_bfloat16* Ap = (ph == 2) ? Al : Ah;
        const __nv_bfloat16* Bp = (ph == 1) ? Bl : Bh;
        unsigned aS = sbase + st * STAGE_BYTES;
        unsigned bS = aS + BUF_BYTES;
        size_t kofs = (size_t)kt * 64;
        #pragma unroll
        for (int i = 0; i < 4; i++) {
            cp16(aS + dst_off[i], Ap + a_off[i] + kofs);
            cp16(bS + dst_off[i], Bp + b_off[i] + kofs);
        }
        CP_COMMIT();
    };

    issue(0, 0); issue(1, 1); issue(2, 2);

    for (int t = 0; t < NT; t++) {
        const int st = t & 3;
        if (t < NT - 2)       asm volatile("cp.async.wait_group 2;\n" ::: "memory");
        else if (t == NT - 2) asm volatile("cp.async.wait_group 1;\n" ::: "memory");
        else                  asm volatile("cp.async.wait_group 0;\n" ::: "memory");
        __syncthreads();
        if (t + 3 < NT) issue(t + 3, (t + 3) & 3);

        unsigned aS = sbase + st * STAGE_BYTES;
        unsigned bS = aS + BUF_BYTES;
        #pragma unroll
        for (int ks = 0; ks < 4; ks++) {
            unsigned af[2][4];
            #pragma unroll
            for (int mt = 0; mt < 2; mt++)
                LDSM4(af[mt], aS + a_rowterm[mt] + ((ks * 32 + akb) ^ (q << 4)));
            unsigned bf_[4][4];
            #pragma unroll
            for (int p = 0; p < 4; p++)
                LDSM4(bf_[p], bS + b_rowterm[p] + ((ks * 32 + bkb) ^ (q << 4)));
            #pragma unroll
            for (int mt = 0; mt < 2; mt++)
                #pragma unroll
                for (int nt = 0; nt < 8; nt++) {
                    const unsigned* bp = bf_[nt >> 1];
                    if (nt & 1) mma_bf16(acc[mt][nt], af[mt], bp[2], bp[3]);
                    else        mma_bf16(acc[mt][nt], af[mt], bp[0], bp[1]);
                }
        }
    }

    const int lr = lane >> 2;
    const int lc = (lane & 3) * 2;
    #pragma unroll
    for (int mt = 0; mt < 2; mt++) {
        #pragma unroll
        for (int nt = 0; nt < 8; nt++) {
            int row = bm + wm * 32 + mt * 16 + lr;
            int col = bn + wn * 64 + nt * 8 + lc;
            float2 v0 = make_float2(acc[mt][nt][0], acc[mt][nt][1]);
            float2 v1 = make_float2(acc[mt][nt][2], acc[mt][nt][3]);
            if (HAS_BIAS) {
                float b0 = bias[col], b1 = bias[col + 1];
                v0.x += b0; v0.y += b1;
                v1.x += b0; v1.y += b1;
            }
            *reinterpret_cast<float2*>(&C[(size_t)row * N + col])       = v0;
            *reinterpret_cast<float2*>(&C[(size_t)(row + 8) * N + col]) = v1;
        }
    }
}

// ===========================================================================
// Fused rope + bf16 hi/lo split + head-major relayout for attention.
// Outputs qh/ql/kh/kl (rope applied) and vh/vl, all head-major
// [((b*NH+h)*SEQ+s)*64+d].
// ===========================================================================
__global__ void rope_conv_kernel(
    const float* __restrict__ q, const float* __restrict__ k, const float* __restrict__ v,
    __nv_bfloat16* __restrict__ qh, __nv_bfloat16* __restrict__ ql,
    __nv_bfloat16* __restrict__ kh, __nv_bfloat16* __restrict__ kl,
    __nv_bfloat16* __restrict__ vh, __nv_bfloat16* __restrict__ vl, int n4)
{
    int idx = blockIdx.x * blockDim.x + threadIdx.x;
    if (idx >= n4) return;
    int row = idx >> 8;            // / (DM/4)
    int c4  = idx & 255;
    int h   = c4 >> 4;
    int d4  = c4 & 15;
    int b   = row >> 11;
    int s   = row & (SEQ - 1);

    int i0 = 2 * d4, i1 = 2 * d4 + 1;
    float th0 = powf(10000.0f, -(float)(2 * i0) * (1.0f / 64.0f));
    float th1 = powf(10000.0f, -(float)(2 * i1) * (1.0f / 64.0f));
    float sn0, cs0, sn1, cs1;
    sincosf((float)s * th0, &sn0, &cs0);
    sincosf((float)s * th1, &sn1, &cs1);

    float4 vq = reinterpret_cast<const float4*>(q)[idx];
    float4 vk = reinterpret_cast<const float4*>(k)[idx];
    float4 vv = reinterpret_cast<const float4*>(v)[idx];

    float qx0 = vq.x*cs0 - vq.y*sn0, qy0 = vq.y*cs0 + vq.x*sn0;
    float qx1 = vq.z*cs1 - vq.w*sn1, qy1 = vq.w*cs1 + vq.z*sn1;
    float kx0 = vk.x*cs0 - vk.y*sn0, ky0 = vk.y*cs0 + vk.x*sn0;
    float kx1 = vk.z*cs1 - vk.w*sn1, ky1 = vk.w*cs1 + vk.z*sn1;

    size_t out4 = (((size_t)(b * NH + h) * SEQ + s) * HD + d4 * 4) >> 2;
    uint2 w;

    float hq0 = __bfloat162float(__float2bfloat16_rn(qx0));
    float hq1 = __bfloat162float(__float2bfloat16_rn(qy0));
    float hq2 = __bfloat162float(__float2bfloat16_rn(qx1));
    float hq3 = __bfloat162float(__float2bfloat16_rn(qy1));
    w.x = pack_bf16x2(hq0, hq1); w.y = pack_bf16x2(hq2, hq3);
    reinterpret_cast<uint2*>(qh)[out4] = w;
    w.x = pack_bf16x2(qx0 - hq0, qy0 - hq1); w.y = pack_bf16x2(qx1 - hq2, qy1 - hq3);
    reinterpret_cast<uint2*>(ql)[out4] = w;

    float hk0 = __bfloat162float(__float2bfloat16_rn(kx0));
    float hk1 = __bfloat162float(__float2bfloat16_rn(ky0));
    float hk2 = __bfloat162float(__float2bfloat16_rn(kx1));
    float hk3 = __bfloat162float(__float2bfloat16_rn(ky1));
    w.x = pack_bf16x2(hk0, hk1); w.y = pack_bf16x2(hk2, hk3);
    reinterpret_cast<uint2*>(kh)[out4] = w;
    w.x = pack_bf16x2(kx0 - hk0, ky0 - hk1); w.y = pack_bf16x2(kx1 - hk2, ky1 - hk3);
    reinterpret_cast<uint2*>(kl)[out4] = w;

    float hv0 = __bfloat162float(__float2bfloat16_rn(vv.x));
    float hv1 = __bfloat162float(__float2bfloat16_rn(vv.y));
    float hv2 = __bfloat162float(__float2bfloat16_rn(vv.z));
    float hv3 = __bfloat162float(__float2bfloat16_rn(vv.w));
    w.x = pack_bf16x2(hv0, hv1); w.y = pack_bf16x2(hv2, hv3);
    reinterpret_cast<uint2*>(vh)[out4] = w;
    w.x = pack_bf16x2(vv.x - hv0, vv.y - hv1); w.y = pack_bf16x2(vv.z - hv2, vv.w - hv3);
    reinterpret_cast<uint2*>(vl)[out4] = w;
}

// ===========================================================================
// Tensor-core causal flash attention, bf16x3 for BOTH S=QK^T and O=PV.
// Block: 128 queries x 1 head x 1 batch. 8 warps, each 16 query rows.
// K/V tiles of 64 keys, 3-stage cp.async ring; Q frags hoisted.
// Stage: Kh 8K | Kl 8K | Vh 8K | Vl 8K | mask 256 = 33024 B.
// ===========================================================================
#define AT_STAGE  33024
#define AT_SMEM   (32768 + 3*AT_STAGE)   // 131840

__global__ void __launch_bounds__(256) attn_tc_kernel(
    const __nv_bfloat16* __restrict__ qh, const __nv_bfloat16* __restrict__ ql,
    const __nv_bfloat16* __restrict__ kh, const __nv_bfloat16* __restrict__ kl,
    const __nv_bfloat16* __restrict__ vh, const __nv_bfloat16* __restrict__ vl,
    const int* __restrict__ am, float* __restrict__ ctx)
{
    extern __shared__ __align__(1024) char smem[];
    const unsigned sb  = (unsigned)__cvta_generic_to_shared(smem);
    const unsigned sQh = sb, sQl = sb + 16384;

    const int tid  = threadIdx.x;
    const int lane = tid & 31;
    const int w    = tid >> 5;
    const int q    = lane & 7;
    const int g    = lane >> 3;
    const int qt   = blockIdx.x, h = blockIdx.y, b = blockIdx.z;
    const int qb   = qt * 128;
    const size_t headbase = (size_t)(b * NH + h) * SEQ;

    // Q tile load (Qh + Ql), one cp.async group
    #pragma unroll
    for (int i = 0; i < 4; i++) {
        int idx = tid + i * 256;
        int r = idx >> 3, ch = idx & 7;
        unsigned dst = (unsigned)(r * 128 + ((ch * 16) ^ ((r & 7) << 4)));
        size_t gidx = (headbase + qb + r) * HD + ch * 8;
        cp16(sQh + dst, qh + gidx);
        cp16(sQl + dst, ql + gidx);
    }
    CP_COMMIT();

    const int nkt = qt * 2 + 2;

    auto issue = [&](int kt, int st) {
        unsigned s0 = sb + 32768 + st * AT_STAGE;
        #pragma unroll
        for (int i = 0; i < 8; i++) {
            int idx = tid + i * 256;              // 0..2047
            int buf = idx >> 9;                   // 0 Kh, 1 Kl, 2 Vh, 3 Vl
            int r   = (idx & 511) >> 3;
            int ch  = idx & 7;
            unsigned dst = s0 + buf * 8192 +
                           (unsigned)(r * 128 + ((ch * 16) ^ ((r & 7) << 4)));
            size_t gidx = (headbase + kt * 64 + r) * HD + ch * 8;
            const __nv_bfloat16* src = (buf == 0) ? kh : (buf == 1) ? kl
                                      : (buf == 2) ? vh : vl;
            cp16(dst, src + gidx);
        }
        if (tid < 16) cp16(s0 + 32768, am + b * SEQ + kt * 64 + tid * 4);
        CP_COMMIT();
    };

    issue(0, 0);
    issue(1, 1);

    float o[8][4];
    #pragma unroll
    for (int j = 0; j < 8; j++)
        #pragma unroll
        for (int r = 0; r < 4; r++) o[j][r] = 0.f;
    float m0 = -1e30f, m1 = -1e30f, l0 = 0.f, l1 = 0.f;

    unsigned qhf[4][4], qlf[4][4];

    const int row0 = qb + w * 16 + (lane >> 2);
    const int row1 = row0 + 8;
    const int c2   = 2 * (lane & 3);

    for (int kt = 0; kt < nkt; kt++) {
        const int st = kt % 3;
        if (kt + 1 < nkt) asm volatile("cp.async.wait_group 1;\n" ::: "memory");
        else              asm volatile("cp.async.wait_group 0;\n" ::: "memory");
        __syncthreads();
        if (kt + 2 < nkt) issue(kt + 2, (kt + 2) % 3);

        if (kt == 0) {
            #pragma unroll
            for (int ks = 0; ks < 4; ks++) {
                unsigned ab = (unsigned)((w * 16 + (g & 1) * 8 + q) * 128) +
                              ((unsigned)(ks * 32 + (g >> 1) * 16) ^ (unsigned)(q << 4));
                LDSM4(qhf[ks], sQh + ab);
                LDSM4(qlf[ks], sQl + ab);
            }
        }

        unsigned sK  = sb + 32768 + st * AT_STAGE;
        unsigned sKl = sK + 8192;
        unsigned sVh = sK + 16384;
        unsigned sVl = sK + 24576;
        const int2* mp = reinterpret_cast<const int2*>(smem + 32768 + st * AT_STAGE + 32768);

        // ---- S = Qh*Kh + Ql*Kh + Qh*Kl ----
        float sc_[8][4];
        #pragma unroll
        for (int j = 0; j < 8; j++)
            #pragma unroll
            for (int r = 0; r < 4; r++) sc_[j][r] = 0.f;

        #pragma unroll
        for (int ks = 0; ks < 4; ks++) {
            unsigned kb = ((unsigned)(ks * 32 + (g & 1) * 16)) ^ (unsigned)(q << 4);
            #pragma unroll
            for (int p = 0; p < 4; p++) {
                unsigned rowoff = (unsigned)((p * 16 + (g >> 1) * 8 + q) * 128);
                unsigned kf[4], kf2[4];
                LDSM4(kf,  sK  + rowoff + kb);
                LDSM4(kf2, sKl + rowoff + kb);
                mma_bf16(sc_[2*p],   qhf[ks], kf[0],  kf[1]);
                mma_bf16(sc_[2*p+1], qhf[ks], kf[2],  kf[3]);
                mma_bf16(sc_[2*p],   qlf[ks], kf[0],  kf[1]);
                mma_bf16(sc_[2*p+1], qlf[ks], kf[2],  kf[3]);
                mma_bf16(sc_[2*p],   qhf[ks], kf2[0], kf2[1]);
                mma_bf16(sc_[2*p+1], qhf[ks], kf2[2], kf2[3]);
            }
        }

        // ---- scale + causal + padding mask ----
        #pragma unroll
        for (int j = 0; j < 8; j++) {
            int c0 = kt * 64 + 8 * j + c2;
            int2 mk = mp[4 * j + (lane & 3)];
            sc_[j][0] = (c0     <= row0 && mk.x) ? sc_[j][0] * 0.125f : -1e30f;
            sc_[j][1] = (c0 + 1 <= row0 && mk.y) ? sc_[j][1] * 0.125f : -1e30f;
            sc_[j][2] = (c0     <= row1 && mk.x) ? sc_[j][2] * 0.125f : -1e30f;
            sc_[j][3] = (c0 + 1 <= row1 && mk.y) ? sc_[j][3] * 0.125f : -1e30f;
        }

        // ---- online softmax ----
        float mx0 = -1e30f, mx1 = -1e30f;
        #pragma unroll
        for (int j = 0; j < 8; j++) {
            mx0 = fmaxf(mx0, fmaxf(sc_[j][0], sc_[j][1]));
            mx1 = fmaxf(mx1, fmaxf(sc_[j][2], sc_[j][3]));
        }
        mx0 = fmaxf(mx0, __shfl_xor_sync(0xffffffffu, mx0, 1));
        mx0 = fmaxf(mx0, __shfl_xor_sync(0xffffffffu, mx0, 2));
        mx1 = fmaxf(mx1, __shfl_xor_sync(0xffffffffu, mx1, 1));
        mx1 = fmaxf(mx1, __shfl_xor_sync(0xffffffffu, mx1, 2));
        float mn0 = fmaxf(m0, mx0), mn1 = fmaxf(m1, mx1);
        float a0 = __expf(m0 - mn0), a1 = __expf(m1 - mn1);
        m0 = mn0; m1 = mn1;
        float s0s = 0.f, s1s = 0.f;
        #pragma unroll
        for (int j = 0; j < 8; j++) {
            sc_[j][0] = __expf(sc_[j][0] - mn0);
            sc_[j][1] = __expf(sc_[j][1] - mn0);
            sc_[j][2] = __expf(sc_[j][2] - mn1);
            sc_[j][3] = __expf(sc_[j][3] - mn1);
            s0s += sc_[j][0] + sc_[j][1];
            s1s += sc_[j][2] + sc_[j][3];
        }
        s0s += __shfl_xor_sync(0xffffffffu, s0s, 1);
        s0s += __shfl_xor_sync(0xffffffffu, s0s, 2);
        s1s += __shfl_xor_sync(0xffffffffu, s1s, 1);
        s1s += __shfl_xor_sync(0xffffffffu, s1s, 2);
        l0 = l0 * a0 + s0s;
        l1 = l1 * a1 + s1s;
        #pragma unroll
        for (int j = 0; j < 8; j++) {
            o[j][0] *= a0; o[j][1] *= a0;
            o[j][2] *= a1; o[j][3] *= a1;
        }

        // ---- split P into hi/lo bf16 A-frags ----
        unsigned pkh[4][4], pkl[4][4];
        #pragma unroll
        for (int ks = 0; ks < 4; ks++) {
            float a0h0 = __bfloat162float(__float2bfloat16_rn(sc_[2*ks][0]));
            float a0h1 = __bfloat162float(__float2bfloat16_rn(sc_[2*ks][1]));
            float a1h0 = __bfloat162float(__float2bfloat16_rn(sc_[2*ks][2]));
            float a1h1 = __bfloat162float(__float2bfloat16_rn(sc_[2*ks][3]));
            float b0h0 = __bfloat162float(__float2bfloat16_rn(sc_[2*ks+1][0]));
            float b0h1 = __bfloat162float(__float2bfloat16_rn(sc_[2*ks+1][1]));
            float b1h0 = __bfloat162float(__float2bfloat16_rn(sc_[2*ks+1][2]));
            float b1h1 = __bfloat162float(__float2bfloat16_rn(sc_[2*ks+1][3]));
            pkh[ks][0] = pack_bf16x2(a0h0, a0h1);
            pkh[ks][1] = pack_bf16x2(a1h0, a1h1);
            pkh[ks][2] = pack_bf16x2(b0h0, b0h1);
            pkh[ks][3] = pack_bf16x2(b1h0, b1h1);
            pkl[ks][0] = pack_bf16x2(sc_[2*ks][0] - a0h0,   sc_[2*ks][1] - a0h1);
            pkl[ks][1] = pack_bf16x2(sc_[2*ks][2] - a1h0,   sc_[2*ks][3] - a1h1);
            pkl[ks][2] = pack_bf16x2(sc_[2*ks+1][0] - b0h0, sc_[2*ks+1][1] - b0h1);
            pkl[ks][3] = pack_bf16x2(sc_[2*ks+1][2] - b1h0, sc_[2*ks+1][3] - b1h1);
        }

        // ---- O += Ph*Vh + Pl*Vh + Ph*Vl ----
        #pragma unroll
        for (int ks = 0; ks < 4; ks++) {
            int sl = ks * 16 + (lane & 15);
            unsigned vrowh = sVh + (unsigned)(sl * 128);
            unsigned vrowl = sVl + (unsigned)(sl * 128);
            unsigned swz   = (unsigned)((sl & 7) << 4);
            #pragma unroll
            for (int j = 0; j < 4; j++) {
                unsigned coff = ((unsigned)((2*j + (lane >> 4)) * 16)) ^ swz;
                unsigned vfh[4], vfl[4];
                LDSM4T(vfh, vrowh + coff);
                LDSM4T(vfl, vrowl + coff);
                mma_bf16(o[2*j],   pkh[ks], vfh[0], vfh[1]);
                mma_bf16(o[2*j+1], pkh[ks], vfh[2], vfh[3]);
                mma_bf16(o[2*j],   pkl[ks], vfh[0], vfh[1]);
                mma_bf16(o[2*j+1], pkl[ks], vfh[2], vfh[3]);
                mma_bf16(o[2*j],   pkh[ks], vfl[0], vfl[1]);
                mma_bf16(o[2*j+1], pkh[ks], vfl[2], vfl[3]);
            }
        }
    }

    // ---- normalize + store ----
    float i0 = (l0 > 0.f) ? 1.f / l0 : 0.f;
    float i1 = (l1 > 0.f) ? 1.f / l1 : 0.f;
    size_t gr0 = (size_t)(b * SEQ + row0) * DM + h * HD;
    size_t gr1 = (size_t)(b * SEQ + row1) * DM + h * HD;
    #pragma unroll
    for (int j = 0; j < 8; j++) {
        int d = 8 * j + c2;
        *reinterpret_cast<float2*>(&ctx[gr0 + d]) = make_float2(o[j][0]*i0, o[j][1]*i0);
        *reinterpret_cast<float2*>(&ctx[gr1 + d]) = make_float2(o[j][2]*i1, o[j][3]*i1);
    }
}

// ---------------------------------------------------------------------------
extern "C" void kernel_launch(void* const* d_in, const int* in_sizes, int n_in,
                              void* d_out, int out_size)
{
    const float* Q  = (const float*)d_in[0];
    const float* K  = (const float*)d_in[1];
    const float* V  = (const float*)d_in[2];
    const int*   am = (const int*)  d_in[3];
    const float* Wq = (const float*)d_in[4];
    const float* Wk = (const float*)d_in[5];
    const float* Wv = (const float*)d_in[6];
    const float* Wo = (const float*)d_in[7];
    const float* bo = (const float*)d_in[8];
    float* out = (float*)d_out;

    float *q, *k, *v, *ctx;
    __nv_bfloat16 *ah, *al, *bh, *bl, *kkh, *kkl, *vvh, *vvl;
    cudaGetSymbolAddress((void**)&q,   g_q);
    cudaGetSymbolAddress((void**)&k,   g_k);
    cudaGetSymbolAddress((void**)&v,   g_v);
    cudaGetSymbolAddress((void**)&ctx, g_ctx);
    cudaGetSymbolAddress((void**)&ah,  g_ah);
    cudaGetSymbolAddress((void**)&al,  g_al);
    cudaGetSymbolAddress((void**)&bh,  g_bh);
    cudaGetSymbolAddress((void**)&bl,  g_bl);
    cudaGetSymbolAddress((void**)&kkh, g_kh);
    cudaGetSymbolAddress((void**)&kkl, g_kl);
    cudaGetSymbolAddress((void**)&vvh, g_vh);
    cudaGetSymbolAddress((void**)&vvl, g_vl);

    const int nA4 = MROWS * DM / 4;
    const int nB4 = DM * DM / 4;
    const dim3 gemm_grid(DM / 128, MROWS / 128);

    cudaFuncSetAttribute(gemm_bf16x3_tc<false>,
                         cudaFuncAttributeMaxDynamicSharedMemorySize, GEMM_SMEM);
    cudaFuncSetAttribute(gemm_bf16x3_tc<true>,
                         cudaFuncAttributeMaxDynamicSharedMemorySize, GEMM_SMEM);
    cudaFuncSetAttribute(attn_tc_kernel,
                         cudaFuncAttributeMaxDynamicSharedMemorySize, AT_SMEM);

    // QKV projections
    split_kernel<<<(nA4 + 255) / 256, 256>>>(Q, ah, al, nA4);
    split_kernel<<<(nB4 + 255) / 256, 256>>>(Wq, bh, bl, nB4);
    gemm_bf16x3_tc<false><<<gemm_grid, 256, GEMM_SMEM>>>(ah, al, bh, bl, nullptr, q, MROWS, DM, DM);
    split_kernel<<<(nA4 + 255) / 256, 256>>>(K, ah, al, nA4);
    split_kernel<<<(nB4 + 255) / 256, 256>>>(Wk, bh, bl, nB4);
    gemm_bf16x3_tc<false><<<gemm_grid, 256, GEMM_SMEM>>>(ah, al, bh, bl, nullptr, k, MROWS, DM, DM);
    split_kernel<<<(nA4 + 255) / 256, 256>>>(V, ah, al, nA4);
    split_kernel<<<(nB4 + 255) / 256, 256>>>(Wv, bh, bl, nB4);
    gemm_bf16x3_tc<false><<<gemm_grid, 256, GEMM_SMEM>>>(ah, al, bh, bl, nullptr, v, MROWS, DM, DM);

    // RoPE + convert + head-major relayout (qh/ql reuse ah/al)
    rope_conv_kernel<<<(nA4 + 255) / 256, 256>>>(q, k, v, ah, al, kkh, kkl, vvh, vvl, nA4);

    // Tensor-core flash attention
    attn_tc_kernel<<<dim3(SEQ / 128, NH, BATCH), 256, AT_SMEM>>>(
        ah, al, kkh, kkl, vvh, vvl, am, ctx);

    // Output projection
    split_kernel<<<(nA4 + 255) / 256, 256>>>(ctx, ah, al, nA4);
    split_kernel<<<(nB4 + 255) / 256, 256>>>(Wo, bh, bl, nB4);
    gemm_bf16x3_tc<true><<<gemm_grid, 256, GEMM_SMEM>>>(ah, al, bh, bl, bo, out, MROWS, DM, DM);
}

// round 13
// speedup vs baseline: 3.1326x; 1.0028x over previous
#include <cuda_runtime.h>
#include <cuda_bf16.h>
#include <math.h>
#include <stdint.h>

#define DM   1024
#define NH   16
#define HD   64
#define SEQ  2048
#define BATCH 2
#define MROWS (BATCH*SEQ)   // 4096

// Scratch (static device arrays — no allocation allowed)
__device__ __nv_bfloat16 g_ah[MROWS*DM];   // input-A splits; later ctx split
__device__ __nv_bfloat16 g_al[MROWS*DM];
__device__ __nv_bfloat16 g_bh[DM*DM];
__device__ __nv_bfloat16 g_bl[DM*DM];
__device__ __nv_bfloat16 g_qh[MROWS*DM];   // head-major, rope applied
__device__ __nv_bfloat16 g_ql[MROWS*DM];
__device__ __nv_bfloat16 g_kh[MROWS*DM];
__device__ __nv_bfloat16 g_kl[MROWS*DM];
__device__ __nv_bfloat16 g_vh[MROWS*DM];
__device__ __nv_bfloat16 g_vl[MROWS*DM];
__device__ float2 g_tab[SEQ*32];           // (cos, sin) per (s, pair)

// ===========================================================================
// Common PTX helpers
// ===========================================================================
__device__ __forceinline__ void mma_bf16(float c[4], const unsigned a[4], unsigned b0, unsigned b1)
{
    asm volatile(
        "mma.sync.aligned.m16n8k16.row.col.f32.bf16.bf16.f32 "
        "{%0,%1,%2,%3}, {%4,%5,%6,%7}, {%8,%9}, {%0,%1,%2,%3};\n"
        : "+f"(c[0]), "+f"(c[1]), "+f"(c[2]), "+f"(c[3])
        : "r"(a[0]), "r"(a[1]), "r"(a[2]), "r"(a[3]), "r"(b0), "r"(b1));
}
__device__ __forceinline__ void cp16(unsigned saddr, const void* gptr)
{
    asm volatile("cp.async.cg.shared.global [%0], [%1], 16;\n" :: "r"(saddr), "l"(gptr));
}
#define CP_COMMIT() asm volatile("cp.async.commit_group;\n" ::: "memory")
#define LDSM4(r, addr) \
    asm volatile("ldmatrix.sync.aligned.m8n8.x4.shared.b16 {%0,%1,%2,%3}, [%4];" \
        : "=r"((r)[0]), "=r"((r)[1]), "=r"((r)[2]), "=r"((r)[3]) : "r"(addr))
#define LDSM4T(r, addr) \
    asm volatile("ldmatrix.sync.aligned.m8n8.x4.trans.shared.b16 {%0,%1,%2,%3}, [%4];" \
        : "=r"((r)[0]), "=r"((r)[1]), "=r"((r)[2]), "=r"((r)[3]) : "r"(addr))

__device__ __forceinline__ unsigned pack_bf16x2(float lo, float hi)
{
    __nv_bfloat162 p = __float22bfloat162_rn(make_float2(lo, hi));
    return *reinterpret_cast<unsigned*>(&p);
}

// ===========================================================================
// RoPE cos/sin table: tab[s*32+i] = (cos(s*theta_i), sin(s*theta_i))
// ===========================================================================
__global__ void rope_tab_kernel(float2* __restrict__ tab)
{
    int idx = blockIdx.x * blockDim.x + threadIdx.x;
    if (idx >= SEQ * 32) return;
    int s = idx >> 5, i = idx & 31;
    float theta = powf(10000.0f, -(float)(2 * i) * (1.0f / 64.0f));
    float sn, cs;
    sincosf((float)s * theta, &sn, &cs);
    tab[idx] = make_float2(cs, sn);
}

// ===========================================================================
// Split: fp32 -> (hi bf16, lo bf16) where lo = bf16(x - fp32(hi))
// ===========================================================================
__global__ void split_kernel(const float* __restrict__ X,
                             __nv_bfloat16* __restrict__ hi,
                             __nv_bfloat16* __restrict__ lo, int n4)
{
    int i = blockIdx.x * blockDim.x + threadIdx.x;
    if (i >= n4) return;
    float4 v = reinterpret_cast<const float4*>(X)[i];
    float h0 = __bfloat162float(__float2bfloat16_rn(v.x));
    float h1 = __bfloat162float(__float2bfloat16_rn(v.y));
    float h2 = __bfloat162float(__float2bfloat16_rn(v.z));
    float h3 = __bfloat162float(__float2bfloat16_rn(v.w));
    uint2 hw, lw;
    hw.x = pack_bf16x2(h0, h1);
    hw.y = pack_bf16x2(h2, h3);
    lw.x = pack_bf16x2(v.x - h0, v.y - h1);
    lw.y = pack_bf16x2(v.z - h2, v.w - h3);
    reinterpret_cast<uint2*>(hi)[i] = hw;
    reinterpret_cast<uint2*>(lo)[i] = lw;
}

// ===========================================================================
// Tensor-core bf16x3 GEMM (NT) over virtual K' = 3K, 4-stage cp.async ring.
// Epilogues: EPI=0 plain fp32 (+bias), EPI=1 rope+split head-major,
//            EPI=2 split-only head-major.
// ===========================================================================
#define BUF_BYTES   16384
#define STAGE_BYTES 32768
#define KCHUNKS     16
#define NT          (3*KCHUNKS)
#define GEMM_SMEM   (4*STAGE_BYTES)

template<int EPI, bool HAS_BIAS>
__global__ void __launch_bounds__(256) gemm_bf16x3_tc(
    const __nv_bfloat16* __restrict__ Ah, const __nv_bfloat16* __restrict__ Al,
    const __nv_bfloat16* __restrict__ Bh, const __nv_bfloat16* __restrict__ Bl,
    const float* __restrict__ bias, const float2* __restrict__ tab,
    float* __restrict__ Cf,
    __nv_bfloat16* __restrict__ Ch, __nv_bfloat16* __restrict__ Cl,
    int M, int N, int K)
{
    extern __shared__ __align__(1024) char smem[];
    const unsigned sbase = (unsigned)__cvta_generic_to_shared(smem);

    const int tid  = threadIdx.x;
    const int lane = tid & 31;
    const int warp = tid >> 5;
    const int wm   = warp >> 1;
    const int wn   = warp & 1;
    const int bm   = blockIdx.y * 128;
    const int bn   = blockIdx.x * 128;
    const int q    = lane & 7;
    const int g    = lane >> 3;

    unsigned dst_off[4];
    size_t   a_off[4], b_off[4];
    #pragma unroll
    for (int i = 0; i < 4; i++) {
        int idx = tid + i * 256;
        int r   = idx >> 3;
        int ch  = idx & 7;
        dst_off[i] = (unsigned)(r * 128 + ((ch * 16) ^ ((r & 7) << 4)));
        a_off[i]   = (size_t)(bm + r) * K + ch * 8;
        b_off[i]   = (size_t)(bn + r) * K + ch * 8;
    }

    int a_rowterm[2], akb;
    {
        int row_a = (g & 1) * 8 + q;
        akb = (g >> 1) * 16;
        #pragma unroll
        for (int mt = 0; mt < 2; mt++)
            a_rowterm[mt] = (wm * 32 + mt * 16 + row_a) * 128;
    }
    int b_rowterm[4], bkb;
    {
        int row_b = (g >> 1) * 8 + q;
        bkb = (g & 1) * 16;
        #pragma unroll
        for (int p = 0; p < 4; p++)
            b_rowterm[p] = (wn * 64 + p * 16 + row_b) * 128;
    }

    float acc[2][8][4];
    #pragma unroll
    for (int mt = 0; mt < 2; mt++)
        #pragma unroll
        for (int nt = 0; nt < 8; nt++)
            #pragma unroll
            for (int r = 0; r < 4; r++) acc[mt][nt][r] = 0.f;

    auto issue = [&](int t, int st) {
        int ph = t >> 4;
        int kt = t & 15;
        const __nv_bfloat16* Ap = (ph == 2) ? Al : Ah;
        const __nv_bfloat16* Bp = (ph == 1) ? Bl : Bh;
        unsigned aS = sbase + st * STAGE_BYTES;
        unsigned bS = aS + BUF_BYTES;
        size_t kofs = (size_t)kt * 64;
        #pragma unroll
        for (int i = 0; i < 4; i++) {
            cp16(aS + dst_off[i], Ap + a_off[i] + kofs);
            cp16(bS + dst_off[i], Bp + b_off[i] + kofs);
        }
        CP_COMMIT();
    };

    issue(0, 0); issue(1, 1); issue(2, 2);

    for (int t = 0; t < NT; t++) {
        const int st = t & 3;
        if (t < NT - 2)       asm volatile("cp.async.wait_group 2;\n" ::: "memory");
        else if (t == NT - 2) asm volatile("cp.async.wait_group 1;\n" ::: "memory");
        else                  asm volatile("cp.async.wait_group 0;\n" ::: "memory");
        __syncthreads();
        if (t + 3 < NT) issue(t + 3, (t + 3) & 3);

        unsigned aS = sbase + st * STAGE_BYTES;
        unsigned bS = aS + BUF_BYTES;
        #pragma unroll
        for (int ks = 0; ks < 4; ks++) {
            unsigned af[2][4];
            #pragma unroll
            for (int mt = 0; mt < 2; mt++)
                LDSM4(af[mt], aS + a_rowterm[mt] + ((ks * 32 + akb) ^ (q << 4)));
            unsigned bf_[4][4];
            #pragma unroll
            for (int p = 0; p < 4; p++)
                LDSM4(bf_[p], bS + b_rowterm[p] + ((ks * 32 + bkb) ^ (q << 4)));
            #pragma unroll
            for (int mt = 0; mt < 2; mt++)
                #pragma unroll
                for (int nt = 0; nt < 8; nt++) {
                    const unsigned* bp = bf_[nt >> 1];
                    if (nt & 1) mma_bf16(acc[mt][nt], af[mt], bp[2], bp[3]);
                    else        mma_bf16(acc[mt][nt], af[mt], bp[0], bp[1]);
                }
        }
    }

    const int lr = lane >> 2;
    const int lc = (lane & 3) * 2;
    #pragma unroll
    for (int mt = 0; mt < 2; mt++) {
        #pragma unroll
        for (int nt = 0; nt < 8; nt++) {
            int row = bm + wm * 32 + mt * 16 + lr;
            int col = bn + wn * 64 + nt * 8 + lc;
            float x0 = acc[mt][nt][0], y0 = acc[mt][nt][1];
            float x1 = acc[mt][nt][2], y1 = acc[mt][nt][3];
            if (EPI == 0) {
                if (HAS_BIAS) {
                    float b0 = bias[col], b1 = bias[col + 1];
                    x0 += b0; y0 += b1; x1 += b0; y1 += b1;
                }
                *reinterpret_cast<float2*>(&Cf[(size_t)row * N + col])       = make_float2(x0, y0);
                *reinterpret_cast<float2*>(&Cf[(size_t)(row + 8) * N + col]) = make_float2(x1, y1);
            } else {
                int s0 = row & (SEQ - 1);
                int s1 = (row + 8) & (SEQ - 1);
                int bb = row >> 11;
                int hh = col >> 6;
                int dd = col & 63;
                size_t base = (size_t)(bb * NH + hh) * SEQ;
                size_t e0 = (base + s0) * HD + dd;
                size_t e1 = (base + s1) * HD + dd;
                if (EPI == 1) {
                    float2 cs0 = tab[s0 * 32 + (dd >> 1)];
                    float2 cs1 = tab[s1 * 32 + (dd >> 1)];
                    float rx = x0 * cs0.x - y0 * cs0.y;
                    float ry = y0 * cs0.x + x0 * cs0.y;
                    x0 = rx; y0 = ry;
                    rx = x1 * cs1.x - y1 * cs1.y;
                    ry = y1 * cs1.x + x1 * cs1.y;
                    x1 = rx; y1 = ry;
                }
                float hx0 = __bfloat162float(__float2bfloat16_rn(x0));
                float hy0 = __bfloat162float(__float2bfloat16_rn(y0));
                float hx1 = __bfloat162float(__float2bfloat16_rn(x1));
                float hy1 = __bfloat162float(__float2bfloat16_rn(y1));
                *reinterpret_cast<unsigned*>(Ch + e0) = pack_bf16x2(hx0, hy0);
                *reinterpret_cast<unsigned*>(Cl + e0) = pack_bf16x2(x0 - hx0, y0 - hy0);
                *reinterpret_cast<unsigned*>(Ch + e1) = pack_bf16x2(hx1, hy1);
                *reinterpret_cast<unsigned*>(Cl + e1) = pack_bf16x2(x1 - hx1, y1 - hy1);
            }
        }
    }
}

// ===========================================================================
// Tensor-core causal flash attention, bf16x3 for BOTH S=QK^T and O=PV.
// Block: 128 queries x 1 head x 1 batch; heavy tiles launched FIRST.
// Outputs ctx as hi/lo bf16 (row-major) for the Wo GEMM.
// ===========================================================================
#define AT_STAGE  33024
#define AT_SMEM   (32768 + 3*AT_STAGE)   // 131840

__global__ void __launch_bounds__(256) attn_tc_kernel(
    const __nv_bfloat16* __restrict__ qh, const __nv_bfloat16* __restrict__ ql,
    const __nv_bfloat16* __restrict__ kh, const __nv_bfloat16* __restrict__ kl,
    const __nv_bfloat16* __restrict__ vh, const __nv_bfloat16* __restrict__ vl,
    const int* __restrict__ am,
    __nv_bfloat16* __restrict__ coh, __nv_bfloat16* __restrict__ col_)
{
    extern __shared__ __align__(1024) char smem[];
    const unsigned sb  = (unsigned)__cvta_generic_to_shared(smem);
    const unsigned sQh = sb, sQl = sb + 16384;

    const int tid  = threadIdx.x;
    const int lane = tid & 31;
    const int w    = tid >> 5;
    const int q    = lane & 7;
    const int g    = lane >> 3;
    const int qt   = (gridDim.x - 1) - blockIdx.x;   // heavy tiles first
    const int h = blockIdx.y, b = blockIdx.z;
    const int qb   = qt * 128;
    const size_t headbase = (size_t)(b * NH + h) * SEQ;

    #pragma unroll
    for (int i = 0; i < 4; i++) {
        int idx = tid + i * 256;
        int r = idx >> 3, ch = idx & 7;
        unsigned dst = (unsigned)(r * 128 + ((ch * 16) ^ ((r & 7) << 4)));
        size_t gidx = (headbase + qb + r) * HD + ch * 8;
        cp16(sQh + dst, qh + gidx);
        cp16(sQl + dst, ql + gidx);
    }
    CP_COMMIT();

    const int nkt = qt * 2 + 2;

    auto issue = [&](int kt, int st) {
        unsigned s0 = sb + 32768 + st * AT_STAGE;
        #pragma unroll
        for (int i = 0; i < 8; i++) {
            int idx = tid + i * 256;
            int buf = idx >> 9;
            int r   = (idx & 511) >> 3;
            int ch  = idx & 7;
            unsigned dst = s0 + buf * 8192 +
                           (unsigned)(r * 128 + ((ch * 16) ^ ((r & 7) << 4)));
            size_t gidx = (headbase + kt * 64 + r) * HD + ch * 8;
            const __nv_bfloat16* src = (buf == 0) ? kh : (buf == 1) ? kl
                                      : (buf == 2) ? vh : vl;
            cp16(dst, src + gidx);
        }
        if (tid < 16) cp16(s0 + 32768, am + b * SEQ + kt * 64 + tid * 4);
        CP_COMMIT();
    };

    issue(0, 0);
    issue(1, 1);

    float o[8][4];
    #pragma unroll
    for (int j = 0; j < 8; j++)
        #pragma unroll
        for (int r = 0; r < 4; r++) o[j][r] = 0.f;
    float m0 = -1e30f, m1 = -1e30f, l0 = 0.f, l1 = 0.f;

    unsigned qhf[4][4], qlf[4][4];

    const int row0 = qb + w * 16 + (lane >> 2);
    const int row1 = row0 + 8;
    const int c2   = 2 * (lane & 3);

    for (int kt = 0; kt < nkt; kt++) {
        const int st = kt % 3;
        if (kt + 1 < nkt) asm volatile("cp.async.wait_group 1;\n" ::: "memory");
        else              asm volatile("cp.async.wait_group 0;\n" ::: "memory");
        __syncthreads();
        if (kt + 2 < nkt) issue(kt + 2, (kt + 2) % 3);

        if (kt == 0) {
            #pragma unroll
            for (int ks = 0; ks < 4; ks++) {
                unsigned ab = (unsigned)((w * 16 + (g & 1) * 8 + q) * 128) +
                              ((unsigned)(ks * 32 + (g >> 1) * 16) ^ (unsigned)(q << 4));
                LDSM4(qhf[ks], sQh + ab);
                LDSM4(qlf[ks], sQl + ab);
            }
        }

        unsigned sK  = sb + 32768 + st * AT_STAGE;
        unsigned sKl = sK + 8192;
        unsigned sVh = sK + 16384;
        unsigned sVl = sK + 24576;
        const int2* mp = reinterpret_cast<const int2*>(smem + 32768 + st * AT_STAGE + 32768);

        float sc_[8][4];
        #pragma unroll
        for (int j = 0; j < 8; j++)
            #pragma unroll
            for (int r = 0; r < 4; r++) sc_[j][r] = 0.f;

        #pragma unroll
        for (int ks = 0; ks < 4; ks++) {
            unsigned kb = ((unsigned)(ks * 32 + (g & 1) * 16)) ^ (unsigned)(q << 4);
            #pragma unroll
            for (int p = 0; p < 4; p++) {
                unsigned rowoff = (unsigned)((p * 16 + (g >> 1) * 8 + q) * 128);
                unsigned kf[4], kf2[4];
                LDSM4(kf,  sK  + rowoff + kb);
                LDSM4(kf2, sKl + rowoff + kb);
                mma_bf16(sc_[2*p],   qhf[ks], kf[0],  kf[1]);
                mma_bf16(sc_[2*p+1], qhf[ks], kf[2],  kf[3]);
                mma_bf16(sc_[2*p],   qlf[ks], kf[0],  kf[1]);
                mma_bf16(sc_[2*p+1], qlf[ks], kf[2],  kf[3]);
                mma_bf16(sc_[2*p],   qhf[ks], kf2[0], kf2[1]);
                mma_bf16(sc_[2*p+1], qhf[ks], kf2[2], kf2[3]);
            }
        }

        #pragma unroll
        for (int j = 0; j < 8; j++) {
            int c0 = kt * 64 + 8 * j + c2;
            int2 mk = mp[4 * j + (lane & 3)];
            sc_[j][0] = (c0     <= row0 && mk.x) ? sc_[j][0] * 0.125f : -1e30f;
            sc_[j][1] = (c0 + 1 <= row0 && mk.y) ? sc_[j][1] * 0.125f : -1e30f;
            sc_[j][2] = (c0     <= row1 && mk.x) ? sc_[j][2] * 0.125f : -1e30f;
            sc_[j][3] = (c0 + 1 <= row1 && mk.y) ? sc_[j][3] * 0.125f : -1e30f;
        }

        float mx0 = -1e30f, mx1 = -1e30f;
        #pragma unroll
        for (int j = 0; j < 8; j++) {
            mx0 = fmaxf(mx0, fmaxf(sc_[j][0], sc_[j][1]));
            mx1 = fmaxf(mx1, fmaxf(sc_[j][2], sc_[j][3]));
        }
        mx0 = fmaxf(mx0, __shfl_xor_sync(0xffffffffu, mx0, 1));
        mx0 = fmaxf(mx0, __shfl_xor_sync(0xffffffffu, mx0, 2));
        mx1 = fmaxf(mx1, __shfl_xor_sync(0xffffffffu, mx1, 1));
        mx1 = fmaxf(mx1, __shfl_xor_sync(0xffffffffu, mx1, 2));
        float mn0 = fmaxf(m0, mx0), mn1 = fmaxf(m1, mx1);
        float a0 = __expf(m0 - mn0), a1 = __expf(m1 - mn1);
        m0 = mn0; m1 = mn1;
        float s0s = 0.f, s1s = 0.f;
        #pragma unroll
        for (int j = 0; j < 8; j++) {
            sc_[j][0] = __expf(sc_[j][0] - mn0);
            sc_[j][1] = __expf(sc_[j][1] - mn0);
            sc_[j][2] = __expf(sc_[j][2] - mn1);
            sc_[j][3] = __expf(sc_[j][3] - mn1);
            s0s += sc_[j][0] + sc_[j][1];
            s1s += sc_[j][2] + sc_[j][3];
        }
        s0s += __shfl_xor_sync(0xffffffffu, s0s, 1);
        s0s += __shfl_xor_sync(0xffffffffu, s0s, 2);
        s1s += __shfl_xor_sync(0xffffffffu, s1s, 1);
        s1s += __shfl_xor_sync(0xffffffffu, s1s, 2);
        l0 = l0 * a0 + s0s;
        l1 = l1 * a1 + s1s;
        #pragma unroll
        for (int j = 0; j < 8; j++) {
            o[j][0] *= a0; o[j][1] *= a0;
            o[j][2] *= a1; o[j][3] *= a1;
        }

        unsigned pkh[4][4], pkl[4][4];
        #pragma unroll
        for (int ks = 0; ks < 4; ks++) {
            float a0h0 = __bfloat162float(__float2bfloat16_rn(sc_[2*ks][0]));
            float a0h1 = __bfloat162float(__float2bfloat16_rn(sc_[2*ks][1]));
            float a1h0 = __bfloat162float(__float2bfloat16_rn(sc_[2*ks][2]));
            float a1h1 = __bfloat162float(__float2bfloat16_rn(sc_[2*ks][3]));
            float b0h0 = __bfloat162float(__float2bfloat16_rn(sc_[2*ks+1][0]));
            float b0h1 = __bfloat162float(__float2bfloat16_rn(sc_[2*ks+1][1]));
            float b1h0 = __bfloat162float(__float2bfloat16_rn(sc_[2*ks+1][2]));
            float b1h1 = __bfloat162float(__float2bfloat16_rn(sc_[2*ks+1][3]));
            pkh[ks][0] = pack_bf16x2(a0h0, a0h1);
            pkh[ks][1] = pack_bf16x2(a1h0, a1h1);
            pkh[ks][2] = pack_bf16x2(b0h0, b0h1);
            pkh[ks][3] = pack_bf16x2(b1h0, b1h1);
            pkl[ks][0] = pack_bf16x2(sc_[2*ks][0] - a0h0,   sc_[2*ks][1] - a0h1);
            pkl[ks][1] = pack_bf16x2(sc_[2*ks][2] - a1h0,   sc_[2*ks][3] - a1h1);
            pkl[ks][2] = pack_bf16x2(sc_[2*ks+1][0] - b0h0, sc_[2*ks+1][1] - b0h1);
            pkl[ks][3] = pack_bf16x2(sc_[2*ks+1][2] - b1h0, sc_[2*ks+1][3] - b1h1);
        }

        #pragma unroll
        for (int ks = 0; ks < 4; ks++) {
            int sl = ks * 16 + (lane & 15);
            unsigned vrowh = sVh + (unsigned)(sl * 128);
            unsigned vrowl = sVl + (unsigned)(sl * 128);
            unsigned swz   = (unsigned)((sl & 7) << 4);
            #pragma unroll
            for (int j = 0; j < 4; j++) {
                unsigned coff = ((unsigned)((2*j + (lane >> 4)) * 16)) ^ swz;
                unsigned vfh[4], vfl[4];
                LDSM4T(vfh, vrowh + coff);
                LDSM4T(vfl, vrowl + coff);
                mma_bf16(o[2*j],   pkh[ks], vfh[0], vfh[1]);
                mma_bf16(o[2*j+1], pkh[ks], vfh[2], vfh[3]);
                mma_bf16(o[2*j],   pkl[ks], vfh[0], vfh[1]);
                mma_bf16(o[2*j+1], pkl[ks], vfh[2], vfh[3]);
                mma_bf16(o[2*j],   pkh[ks], vfl[0], vfl[1]);
                mma_bf16(o[2*j+1], pkh[ks], vfl[2], vfl[3]);
            }
        }
    }

    // ---- normalize + hi/lo split + store (row-major for Wo GEMM) ----
    float i0 = (l0 > 0.f) ? 1.f / l0 : 0.f;
    float i1 = (l1 > 0.f) ? 1.f / l1 : 0.f;
    size_t gr0 = (size_t)(b * SEQ + row0) * DM + h * HD;
    size_t gr1 = (size_t)(b * SEQ + row1) * DM + h * HD;
    #pragma unroll
    for (int j = 0; j < 8; j++) {
        int d = 8 * j + c2;
        float x0 = o[j][0] * i0, y0 = o[j][1] * i0;
        float x1 = o[j][2] * i1, y1 = o[j][3] * i1;
        float hx0 = __bfloat162float(__float2bfloat16_rn(x0));
        float hy0 = __bfloat162float(__float2bfloat16_rn(y0));
        float hx1 = __bfloat162float(__float2bfloat16_rn(x1));
        float hy1 = __bfloat162float(__float2bfloat16_rn(y1));
        *reinterpret_cast<unsigned*>(coh  + gr0 + d) = pack_bf16x2(hx0, hy0);
        *reinterpret_cast<unsigned*>(col_ + gr0 + d) = pack_bf16x2(x0 - hx0, y0 - hy0);
        *reinterpret_cast<unsigned*>(coh  + gr1 + d) = pack_bf16x2(hx1, hy1);
        *reinterpret_cast<unsigned*>(col_ + gr1 + d) = pack_bf16x2(x1 - hx1, y1 - hy1);
    }
}

// ---------------------------------------------------------------------------
extern "C" void kernel_launch(void* const* d_in, const int* in_sizes, int n_in,
                              void* d_out, int out_size)
{
    const float* Q  = (const float*)d_in[0];
    const float* K  = (const float*)d_in[1];
    const float* V  = (const float*)d_in[2];
    const int*   am = (const int*)  d_in[3];
    const float* Wq = (const float*)d_in[4];
    const float* Wk = (const float*)d_in[5];
    const float* Wv = (const float*)d_in[6];
    const float* Wo = (const float*)d_in[7];
    const float* bo = (const float*)d_in[8];
    float* out = (float*)d_out;

    __nv_bfloat16 *ah, *al, *bh, *bl, *qqh, *qql, *kkh, *kkl, *vvh, *vvl;
    float2* tab;
    cudaGetSymbolAddress((void**)&ah,  g_ah);
    cudaGetSymbolAddress((void**)&al,  g_al);
    cudaGetSymbolAddress((void**)&bh,  g_bh);
    cudaGetSymbolAddress((void**)&bl,  g_bl);
    cudaGetSymbolAddress((void**)&qqh, g_qh);
    cudaGetSymbolAddress((void**)&qql, g_ql);
    cudaGetSymbolAddress((void**)&kkh, g_kh);
    cudaGetSymbolAddress((void**)&kkl, g_kl);
    cudaGetSymbolAddress((void**)&vvh, g_vh);
    cudaGetSymbolAddress((void**)&vvl, g_vl);
    cudaGetSymbolAddress((void**)&tab, g_tab);

    const int nA4 = MROWS * DM / 4;
    const int nB4 = DM * DM / 4;
    const dim3 gemm_grid(DM / 128, MROWS / 128);

    cudaFuncSetAttribute(gemm_bf16x3_tc<0,true>,
                         cudaFuncAttributeMaxDynamicSharedMemorySize, GEMM_SMEM);
    cudaFuncSetAttribute(gemm_bf16x3_tc<1,false>,
                         cudaFuncAttributeMaxDynamicSharedMemorySize, GEMM_SMEM);
    cudaFuncSetAttribute(gemm_bf16x3_tc<2,false>,
                         cudaFuncAttributeMaxDynamicSharedMemorySize, GEMM_SMEM);
    cudaFuncSetAttribute(attn_tc_kernel,
                         cudaFuncAttributeMaxDynamicSharedMemorySize, AT_SMEM);

    rope_tab_kernel<<<(SEQ * 32 + 255) / 256, 256>>>(tab);

    // Q projection (rope+split epilogue, head-major)
    split_kernel<<<(nA4 + 255) / 256, 256>>>(Q, ah, al, nA4);
    split_kernel<<<(nB4 + 255) / 256, 256>>>(Wq, bh, bl, nB4);
    gemm_bf16x3_tc<1,false><<<gemm_grid, 256, GEMM_SMEM>>>(
        ah, al, bh, bl, nullptr, tab, nullptr, qqh, qql, MROWS, DM, DM);
    // K projection
    split_kernel<<<(nA4 + 255) / 256, 256>>>(K, ah, al, nA4);
    split_kernel<<<(nB4 + 255) / 256, 256>>>(Wk, bh, bl, nB4);
    gemm_bf16x3_tc<1,false><<<gemm_grid, 256, GEMM_SMEM>>>(
        ah, al, bh, bl, nullptr, tab, nullptr, kkh, kkl, MROWS, DM, DM);
    // V projection (split-only epilogue, head-major)
    split_kernel<<<(nA4 + 255) / 256, 256>>>(V, ah, al, nA4);
    split_kernel<<<(nB4 + 255) / 256, 256>>>(Wv, bh, bl, nB4);
    gemm_bf16x3_tc<2,false><<<gemm_grid, 256, GEMM_SMEM>>>(
        ah, al, bh, bl, nullptr, tab, nullptr, vvh, vvl, MROWS, DM, DM);

    // Tensor-core flash attention -> ctx split (reuses ah/al)
    attn_tc_kernel<<<dim3(SEQ / 128, NH, BATCH), 256, AT_SMEM>>>(
        qqh, qql, kkh, kkl, vvh, vvl, am, ah, al);

    // Output projection
    split_kernel<<<(nB4 + 255) / 256, 256>>>(Wo, bh, bl, nB4);
    gemm_bf16x3_tc<0,true><<<gemm_grid, 256, GEMM_SMEM>>>(
        ah, al, bh, bl, bo, tab, out, nullptr, nullptr, MROWS, DM, DM);
}

// round 15
// speedup vs baseline: 3.4354x; 1.0966x over previous
#include <cuda_runtime.h>
#include <cuda_bf16.h>
#include <math.h>
#include <stdint.h>

#define DM   1024
#define NH   16
#define HD   64
#define SEQ  2048
#define BATCH 2
#define MROWS (BATCH*SEQ)   // 4096
#define NA4  (MROWS*DM/4)   // 1048576 = 2^20
#define NB4  (DM*DM/4)      // 262144  = 2^18

// Scratch (static device arrays — no allocation allowed)
__device__ __nv_bfloat16 g_xh[3][MROWS*DM];  // Q,K,V input splits (hi)
__device__ __nv_bfloat16 g_xl[3][MROWS*DM];  // (lo)
__device__ __nv_bfloat16 g_wh[4][DM*DM];     // Wq,Wk,Wv,Wo splits (hi)
__device__ __nv_bfloat16 g_wl[4][DM*DM];     // (lo)
__device__ __nv_bfloat16 g_ah[MROWS*DM];     // ctx split (attention output)
__device__ __nv_bfloat16 g_al[MROWS*DM];
__device__ __nv_bfloat16 g_qh[MROWS*DM];     // head-major, rope applied
__device__ __nv_bfloat16 g_ql[MROWS*DM];
__device__ __nv_bfloat16 g_kh[MROWS*DM];
__device__ __nv_bfloat16 g_kl[MROWS*DM];
__device__ __nv_bfloat16 g_vh[MROWS*DM];
__device__ __nv_bfloat16 g_vl[MROWS*DM];
__device__ float2 g_tab[SEQ*32];             // (cos, sin) per (s, pair)

// ===========================================================================
// Common PTX helpers
// ===========================================================================
__device__ __forceinline__ void mma_bf16(float c[4], const unsigned a[4], unsigned b0, unsigned b1)
{
    asm volatile(
        "mma.sync.aligned.m16n8k16.row.col.f32.bf16.bf16.f32 "
        "{%0,%1,%2,%3}, {%4,%5,%6,%7}, {%8,%9}, {%0,%1,%2,%3};\n"
        : "+f"(c[0]), "+f"(c[1]), "+f"(c[2]), "+f"(c[3])
        : "r"(a[0]), "r"(a[1]), "r"(a[2]), "r"(a[3]), "r"(b0), "r"(b1));
}
__device__ __forceinline__ void cp16(unsigned saddr, const void* gptr)
{
    asm volatile("cp.async.cg.shared.global [%0], [%1], 16;\n" :: "r"(saddr), "l"(gptr));
}
#define CP_COMMIT() asm volatile("cp.async.commit_group;\n" ::: "memory")
#define LDSM4(r, addr) \
    asm volatile("ldmatrix.sync.aligned.m8n8.x4.shared.b16 {%0,%1,%2,%3}, [%4];" \
        : "=r"((r)[0]), "=r"((r)[1]), "=r"((r)[2]), "=r"((r)[3]) : "r"(addr))
#define LDSM4T(r, addr) \
    asm volatile("ldmatrix.sync.aligned.m8n8.x4.trans.shared.b16 {%0,%1,%2,%3}, [%4];" \
        : "=r"((r)[0]), "=r"((r)[1]), "=r"((r)[2]), "=r"((r)[3]) : "r"(addr))

__device__ __forceinline__ unsigned pack_bf16x2(float lo, float hi)
{
    __nv_bfloat162 p = __float22bfloat162_rn(make_float2(lo, hi));
    return *reinterpret_cast<unsigned*>(&p);
}

// ===========================================================================
// RoPE cos/sin table
// ===========================================================================
__global__ void rope_tab_kernel(float2* __restrict__ tab)
{
    int idx = blockIdx.x * blockDim.x + threadIdx.x;
    if (idx >= SEQ * 32) return;
    int s = idx >> 5, i = idx & 31;
    float theta = powf(10000.0f, -(float)(2 * i) * (1.0f / 64.0f));
    float sn, cs;
    sincosf((float)s * theta, &sn, &cs);
    tab[idx] = make_float2(cs, sn);
}

// ===========================================================================
// Fused split of ALL inputs+weights: fp32 -> (hi bf16, lo bf16).
// idx < 3*NA4: inputs Q,K,V; else: weights Wq,Wk,Wv,Wo.
// ===========================================================================
__global__ void split_all_kernel(
    const float* __restrict__ Q, const float* __restrict__ K, const float* __restrict__ V,
    const float* __restrict__ Wq, const float* __restrict__ Wk,
    const float* __restrict__ Wv, const float* __restrict__ Wo,
    __nv_bfloat16* __restrict__ xh, __nv_bfloat16* __restrict__ xl,
    __nv_bfloat16* __restrict__ wh, __nv_bfloat16* __restrict__ wl)
{
    int idx = blockIdx.x * blockDim.x + threadIdx.x;
    const int NIN = 3 * NA4;
    const float* src;
    __nv_bfloat16 *hi, *lo;
    int r;
    if (idx < NIN) {
        int i = idx >> 20;            // / NA4
        r = idx & (NA4 - 1);
        src = (i == 0) ? Q : (i == 1) ? K : V;
        hi = xh + (size_t)i * (MROWS * DM);
        lo = xl + (size_t)i * (MROWS * DM);
    } else {
        int t = idx - NIN;
        if (t >= 4 * NB4) return;
        int j = t >> 18;              // / NB4
        r = t & (NB4 - 1);
        src = (j == 0) ? Wq : (j == 1) ? Wk : (j == 2) ? Wv : Wo;
        hi = wh + (size_t)j * (DM * DM);
        lo = wl + (size_t)j * (DM * DM);
    }
    float4 v = reinterpret_cast<const float4*>(src)[r];
    float h0 = __bfloat162float(__float2bfloat16_rn(v.x));
    float h1 = __bfloat162float(__float2bfloat16_rn(v.y));
    float h2 = __bfloat162float(__float2bfloat16_rn(v.z));
    float h3 = __bfloat162float(__float2bfloat16_rn(v.w));
    uint2 hw, lw;
    hw.x = pack_bf16x2(h0, h1);
    hw.y = pack_bf16x2(h2, h3);
    lw.x = pack_bf16x2(v.x - h0, v.y - h1);
    lw.y = pack_bf16x2(v.z - h2, v.w - h3);
    reinterpret_cast<uint2*>(hi)[r] = hw;
    reinterpret_cast<uint2*>(lo)[r] = lw;
}

// ===========================================================================
// Tensor-core bf16x3 GEMM (NT) over virtual K' = 3K, 3-stage cp.async ring.
// 96 KB smem -> 2 CTAs/SM (16 warps). Epilogues: 0 fp32+bias, 1 rope+split
// head-major, 2 split-only head-major.
// ===========================================================================
#define BUF_BYTES   16384
#define STAGE_BYTES 32768
#define NSTAGE      3
#define KCHUNKS     16
#define NT          (3*KCHUNKS)
#define GEMM_SMEM   (NSTAGE*STAGE_BYTES)   // 98304

template<int EPI, bool HAS_BIAS>
__global__ void __launch_bounds__(256, 2) gemm_bf16x3_tc(
    const __nv_bfloat16* __restrict__ Ah, const __nv_bfloat16* __restrict__ Al,
    const __nv_bfloat16* __restrict__ Bh, const __nv_bfloat16* __restrict__ Bl,
    const float* __restrict__ bias, const float2* __restrict__ tab,
    float* __restrict__ Cf,
    __nv_bfloat16* __restrict__ Ch, __nv_bfloat16* __restrict__ Cl,
    int M, int N, int K)
{
    extern __shared__ __align__(1024) char smem[];
    const unsigned sbase = (unsigned)__cvta_generic_to_shared(smem);

    const int tid  = threadIdx.x;
    const int lane = tid & 31;
    const int warp = tid >> 5;
    const int wm   = warp >> 1;
    const int wn   = warp & 1;
    const int bm   = blockIdx.y * 128;
    const int bn   = blockIdx.x * 128;
    const int q    = lane & 7;
    const int g    = lane >> 3;

    unsigned dst_off[4];
    size_t   a_off[4], b_off[4];
    #pragma unroll
    for (int i = 0; i < 4; i++) {
        int idx = tid + i * 256;
        int r   = idx >> 3;
        int ch  = idx & 7;
        dst_off[i] = (unsigned)(r * 128 + ((ch * 16) ^ ((r & 7) << 4)));
        a_off[i]   = (size_t)(bm + r) * K + ch * 8;
        b_off[i]   = (size_t)(bn + r) * K + ch * 8;
    }

    int a_rowterm[2], akb;
    {
        int row_a = (g & 1) * 8 + q;
        akb = (g >> 1) * 16;
        #pragma unroll
        for (int mt = 0; mt < 2; mt++)
            a_rowterm[mt] = (wm * 32 + mt * 16 + row_a) * 128;
    }
    int b_rowterm[4], bkb;
    {
        int row_b = (g >> 1) * 8 + q;
        bkb = (g & 1) * 16;
        #pragma unroll
        for (int p = 0; p < 4; p++)
            b_rowterm[p] = (wn * 64 + p * 16 + row_b) * 128;
    }

    float acc[2][8][4];
    #pragma unroll
    for (int mt = 0; mt < 2; mt++)
        #pragma unroll
        for (int nt = 0; nt < 8; nt++)
            #pragma unroll
            for (int r = 0; r < 4; r++) acc[mt][nt][r] = 0.f;

    auto issue = [&](int t, int st) {
        int ph = t >> 4;
        int kt = t & 15;
        const __nv_bfloat16* Ap = (ph == 2) ? Al : Ah;
        const __nv_bfloat16* Bp = (ph == 1) ? Bl : Bh;
        unsigned aS = sbase + st * STAGE_BYTES;
        unsigned bS = aS + BUF_BYTES;
        size_t kofs = (size_t)kt * 64;
        #pragma unroll
        for (int i = 0; i < 4; i++) {
            cp16(aS + dst_off[i], Ap + a_off[i] + kofs);
            cp16(bS + dst_off[i], Bp + b_off[i] + kofs);
        }
        CP_COMMIT();
    };

    issue(0, 0); issue(1, 1);

    for (int t = 0; t < NT; t++) {
        const int st = t % NSTAGE;
        if (t < NT - 1) asm volatile("cp.async.wait_group 1;\n" ::: "memory");
        else            asm volatile("cp.async.wait_group 0;\n" ::: "memory");
        __syncthreads();
        if (t + 2 < NT) issue(t + 2, (t + 2) % NSTAGE);

        unsigned aS = sbase + st * STAGE_BYTES;
        unsigned bS = aS + BUF_BYTES;
        #pragma unroll
        for (int ks = 0; ks < 4; ks++) {
            unsigned af[2][4];
            #pragma unroll
            for (int mt = 0; mt < 2; mt++)
                LDSM4(af[mt], aS + a_rowterm[mt] + ((ks * 32 + akb) ^ (q << 4)));
            unsigned bf_[4][4];
            #pragma unroll
            for (int p = 0; p < 4; p++)
                LDSM4(bf_[p], bS + b_rowterm[p] + ((ks * 32 + bkb) ^ (q << 4)));
            #pragma unroll
            for (int mt = 0; mt < 2; mt++)
                #pragma unroll
                for (int nt = 0; nt < 8; nt++) {
                    const unsigned* bp = bf_[nt >> 1];
                    if (nt & 1) mma_bf16(acc[mt][nt], af[mt], bp[2], bp[3]);
                    else        mma_bf16(acc[mt][nt], af[mt], bp[0], bp[1]);
                }
        }
    }

    const int lr = lane >> 2;
    const int lc = (lane & 3) * 2;
    #pragma unroll
    for (int mt = 0; mt < 2; mt++) {
        #pragma unroll
        for (int nt = 0; nt < 8; nt++) {
            int row = bm + wm * 32 + mt * 16 + lr;
            int col = bn + wn * 64 + nt * 8 + lc;
            float x0 = acc[mt][nt][0], y0 = acc[mt][nt][1];
            float x1 = acc[mt][nt][2], y1 = acc[mt][nt][3];
            if (EPI == 0) {
                if (HAS_BIAS) {
                    float b0 = bias[col], b1 = bias[col + 1];
                    x0 += b0; y0 += b1; x1 += b0; y1 += b1;
                }
                *reinterpret_cast<float2*>(&Cf[(size_t)row * N + col])       = make_float2(x0, y0);
                *reinterpret_cast<float2*>(&Cf[(size_t)(row + 8) * N + col]) = make_float2(x1, y1);
            } else {
                int s0 = row & (SEQ - 1);
                int s1 = (row + 8) & (SEQ - 1);
                int bb = row >> 11;
                int hh = col >> 6;
                int dd = col & 63;
                size_t base = (size_t)(bb * NH + hh) * SEQ;
                size_t e0 = (base + s0) * HD + dd;
                size_t e1 = (base + s1) * HD + dd;
                if (EPI == 1) {
                    float2 cs0 = tab[s0 * 32 + (dd >> 1)];
                    float2 cs1 = tab[s1 * 32 + (dd >> 1)];
                    float rx = x0 * cs0.x - y0 * cs0.y;
                    float ry = y0 * cs0.x + x0 * cs0.y;
                    x0 = rx; y0 = ry;
                    rx = x1 * cs1.x - y1 * cs1.y;
                    ry = y1 * cs1.x + x1 * cs1.y;
                    x1 = rx; y1 = ry;
                }
                float hx0 = __bfloat162float(__float2bfloat16_rn(x0));
                float hy0 = __bfloat162float(__float2bfloat16_rn(y0));
                float hx1 = __bfloat162float(__float2bfloat16_rn(x1));
                float hy1 = __bfloat162float(__float2bfloat16_rn(y1));
                *reinterpret_cast<unsigned*>(Ch + e0) = pack_bf16x2(hx0, hy0);
                *reinterpret_cast<unsigned*>(Cl + e0) = pack_bf16x2(x0 - hx0, y0 - hy0);
                *reinterpret_cast<unsigned*>(Ch + e1) = pack_bf16x2(hx1, hy1);
                *reinterpret_cast<unsigned*>(Cl + e1) = pack_bf16x2(x1 - hx1, y1 - hy1);
            }
        }
    }
}

// ===========================================================================
// Tensor-core causal flash attention, bf16x3 for BOTH S=QK^T and O=PV.
// 128 queries x head x batch; heavy tiles first; ctx emitted as hi/lo bf16.
// ===========================================================================
#define AT_STAGE  33024
#define AT_SMEM   (32768 + 3*AT_STAGE)   // 131840

__global__ void __launch_bounds__(256) attn_tc_kernel(
    const __nv_bfloat16* __restrict__ qh, const __nv_bfloat16* __restrict__ ql,
    const __nv_bfloat16* __restrict__ kh, const __nv_bfloat16* __restrict__ kl,
    const __nv_bfloat16* __restrict__ vh, const __nv_bfloat16* __restrict__ vl,
    const int* __restrict__ am,
    __nv_bfloat16* __restrict__ coh, __nv_bfloat16* __restrict__ col_)
{
    extern __shared__ __align__(1024) char smem[];
    const unsigned sb  = (unsigned)__cvta_generic_to_shared(smem);
    const unsigned sQh = sb, sQl = sb + 16384;

    const int tid  = threadIdx.x;
    const int lane = tid & 31;
    const int w    = tid >> 5;
    const int q    = lane & 7;
    const int g    = lane >> 3;
    const int qt   = (gridDim.x - 1) - blockIdx.x;   // heavy tiles first
    const int h = blockIdx.y, b = blockIdx.z;
    const int qb   = qt * 128;
    const size_t headbase = (size_t)(b * NH + h) * SEQ;

    #pragma unroll
    for (int i = 0; i < 4; i++) {
        int idx = tid + i * 256;
        int r = idx >> 3, ch = idx & 7;
        unsigned dst = (unsigned)(r * 128 + ((ch * 16) ^ ((r & 7) << 4)));
        size_t gidx = (headbase + qb + r) * HD + ch * 8;
        cp16(sQh + dst, qh + gidx);
        cp16(sQl + dst, ql + gidx);
    }
    CP_COMMIT();

    const int nkt = qt * 2 + 2;

    auto issue = [&](int kt, int st) {
        unsigned s0 = sb + 32768 + st * AT_STAGE;
        #pragma unroll
        for (int i = 0; i < 8; i++) {
            int idx = tid + i * 256;
            int buf = idx >> 9;
            int r   = (idx & 511) >> 3;
            int ch  = idx & 7;
            unsigned dst = s0 + buf * 8192 +
                           (unsigned)(r * 128 + ((ch * 16) ^ ((r & 7) << 4)));
            size_t gidx = (headbase + kt * 64 + r) * HD + ch * 8;
            const __nv_bfloat16* src = (buf == 0) ? kh : (buf == 1) ? kl
                                      : (buf == 2) ? vh : vl;
            cp16(dst, src + gidx);
        }
        if (tid < 16) cp16(s0 + 32768, am + b * SEQ + kt * 64 + tid * 4);
        CP_COMMIT();
    };

    issue(0, 0);
    issue(1, 1);

    float o[8][4];
    #pragma unroll
    for (int j = 0; j < 8; j++)
        #pragma unroll
        for (int r = 0; r < 4; r++) o[j][r] = 0.f;
    float m0 = -1e30f, m1 = -1e30f, l0 = 0.f, l1 = 0.f;

    unsigned qhf[4][4], qlf[4][4];

    const int row0 = qb + w * 16 + (lane >> 2);
    const int row1 = row0 + 8;
    const int c2   = 2 * (lane & 3);

    for (int kt = 0; kt < nkt; kt++) {
        const int st = kt % 3;
        if (kt + 1 < nkt) asm volatile("cp.async.wait_group 1;\n" ::: "memory");
        else              asm volatile("cp.async.wait_group 0;\n" ::: "memory");
        __syncthreads();
        if (kt + 2 < nkt) issue(kt + 2, (kt + 2) % 3);

        if (kt == 0) {
            #pragma unroll
            for (int ks = 0; ks < 4; ks++) {
                unsigned ab = (unsigned)((w * 16 + (g & 1) * 8 + q) * 128) +
                              ((unsigned)(ks * 32 + (g >> 1) * 16) ^ (unsigned)(q << 4));
                LDSM4(qhf[ks], sQh + ab);
                LDSM4(qlf[ks], sQl + ab);
            }
        }

        unsigned sK  = sb + 32768 + st * AT_STAGE;
        unsigned sKl = sK + 8192;
        unsigned sVh = sK + 16384;
        unsigned sVl = sK + 24576;
        const int2* mp = reinterpret_cast<const int2*>(smem + 32768 + st * AT_STAGE + 32768);

        float sc_[8][4];
        #pragma unroll
        for (int j = 0; j < 8; j++)
            #pragma unroll
            for (int r = 0; r < 4; r++) sc_[j][r] = 0.f;

        #pragma unroll
        for (int ks = 0; ks < 4; ks++) {
            unsigned kb = ((unsigned)(ks * 32 + (g & 1) * 16)) ^ (unsigned)(q << 4);
            #pragma unroll
            for (int p = 0; p < 4; p++) {
                unsigned rowoff = (unsigned)((p * 16 + (g >> 1) * 8 + q) * 128);
                unsigned kf[4], kf2[4];
                LDSM4(kf,  sK  + rowoff + kb);
                LDSM4(kf2, sKl + rowoff + kb);
                mma_bf16(sc_[2*p],   qhf[ks], kf[0],  kf[1]);
                mma_bf16(sc_[2*p+1], qhf[ks], kf[2],  kf[3]);
                mma_bf16(sc_[2*p],   qlf[ks], kf[0],  kf[1]);
                mma_bf16(sc_[2*p+1], qlf[ks], kf[2],  kf[3]);
                mma_bf16(sc_[2*p],   qhf[ks], kf2[0], kf2[1]);
                mma_bf16(sc_[2*p+1], qhf[ks], kf2[2], kf2[3]);
            }
        }

        #pragma unroll
        for (int j = 0; j < 8; j++) {
            int c0 = kt * 64 + 8 * j + c2;
            int2 mk = mp[4 * j + (lane & 3)];
            sc_[j][0] = (c0     <= row0 && mk.x) ? sc_[j][0] * 0.125f : -1e30f;
            sc_[j][1] = (c0 + 1 <= row0 && mk.y) ? sc_[j][1] * 0.125f : -1e30f;
            sc_[j][2] = (c0     <= row1 && mk.x) ? sc_[j][2] * 0.125f : -1e30f;
            sc_[j][3] = (c0 + 1 <= row1 && mk.y) ? sc_[j][3] * 0.125f : -1e30f;
        }

        float mx0 = -1e30f, mx1 = -1e30f;
        #pragma unroll
        for (int j = 0; j < 8; j++) {
            mx0 = fmaxf(mx0, fmaxf(sc_[j][0], sc_[j][1]));
            mx1 = fmaxf(mx1, fmaxf(sc_[j][2], sc_[j][3]));
        }
        mx0 = fmaxf(mx0, __shfl_xor_sync(0xffffffffu, mx0, 1));
        mx0 = fmaxf(mx0, __shfl_xor_sync(0xffffffffu, mx0, 2));
        mx1 = fmaxf(mx1, __shfl_xor_sync(0xffffffffu, mx1, 1));
        mx1 = fmaxf(mx1, __shfl_xor_sync(0xffffffffu, mx1, 2));
        float mn0 = fmaxf(m0, mx0), mn1 = fmaxf(m1, mx1);
        float a0 = __expf(m0 - mn0), a1 = __expf(m1 - mn1);
        m0 = mn0; m1 = mn1;
        float s0s = 0.f, s1s = 0.f;
        #pragma unroll
        for (int j = 0; j < 8; j++) {
            sc_[j][0] = __expf(sc_[j][0] - mn0);
            sc_[j][1] = __expf(sc_[j][1] - mn0);
            sc_[j][2] = __expf(sc_[j][2] - mn1);
            sc_[j][3] = __expf(sc_[j][3] - mn1);
            s0s += sc_[j][0] + sc_[j][1];
            s1s += sc_[j][2] + sc_[j][3];
        }
        s0s += __shfl_xor_sync(0xffffffffu, s0s, 1);
        s0s += __shfl_xor_sync(0xffffffffu, s0s, 2);
        s1s += __shfl_xor_sync(0xffffffffu, s1s, 1);
        s1s += __shfl_xor_sync(0xffffffffu, s1s, 2);
        l0 = l0 * a0 + s0s;
        l1 = l1 * a1 + s1s;
        #pragma unroll
        for (int j = 0; j < 8; j++) {
            o[j][0] *= a0; o[j][1] *= a0;
            o[j][2] *= a1; o[j][3] *= a1;
        }

        unsigned pkh[4][4], pkl[4][4];
        #pragma unroll
        for (int ks = 0; ks < 4; ks++) {
            float a0h0 = __bfloat162float(__float2bfloat16_rn(sc_[2*ks][0]));
            float a0h1 = __bfloat162float(__float2bfloat16_rn(sc_[2*ks][1]));
            float a1h0 = __bfloat162float(__float2bfloat16_rn(sc_[2*ks][2]));
            float a1h1 = __bfloat162float(__float2bfloat16_rn(sc_[2*ks][3]));
            float b0h0 = __bfloat162float(__float2bfloat16_rn(sc_[2*ks+1][0]));
            float b0h1 = __bfloat162float(__float2bfloat16_rn(sc_[2*ks+1][1]));
            float b1h0 = __bfloat162float(__float2bfloat16_rn(sc_[2*ks+1][2]));
            float b1h1 = __bfloat162float(__float2bfloat16_rn(sc_[2*ks+1][3]));
            pkh[ks][0] = pack_bf16x2(a0h0, a0h1);
            pkh[ks][1] = pack_bf16x2(a1h0, a1h1);
            pkh[ks][2] = pack_bf16x2(b0h0, b0h1);
            pkh[ks][3] = pack_bf16x2(b1h0, b1h1);
            pkl[ks][0] = pack_bf16x2(sc_[2*ks][0] - a0h0,   sc_[2*ks][1] - a0h1);
            pkl[ks][1] = pack_bf16x2(sc_[2*ks][2] - a1h0,   sc_[2*ks][3] - a1h1);
            pkl[ks][2] = pack_bf16x2(sc_[2*ks+1][0] - b0h0, sc_[2*ks+1][1] - b0h1);
            pkl[ks][3] = pack_bf16x2(sc_[2*ks+1][2] - b1h0, sc_[2*ks+1][3] - b1h1);
        }

        #pragma unroll
        for (int ks = 0; ks < 4; ks++) {
            int sl = ks * 16 + (lane & 15);
            unsigned vrowh = sVh + (unsigned)(sl * 128);
            unsigned vrowl = sVl + (unsigned)(sl * 128);
            unsigned swz   = (unsigned)((sl & 7) << 4);
            #pragma unroll
            for (int j = 0; j < 4; j++) {
                unsigned coff = ((unsigned)((2*j + (lane >> 4)) * 16)) ^ swz;
                unsigned vfh[4], vfl[4];
                LDSM4T(vfh, vrowh + coff);
                LDSM4T(vfl, vrowl + coff);
                mma_bf16(o[2*j],   pkh[ks], vfh[0], vfh[1]);
                mma_bf16(o[2*j+1], pkh[ks], vfh[2], vfh[3]);
                mma_bf16(o[2*j],   pkl[ks], vfh[0], vfh[1]);
                mma_bf16(o[2*j+1], pkl[ks], vfh[2], vfh[3]);
                mma_bf16(o[2*j],   pkh[ks], vfl[0], vfl[1]);
                mma_bf16(o[2*j+1], pkh[ks], vfl[2], vfl[3]);
            }
        }
    }

    // ---- normalize + hi/lo split + store (row-major for Wo GEMM) ----
    float i0 = (l0 > 0.f) ? 1.f / l0 : 0.f;
    float i1 = (l1 > 0.f) ? 1.f / l1 : 0.f;
    size_t gr0 = (size_t)(b * SEQ + row0) * DM + h * HD;
    size_t gr1 = (size_t)(b * SEQ + row1) * DM + h * HD;
    #pragma unroll
    for (int j = 0; j < 8; j++) {
        int d = 8 * j + c2;
        float x0 = o[j][0] * i0, y0 = o[j][1] * i0;
        float x1 = o[j][2] * i1, y1 = o[j][3] * i1;
        float hx0 = __bfloat162float(__float2bfloat16_rn(x0));
        float hy0 = __bfloat162float(__float2bfloat16_rn(y0));
        float hx1 = __bfloat162float(__float2bfloat16_rn(x1));
        float hy1 = __bfloat162float(__float2bfloat16_rn(y1));
        *reinterpret_cast<unsigned*>(coh  + gr0 + d) = pack_bf16x2(hx0, hy0);
        *reinterpret_cast<unsigned*>(col_ + gr0 + d) = pack_bf16x2(x0 - hx0, y0 - hy0);
        *reinterpret_cast<unsigned*>(coh  + gr1 + d) = pack_bf16x2(hx1, hy1);
        *reinterpret_cast<unsigned*>(col_ + gr1 + d) = pack_bf16x2(x1 - hx1, y1 - hy1);
    }
}

// ---------------------------------------------------------------------------
extern "C" void kernel_launch(void* const* d_in, const int* in_sizes, int n_in,
                              void* d_out, int out_size)
{
    const float* Q  = (const float*)d_in[0];
    const float* K  = (const float*)d_in[1];
    const float* V  = (const float*)d_in[2];
    const int*   am = (const int*)  d_in[3];
    const float* Wq = (const float*)d_in[4];
    const float* Wk = (const float*)d_in[5];
    const float* Wv = (const float*)d_in[6];
    const float* Wo = (const float*)d_in[7];
    const float* bo = (const float*)d_in[8];
    float* out = (float*)d_out;

    __nv_bfloat16 *xh, *xl, *wh, *wl, *ah, *al, *qqh, *qql, *kkh, *kkl, *vvh, *vvl;
    float2* tab;
    cudaGetSymbolAddress((void**)&xh,  g_xh);
    cudaGetSymbolAddress((void**)&xl,  g_xl);
    cudaGetSymbolAddress((void**)&wh,  g_wh);
    cudaGetSymbolAddress((void**)&wl,  g_wl);
    cudaGetSymbolAddress((void**)&ah,  g_ah);
    cudaGetSymbolAddress((void**)&al,  g_al);
    cudaGetSymbolAddress((void**)&qqh, g_qh);
    cudaGetSymbolAddress((void**)&qql, g_ql);
    cudaGetSymbolAddress((void**)&kkh, g_kh);
    cudaGetSymbolAddress((void**)&kkl, g_kl);
    cudaGetSymbolAddress((void**)&vvh, g_vh);
    cudaGetSymbolAddress((void**)&vvl, g_vl);
    cudaGetSymbolAddress((void**)&tab, g_tab);

    const dim3 gemm_grid(DM / 128, MROWS / 128);
    const int n_split = 3 * NA4 + 4 * NB4;

    cudaFuncSetAttribute(gemm_bf16x3_tc<0,true>,
                         cudaFuncAttributeMaxDynamicSharedMemorySize, GEMM_SMEM);
    cudaFuncSetAttribute(gemm_bf16x3_tc<1,false>,
                         cudaFuncAttributeMaxDynamicSharedMemorySize, GEMM_SMEM);
    cudaFuncSetAttribute(gemm_bf16x3_tc<2,false>,
                         cudaFuncAttributeMaxDynamicSharedMemorySize, GEMM_SMEM);
    cudaFuncSetAttribute(attn_tc_kernel,
                         cudaFuncAttributeMaxDynamicSharedMemorySize, AT_SMEM);

    rope_tab_kernel<<<(SEQ * 32 + 255) / 256, 256>>>(tab);
    split_all_kernel<<<(n_split + 255) / 256, 256>>>(
        Q, K, V, Wq, Wk, Wv, Wo, xh, xl, wh, wl);

    const size_t XN = (size_t)MROWS * DM;
    const size_t WN = (size_t)DM * DM;

    // Q projection (rope+split epilogue, head-major)
    gemm_bf16x3_tc<1,false><<<gemm_grid, 256, GEMM_SMEM>>>(
        xh, xl, wh, wl, nullptr, tab, nullptr, qqh, qql, MROWS, DM, DM);
    // K projection
    gemm_bf16x3_tc<1,false><<<gemm_grid, 256, GEMM_SMEM>>>(
        xh + XN, xl + XN, wh + WN, wl + WN, nullptr, tab, nullptr, kkh, kkl, MROWS, DM, DM);
    // V projection (split-only epilogue, head-major)
    gemm_bf16x3_tc<2,false><<<gemm_grid, 256, GEMM_SMEM>>>(
        xh + 2*XN, xl + 2*XN, wh + 2*WN, wl + 2*WN, nullptr, tab, nullptr, vvh, vvl, MROWS, DM, DM);

    // Tensor-core flash attention -> ctx split
    attn_tc_kernel<<<dim3(SEQ / 128, NH, BATCH), 256, AT_SMEM>>>(
        qqh, qql, kkh, kkl, vvh, vvl, am, ah, al);

    // Output projection
    gemm_bf16x3_tc<0,true><<<gemm_grid, 256, GEMM_SMEM>>>(
        ah, al, wh + 3*WN, wl + 3*WN, bo, tab, out, nullptr, nullptr, MROWS, DM, DM);
}

// round 16
// speedup vs baseline: 3.4476x; 1.0036x over previous
#include <cuda_runtime.h>
#include <cuda_bf16.h>
#include <math.h>
#include <stdint.h>

#define DM   1024
#define NH   16
#define HD   64
#define SEQ  2048
#define BATCH 2
#define MROWS (BATCH*SEQ)   // 4096
#define NA4  (MROWS*DM/4)   // 2^20
#define NB4  (DM*DM/4)      // 2^18

// Scratch (static device arrays — no allocation allowed)
__device__ __nv_bfloat16 g_xh[3][MROWS*DM];  // Q,K,V input splits (hi)
__device__ __nv_bfloat16 g_xl[3][MROWS*DM];  // (lo)
__device__ __nv_bfloat16 g_wh[4][DM*DM];     // Wq,Wk,Wv,Wo splits (hi)
__device__ __nv_bfloat16 g_wl[4][DM*DM];     // (lo)
__device__ __nv_bfloat16 g_ah[MROWS*DM];     // ctx split (attention output)
__device__ __nv_bfloat16 g_al[MROWS*DM];
__device__ __nv_bfloat16 g_qh[MROWS*DM];     // head-major, rope applied
__device__ __nv_bfloat16 g_ql[MROWS*DM];
__device__ __nv_bfloat16 g_kh[MROWS*DM];
__device__ __nv_bfloat16 g_kl[MROWS*DM];
__device__ __nv_bfloat16 g_vh[MROWS*DM];
__device__ __nv_bfloat16 g_vl[MROWS*DM];
__device__ float2 g_tab[SEQ*32];             // (cos, sin) per (s, pair)

// ===========================================================================
// Common PTX helpers
// ===========================================================================
__device__ __forceinline__ void mma_bf16(float c[4], const unsigned a[4], unsigned b0, unsigned b1)
{
    asm volatile(
        "mma.sync.aligned.m16n8k16.row.col.f32.bf16.bf16.f32 "
        "{%0,%1,%2,%3}, {%4,%5,%6,%7}, {%8,%9}, {%0,%1,%2,%3};\n"
        : "+f"(c[0]), "+f"(c[1]), "+f"(c[2]), "+f"(c[3])
        : "r"(a[0]), "r"(a[1]), "r"(a[2]), "r"(a[3]), "r"(b0), "r"(b1));
}
__device__ __forceinline__ void cp16(unsigned saddr, const void* gptr)
{
    asm volatile("cp.async.cg.shared.global [%0], [%1], 16;\n" :: "r"(saddr), "l"(gptr));
}
#define CP_COMMIT() asm volatile("cp.async.commit_group;\n" ::: "memory")
#define LDSM4(r, addr) \
    asm volatile("ldmatrix.sync.aligned.m8n8.x4.shared.b16 {%0,%1,%2,%3}, [%4];" \
        : "=r"((r)[0]), "=r"((r)[1]), "=r"((r)[2]), "=r"((r)[3]) : "r"(addr))
#define LDSM4T(r, addr) \
    asm volatile("ldmatrix.sync.aligned.m8n8.x4.trans.shared.b16 {%0,%1,%2,%3}, [%4];" \
        : "=r"((r)[0]), "=r"((r)[1]), "=r"((r)[2]), "=r"((r)[3]) : "r"(addr))

__device__ __forceinline__ unsigned pack_bf16x2(float lo, float hi)
{
    __nv_bfloat162 p = __float22bfloat162_rn(make_float2(lo, hi));
    return *reinterpret_cast<unsigned*>(&p);
}

// ===========================================================================
// RoPE cos/sin table
// ===========================================================================
__global__ void rope_tab_kernel(float2* __restrict__ tab)
{
    int idx = blockIdx.x * blockDim.x + threadIdx.x;
    if (idx >= SEQ * 32) return;
    int s = idx >> 5, i = idx & 31;
    float theta = powf(10000.0f, -(float)(2 * i) * (1.0f / 64.0f));
    float sn, cs;
    sincosf((float)s * theta, &sn, &cs);
    tab[idx] = make_float2(cs, sn);
}

// ===========================================================================
// Fused split of ALL inputs+weights
// ===========================================================================
__global__ void split_all_kernel(
    const float* __restrict__ Q, const float* __restrict__ K, const float* __restrict__ V,
    const float* __restrict__ Wq, const float* __restrict__ Wk,
    const float* __restrict__ Wv, const float* __restrict__ Wo,
    __nv_bfloat16* __restrict__ xh, __nv_bfloat16* __restrict__ xl,
    __nv_bfloat16* __restrict__ wh, __nv_bfloat16* __restrict__ wl)
{
    int idx = blockIdx.x * blockDim.x + threadIdx.x;
    const int NIN = 3 * NA4;
    const float* src;
    __nv_bfloat16 *hi, *lo;
    int r;
    if (idx < NIN) {
        int i = idx >> 20;
        r = idx & (NA4 - 1);
        src = (i == 0) ? Q : (i == 1) ? K : V;
        hi = xh + (size_t)i * (MROWS * DM);
        lo = xl + (size_t)i * (MROWS * DM);
    } else {
        int t = idx - NIN;
        if (t >= 4 * NB4) return;
        int j = t >> 18;
        r = t & (NB4 - 1);
        src = (j == 0) ? Wq : (j == 1) ? Wk : (j == 2) ? Wv : Wo;
        hi = wh + (size_t)j * (DM * DM);
        lo = wl + (size_t)j * (DM * DM);
    }
    float4 v = reinterpret_cast<const float4*>(src)[r];
    float h0 = __bfloat162float(__float2bfloat16_rn(v.x));
    float h1 = __bfloat162float(__float2bfloat16_rn(v.y));
    float h2 = __bfloat162float(__float2bfloat16_rn(v.z));
    float h3 = __bfloat162float(__float2bfloat16_rn(v.w));
    uint2 hw, lw;
    hw.x = pack_bf16x2(h0, h1);
    hw.y = pack_bf16x2(h2, h3);
    lw.x = pack_bf16x2(v.x - h0, v.y - h1);
    lw.y = pack_bf16x2(v.z - h2, v.w - h3);
    reinterpret_cast<uint2*>(hi)[r] = hw;
    reinterpret_cast<uint2*>(lo)[r] = lw;
}

// ===========================================================================
// GEMM mainloop body (shared by QKV-batched and Wo kernels).
// 3-stage cp.async ring, 96 KB smem, 2 CTAs/SM.
// ===========================================================================
#define BUF_BYTES   16384
#define STAGE_BYTES 32768
#define NSTAGE      3
#define KCHUNKS     16
#define NT          (3*KCHUNKS)
#define GEMM_SMEM   (NSTAGE*STAGE_BYTES)   // 98304

struct GemmCore {
    unsigned sbase;
    int tid, lane, warp, wm, wn, bm, bn, q, g;
    unsigned dst_off[4];
    size_t   a_off[4], b_off[4];
    int a_rowterm[2], akb;
    int b_rowterm[4], bkb;

    __device__ __forceinline__ void init(unsigned sb, int bm_, int bn_, int K) {
        sbase = sb;
        tid  = threadIdx.x;
        lane = tid & 31;
        warp = tid >> 5;
        wm = warp >> 1; wn = warp & 1;
        bm = bm_; bn = bn_;
        q = lane & 7; g = lane >> 3;
        #pragma unroll
        for (int i = 0; i < 4; i++) {
            int idx = tid + i * 256;
            int r   = idx >> 3;
            int ch  = idx & 7;
            dst_off[i] = (unsigned)(r * 128 + ((ch * 16) ^ ((r & 7) << 4)));
            a_off[i]   = (size_t)(bm + r) * K + ch * 8;
            b_off[i]   = (size_t)(bn + r) * K + ch * 8;
        }
        int row_a = (g & 1) * 8 + q;
        akb = (g >> 1) * 16;
        #pragma unroll
        for (int mt = 0; mt < 2; mt++)
            a_rowterm[mt] = (wm * 32 + mt * 16 + row_a) * 128;
        int row_b = (g >> 1) * 8 + q;
        bkb = (g & 1) * 16;
        #pragma unroll
        for (int p = 0; p < 4; p++)
            b_rowterm[p] = (wn * 64 + p * 16 + row_b) * 128;
    }

    __device__ __forceinline__ void issue(int t, int st,
        const __nv_bfloat16* Ah, const __nv_bfloat16* Al,
        const __nv_bfloat16* Bh, const __nv_bfloat16* Bl) {
        int ph = t >> 4;
        int kt = t & 15;
        const __nv_bfloat16* Ap = (ph == 2) ? Al : Ah;
        const __nv_bfloat16* Bp = (ph == 1) ? Bl : Bh;
        unsigned aS = sbase + st * STAGE_BYTES;
        unsigned bS = aS + BUF_BYTES;
        size_t kofs = (size_t)kt * 64;
        #pragma unroll
        for (int i = 0; i < 4; i++) {
            cp16(aS + dst_off[i], Ap + a_off[i] + kofs);
            cp16(bS + dst_off[i], Bp + b_off[i] + kofs);
        }
        CP_COMMIT();
    }

    __device__ __forceinline__ void mainloop(float acc[2][8][4],
        const __nv_bfloat16* Ah, const __nv_bfloat16* Al,
        const __nv_bfloat16* Bh, const __nv_bfloat16* Bl) {
        issue(0, 0, Ah, Al, Bh, Bl);
        issue(1, 1, Ah, Al, Bh, Bl);
        for (int t = 0; t < NT; t++) {
            const int st = t % NSTAGE;
            if (t < NT - 1) asm volatile("cp.async.wait_group 1;\n" ::: "memory");
            else            asm volatile("cp.async.wait_group 0;\n" ::: "memory");
            __syncthreads();
            if (t + 2 < NT) issue(t + 2, (t + 2) % NSTAGE, Ah, Al, Bh, Bl);

            unsigned aS = sbase + st * STAGE_BYTES;
            unsigned bS = aS + BUF_BYTES;
            #pragma unroll
            for (int ks = 0; ks < 4; ks++) {
                unsigned af[2][4];
                #pragma unroll
                for (int mt = 0; mt < 2; mt++)
                    LDSM4(af[mt], aS + a_rowterm[mt] + ((ks * 32 + akb) ^ (q << 4)));
                unsigned bf_[4][4];
                #pragma unroll
                for (int p = 0; p < 4; p++)
                    LDSM4(bf_[p], bS + b_rowterm[p] + ((ks * 32 + bkb) ^ (q << 4)));
                #pragma unroll
                for (int mt = 0; mt < 2; mt++)
                    #pragma unroll
                    for (int nt = 0; nt < 8; nt++) {
                        const unsigned* bp = bf_[nt >> 1];
                        if (nt & 1) mma_bf16(acc[mt][nt], af[mt], bp[2], bp[3]);
                        else        mma_bf16(acc[mt][nt], af[mt], bp[0], bp[1]);
                    }
            }
        }
    }
};

// ===========================================================================
// QKV batched GEMM: blockIdx.z in {0=Q,1=K,2=V}. Rope for z<2; head-major
// hi/lo split epilogue.
// ===========================================================================
__global__ void __launch_bounds__(256, 2) gemm_qkv(
    const __nv_bfloat16* __restrict__ xh, const __nv_bfloat16* __restrict__ xl,
    const __nv_bfloat16* __restrict__ wh, const __nv_bfloat16* __restrict__ wl,
    const float2* __restrict__ tab,
    __nv_bfloat16* __restrict__ qh, __nv_bfloat16* __restrict__ ql,
    __nv_bfloat16* __restrict__ kh, __nv_bfloat16* __restrict__ kl,
    __nv_bfloat16* __restrict__ vh, __nv_bfloat16* __restrict__ vl)
{
    extern __shared__ __align__(1024) char smem[];
    const int z = blockIdx.z;
    const size_t XN = (size_t)MROWS * DM;
    const size_t WN = (size_t)DM * DM;
    const __nv_bfloat16* Ah = xh + (size_t)z * XN;
    const __nv_bfloat16* Al = xl + (size_t)z * XN;
    const __nv_bfloat16* Bh = wh + (size_t)z * WN;
    const __nv_bfloat16* Bl = wl + (size_t)z * WN;
    __nv_bfloat16* Ch = (z == 0) ? qh : (z == 1) ? kh : vh;
    __nv_bfloat16* Cl = (z == 0) ? ql : (z == 1) ? kl : vl;

    GemmCore core;
    core.init((unsigned)__cvta_generic_to_shared(smem),
              blockIdx.y * 128, blockIdx.x * 128, DM);

    float acc[2][8][4];
    #pragma unroll
    for (int mt = 0; mt < 2; mt++)
        #pragma unroll
        for (int nt = 0; nt < 8; nt++)
            #pragma unroll
            for (int r = 0; r < 4; r++) acc[mt][nt][r] = 0.f;

    core.mainloop(acc, Ah, Al, Bh, Bl);

    const int lr = core.lane >> 2;
    const int lc = (core.lane & 3) * 2;
    const bool do_rope = (z < 2);
    #pragma unroll
    for (int mt = 0; mt < 2; mt++) {
        #pragma unroll
        for (int nt = 0; nt < 8; nt++) {
            int row = core.bm + core.wm * 32 + mt * 16 + lr;
            int col = core.bn + core.wn * 64 + nt * 8 + lc;
            float x0 = acc[mt][nt][0], y0 = acc[mt][nt][1];
            float x1 = acc[mt][nt][2], y1 = acc[mt][nt][3];
            int s0 = row & (SEQ - 1);
            int s1 = (row + 8) & (SEQ - 1);
            int bb = row >> 11;
            int hh = col >> 6;
            int dd = col & 63;
            size_t base = (size_t)(bb * NH + hh) * SEQ;
            size_t e0 = (base + s0) * HD + dd;
            size_t e1 = (base + s1) * HD + dd;
            if (do_rope) {
                float2 cs0 = tab[s0 * 32 + (dd >> 1)];
                float2 cs1 = tab[s1 * 32 + (dd >> 1)];
                float rx = x0 * cs0.x - y0 * cs0.y;
                float ry = y0 * cs0.x + x0 * cs0.y;
                x0 = rx; y0 = ry;
                rx = x1 * cs1.x - y1 * cs1.y;
                ry = y1 * cs1.x + x1 * cs1.y;
                x1 = rx; y1 = ry;
            }
            float hx0 = __bfloat162float(__float2bfloat16_rn(x0));
            float hy0 = __bfloat162float(__float2bfloat16_rn(y0));
            float hx1 = __bfloat162float(__float2bfloat16_rn(x1));
            float hy1 = __bfloat162float(__float2bfloat16_rn(y1));
            *reinterpret_cast<unsigned*>(Ch + e0) = pack_bf16x2(hx0, hy0);
            *reinterpret_cast<unsigned*>(Cl + e0) = pack_bf16x2(x0 - hx0, y0 - hy0);
            *reinterpret_cast<unsigned*>(Ch + e1) = pack_bf16x2(hx1, hy1);
            *reinterpret_cast<unsigned*>(Cl + e1) = pack_bf16x2(x1 - hx1, y1 - hy1);
        }
    }
}

// ===========================================================================
// Wo GEMM: fp32 output + bias.
// ===========================================================================
__global__ void __launch_bounds__(256, 2) gemm_out(
    const __nv_bfloat16* __restrict__ Ah, const __nv_bfloat16* __restrict__ Al,
    const __nv_bfloat16* __restrict__ Bh, const __nv_bfloat16* __restrict__ Bl,
    const float* __restrict__ bias, float* __restrict__ Cf)
{
    extern __shared__ __align__(1024) char smem[];
    GemmCore core;
    core.init((unsigned)__cvta_generic_to_shared(smem),
              blockIdx.y * 128, blockIdx.x * 128, DM);

    float acc[2][8][4];
    #pragma unroll
    for (int mt = 0; mt < 2; mt++)
        #pragma unroll
        for (int nt = 0; nt < 8; nt++)
            #pragma unroll
            for (int r = 0; r < 4; r++) acc[mt][nt][r] = 0.f;

    core.mainloop(acc, Ah, Al, Bh, Bl);

    const int lr = core.lane >> 2;
    const int lc = (core.lane & 3) * 2;
    #pragma unroll
    for (int mt = 0; mt < 2; mt++) {
        #pragma unroll
        for (int nt = 0; nt < 8; nt++) {
            int row = core.bm + core.wm * 32 + mt * 16 + lr;
            int col = core.bn + core.wn * 64 + nt * 8 + lc;
            float b0 = bias[col], b1 = bias[col + 1];
            *reinterpret_cast<float2*>(&Cf[(size_t)row * DM + col]) =
                make_float2(acc[mt][nt][0] + b0, acc[mt][nt][1] + b1);
            *reinterpret_cast<float2*>(&Cf[(size_t)(row + 8) * DM + col]) =
                make_float2(acc[mt][nt][2] + b0, acc[mt][nt][3] + b1);
        }
    }
}

// ===========================================================================
// Tensor-core causal flash attention, bf16x3, 2-stage ring, 2 CTAs/SM.
// Ring-of-2: wait -> sync -> compute -> sync -> issue(kt+2) into freed stage.
// ===========================================================================
#define AT_STAGE  33024
#define AT_SMEM   (32768 + 2*AT_STAGE)   // 98816

__global__ void __launch_bounds__(256, 2) attn_tc_kernel(
    const __nv_bfloat16* __restrict__ qh, const __nv_bfloat16* __restrict__ ql,
    const __nv_bfloat16* __restrict__ kh, const __nv_bfloat16* __restrict__ kl,
    const __nv_bfloat16* __restrict__ vh, const __nv_bfloat16* __restrict__ vl,
    const int* __restrict__ am,
    __nv_bfloat16* __restrict__ coh, __nv_bfloat16* __restrict__ col_)
{
    extern __shared__ __align__(1024) char smem[];
    const unsigned sb  = (unsigned)__cvta_generic_to_shared(smem);
    const unsigned sQh = sb, sQl = sb + 16384;

    const int tid  = threadIdx.x;
    const int lane = tid & 31;
    const int w    = tid >> 5;
    const int q    = lane & 7;
    const int g    = lane >> 3;
    const int qt   = (gridDim.x - 1) - blockIdx.x;   // heavy tiles first
    const int h = blockIdx.y, b = blockIdx.z;
    const int qb   = qt * 128;
    const size_t headbase = (size_t)(b * NH + h) * SEQ;

    #pragma unroll
    for (int i = 0; i < 4; i++) {
        int idx = tid + i * 256;
        int r = idx >> 3, ch = idx & 7;
        unsigned dst = (unsigned)(r * 128 + ((ch * 16) ^ ((r & 7) << 4)));
        size_t gidx = (headbase + qb + r) * HD + ch * 8;
        cp16(sQh + dst, qh + gidx);
        cp16(sQl + dst, ql + gidx);
    }
    CP_COMMIT();

    const int nkt = qt * 2 + 2;

    auto issue = [&](int kt, int st) {
        unsigned s0 = sb + 32768 + st * AT_STAGE;
        #pragma unroll
        for (int i = 0; i < 8; i++) {
            int idx = tid + i * 256;
            int buf = idx >> 9;
            int r   = (idx & 511) >> 3;
            int ch  = idx & 7;
            unsigned dst = s0 + buf * 8192 +
                           (unsigned)(r * 128 + ((ch * 16) ^ ((r & 7) << 4)));
            size_t gidx = (headbase + kt * 64 + r) * HD + ch * 8;
            const __nv_bfloat16* src = (buf == 0) ? kh : (buf == 1) ? kl
                                      : (buf == 2) ? vh : vl;
            cp16(dst, src + gidx);
        }
        if (tid < 16) cp16(s0 + 32768, am + b * SEQ + kt * 64 + tid * 4);
        CP_COMMIT();
    };

    issue(0, 0);
    issue(1, 1);

    float o[8][4];
    #pragma unroll
    for (int j = 0; j < 8; j++)
        #pragma unroll
        for (int r = 0; r < 4; r++) o[j][r] = 0.f;
    float m0 = -1e30f, m1 = -1e30f, l0 = 0.f, l1 = 0.f;

    unsigned qhf[4][4], qlf[4][4];

    const int row0 = qb + w * 16 + (lane >> 2);
    const int row1 = row0 + 8;
    const int c2   = 2 * (lane & 3);

    for (int kt = 0; kt < nkt; kt++) {
        const int st = kt & 1;
        if (kt + 1 < nkt) asm volatile("cp.async.wait_group 1;\n" ::: "memory");
        else              asm volatile("cp.async.wait_group 0;\n" ::: "memory");
        __syncthreads();

        if (kt == 0) {
            #pragma unroll
            for (int ks = 0; ks < 4; ks++) {
                unsigned ab = (unsigned)((w * 16 + (g & 1) * 8 + q) * 128) +
                              ((unsigned)(ks * 32 + (g >> 1) * 16) ^ (unsigned)(q << 4));
                LDSM4(qhf[ks], sQh + ab);
                LDSM4(qlf[ks], sQl + ab);
            }
        }

        unsigned sK  = sb + 32768 + st * AT_STAGE;
        unsigned sKl = sK + 8192;
        unsigned sVh = sK + 16384;
        unsigned sVl = sK + 24576;
        const int2* mp = reinterpret_cast<const int2*>(smem + 32768 + st * AT_STAGE + 32768);

        float sc_[8][4];
        #pragma unroll
        for (int j = 0; j < 8; j++)
            #pragma unroll
            for (int r = 0; r < 4; r++) sc_[j][r] = 0.f;

        #pragma unroll
        for (int ks = 0; ks < 4; ks++) {
            unsigned kb = ((unsigned)(ks * 32 + (g & 1) * 16)) ^ (unsigned)(q << 4);
            #pragma unroll
            for (int p = 0; p < 4; p++) {
                unsigned rowoff = (unsigned)((p * 16 + (g >> 1) * 8 + q) * 128);
                unsigned kf[4], kf2[4];
                LDSM4(kf,  sK  + rowoff + kb);
                LDSM4(kf2, sKl + rowoff + kb);
                mma_bf16(sc_[2*p],   qhf[ks], kf[0],  kf[1]);
                mma_bf16(sc_[2*p+1], qhf[ks], kf[2],  kf[3]);
                mma_bf16(sc_[2*p],   qlf[ks], kf[0],  kf[1]);
                mma_bf16(sc_[2*p+1], qlf[ks], kf[2],  kf[3]);
                mma_bf16(sc_[2*p],   qhf[ks], kf2[0], kf2[1]);
                mma_bf16(sc_[2*p+1], qhf[ks], kf2[2], kf2[3]);
            }
        }

        #pragma unroll
        for (int j = 0; j < 8; j++) {
            int c0 = kt * 64 + 8 * j + c2;
            int2 mk = mp[4 * j + (lane & 3)];
            sc_[j][0] = (c0     <= row0 && mk.x) ? sc_[j][0] * 0.125f : -1e30f;
            sc_[j][1] = (c0 + 1 <= row0 && mk.y) ? sc_[j][1] * 0.125f : -1e30f;
            sc_[j][2] = (c0     <= row1 && mk.x) ? sc_[j][2] * 0.125f : -1e30f;
            sc_[j][3] = (c0 + 1 <= row1 && mk.y) ? sc_[j][3] * 0.125f : -1e30f;
        }

        float mx0 = -1e30f, mx1 = -1e30f;
        #pragma unroll
        for (int j = 0; j < 8; j++) {
            mx0 = fmaxf(mx0, fmaxf(sc_[j][0], sc_[j][1]));
            mx1 = fmaxf(mx1, fmaxf(sc_[j][2], sc_[j][3]));
        }
        mx0 = fmaxf(mx0, __shfl_xor_sync(0xffffffffu, mx0, 1));
        mx0 = fmaxf(mx0, __shfl_xor_sync(0xffffffffu, mx0, 2));
        mx1 = fmaxf(mx1, __shfl_xor_sync(0xffffffffu, mx1, 1));
        mx1 = fmaxf(mx1, __shfl_xor_sync(0xffffffffu, mx1, 2));
        float mn0 = fmaxf(m0, mx0), mn1 = fmaxf(m1, mx1);
        float a0 = __expf(m0 - mn0), a1 = __expf(m1 - mn1);
        m0 = mn0; m1 = mn1;
        float s0s = 0.f, s1s = 0.f;
        #pragma unroll
        for (int j = 0; j < 8; j++) {
            sc_[j][0] = __expf(sc_[j][0] - mn0);
            sc_[j][1] = __expf(sc_[j][1] - mn0);
            sc_[j][2] = __expf(sc_[j][2] - mn1);
            sc_[j][3] = __expf(sc_[j][3] - mn1);
            s0s += sc_[j][0] + sc_[j][1];
            s1s += sc_[j][2] + sc_[j][3];
        }
        s0s += __shfl_xor_sync(0xffffffffu, s0s, 1);
        s0s += __shfl_xor_sync(0xffffffffu, s0s, 2);
        s1s += __shfl_xor_sync(0xffffffffu, s1s, 1);
        s1s += __shfl_xor_sync(0xffffffffu, s1s, 2);
        l0 = l0 * a0 + s0s;
        l1 = l1 * a1 + s1s;
        #pragma unroll
        for (int j = 0; j < 8; j++) {
            o[j][0] *= a0; o[j][1] *= a0;
            o[j][2] *= a1; o[j][3] *= a1;
        }

        unsigned pkh[4][4], pkl[4][4];
        #pragma unroll
        for (int ks = 0; ks < 4; ks++) {
            float a0h0 = __bfloat162float(__float2bfloat16_rn(sc_[2*ks][0]));
            float a0h1 = __bfloat162float(__float2bfloat16_rn(sc_[2*ks][1]));
            float a1h0 = __bfloat162float(__float2bfloat16_rn(sc_[2*ks][2]));
            float a1h1 = __bfloat162float(__float2bfloat16_rn(sc_[2*ks][3]));
            float b0h0 = __bfloat162float(__float2bfloat16_rn(sc_[2*ks+1][0]));
            float b0h1 = __bfloat162float(__float2bfloat16_rn(sc_[2*ks+1][1]));
            float b1h0 = __bfloat162float(__float2bfloat16_rn(sc_[2*ks+1][2]));
            float b1h1 = __bfloat162float(__float2bfloat16_rn(sc_[2*ks+1][3]));
            pkh[ks][0] = pack_bf16x2(a0h0, a0h1);
            pkh[ks][1] = pack_bf16x2(a1h0, a1h1);
            pkh[ks][2] = pack_bf16x2(b0h0, b0h1);
            pkh[ks][3] = pack_bf16x2(b1h0, b1h1);
            pkl[ks][0] = pack_bf16x2(sc_[2*ks][0] - a0h0,   sc_[2*ks][1] - a0h1);
            pkl[ks][1] = pack_bf16x2(sc_[2*ks][2] - a1h0,   sc_[2*ks][3] - a1h1);
            pkl[ks][2] = pack_bf16x2(sc_[2*ks+1][0] - b0h0, sc_[2*ks+1][1] - b0h1);
            pkl[ks][3] = pack_bf16x2(sc_[2*ks+1][2] - b1h0, sc_[2*ks+1][3] - b1h1);
        }

        #pragma unroll
        for (int ks = 0; ks < 4; ks++) {
            int sl = ks * 16 + (lane & 15);
            unsigned vrowh = sVh + (unsigned)(sl * 128);
            unsigned vrowl = sVl + (unsigned)(sl * 128);
            unsigned swz   = (unsigned)((sl & 7) << 4);
            #pragma unroll
            for (int j = 0; j < 4; j++) {
                unsigned coff = ((unsigned)((2*j + (lane >> 4)) * 16)) ^ swz;
                unsigned vfh[4], vfl[4];
                LDSM4T(vfh, vrowh + coff);
                LDSM4T(vfl, vrowl + coff);
                mma_bf16(o[2*j],   pkh[ks], vfh[0], vfh[1]);
                mma_bf16(o[2*j+1], pkh[ks], vfh[2], vfh[3]);
                mma_bf16(o[2*j],   pkl[ks], vfh[0], vfh[1]);
                mma_bf16(o[2*j+1], pkl[ks], vfh[2], vfh[3]);
                mma_bf16(o[2*j],   pkh[ks], vfl[0], vfl[1]);
                mma_bf16(o[2*j+1], pkh[ks], vfl[2], vfl[3]);
            }
        }

        // Stage kt fully consumed; refill it for kt+2.
        __syncthreads();
        if (kt + 2 < nkt) issue(kt + 2, st);
    }

    // ---- normalize + hi/lo split + store (row-major for Wo GEMM) ----
    float i0 = (l0 > 0.f) ? 1.f / l0 : 0.f;
    float i1 = (l1 > 0.f) ? 1.f / l1 : 0.f;
    size_t gr0 = (size_t)(b * SEQ + row0) * DM + h * HD;
    size_t gr1 = (size_t)(b * SEQ + row1) * DM + h * HD;
    #pragma unroll
    for (int j = 0; j < 8; j++) {
        int d = 8 * j + c2;
        float x0 = o[j][0] * i0, y0 = o[j][1] * i0;
        float x1 = o[j][2] * i1, y1 = o[j][3] * i1;
        float hx0 = __bfloat162float(__float2bfloat16_rn(x0));
        float hy0 = __bfloat162float(__float2bfloat16_rn(y0));
        float hx1 = __bfloat162float(__float2bfloat16_rn(x1));
        float hy1 = __bfloat162float(__float2bfloat16_rn(y1));
        *reinterpret_cast<unsigned*>(coh  + gr0 + d) = pack_bf16x2(hx0, hy0);
        *reinterpret_cast<unsigned*>(col_ + gr0 + d) = pack_bf16x2(x0 - hx0, y0 - hy0);
        *reinterpret_cast<unsigned*>(coh  + gr1 + d) = pack_bf16x2(hx1, hy1);
        *reinterpret_cast<unsigned*>(col_ + gr1 + d) = pack_bf16x2(x1 - hx1, y1 - hy1);
    }
}

// ---------------------------------------------------------------------------
extern "C" void kernel_launch(void* const* d_in, const int* in_sizes, int n_in,
                              void* d_out, int out_size)
{
    const float* Q  = (const float*)d_in[0];
    const float* K  = (const float*)d_in[1];
    const float* V  = (const float*)d_in[2];
    const int*   am = (const int*)  d_in[3];
    const float* Wq = (const float*)d_in[4];
    const float* Wk = (const float*)d_in[5];
    const float* Wv = (const float*)d_in[6];
    const float* Wo = (const float*)d_in[7];
    const float* bo = (const float*)d_in[8];
    float* out = (float*)d_out;

    __nv_bfloat16 *xh, *xl, *wh, *wl, *ah, *al, *qqh, *qql, *kkh, *kkl, *vvh, *vvl;
    float2* tab;
    cudaGetSymbolAddress((void**)&xh,  g_xh);
    cudaGetSymbolAddress((void**)&xl,  g_xl);
    cudaGetSymbolAddress((void**)&wh,  g_wh);
    cudaGetSymbolAddress((void**)&wl,  g_wl);
    cudaGetSymbolAddress((void**)&ah,  g_ah);
    cudaGetSymbolAddress((void**)&al,  g_al);
    cudaGetSymbolAddress((void**)&qqh, g_qh);
    cudaGetSymbolAddress((void**)&qql, g_ql);
    cudaGetSymbolAddress((void**)&kkh, g_kh);
    cudaGetSymbolAddress((void**)&kkl, g_kl);
    cudaGetSymbolAddress((void**)&vvh, g_vh);
    cudaGetSymbolAddress((void**)&vvl, g_vl);
    cudaGetSymbolAddress((void**)&tab, g_tab);

    const int n_split = 3 * NA4 + 4 * NB4;
    const size_t WN = (size_t)DM * DM;

    cudaFuncSetAttribute(gemm_qkv,
                         cudaFuncAttributeMaxDynamicSharedMemorySize, GEMM_SMEM);
    cudaFuncSetAttribute(gemm_out,
                         cudaFuncAttributeMaxDynamicSharedMemorySize, GEMM_SMEM);
    cudaFuncSetAttribute(attn_tc_kernel,
                         cudaFuncAttributeMaxDynamicSharedMemorySize, AT_SMEM);

    rope_tab_kernel<<<(SEQ * 32 + 255) / 256, 256>>>(tab);
    split_all_kernel<<<(n_split + 255) / 256, 256>>>(
        Q, K, V, Wq, Wk, Wv, Wo, xh, xl, wh, wl);

    // Batched Q/K/V projections (z selects matrix; rope for z<2)
    gemm_qkv<<<dim3(DM / 128, MROWS / 128, 3), 256, GEMM_SMEM>>>(
        xh, xl, wh, wl, tab, qqh, qql, kkh, kkl, vvh, vvl);

    // Tensor-core flash attention -> ctx split
    attn_tc_kernel<<<dim3(SEQ / 128, NH, BATCH), 256, AT_SMEM>>>(
        qqh, qql, kkh, kkl, vvh, vvl, am, ah, al);

    // Output projection
    gemm_out<<<dim3(DM / 128, MROWS / 128), 256, GEMM_SMEM>>>(
        ah, al, wh + 3*WN, wl + 3*WN, bo, out);
}

// round 17
// speedup vs baseline: 3.5002x; 1.0152x over previous
#include <cuda_runtime.h>
#include <cuda_bf16.h>
#include <math.h>
#include <stdint.h>

#define DM   1024
#define NH   16
#define HD   64
#define SEQ  2048
#define BATCH 2
#define MROWS (BATCH*SEQ)   // 4096
#define NA4  (MROWS*DM/4)   // 2^20
#define NB4  (DM*DM/4)      // 2^18

// Scratch (static device arrays — no allocation allowed)
__device__ __nv_bfloat16 g_xh[3][MROWS*DM];  // Q,K,V input splits (hi)
__device__ __nv_bfloat16 g_xl[3][MROWS*DM];  // (lo)
__device__ __nv_bfloat16 g_wh[4][DM*DM];     // Wq,Wk,Wv,Wo splits (hi)
__device__ __nv_bfloat16 g_wl[4][DM*DM];     // (lo)
__device__ __nv_bfloat16 g_ah[MROWS*DM];     // ctx split (attention output)
__device__ __nv_bfloat16 g_al[MROWS*DM];
__device__ __nv_bfloat16 g_qh[MROWS*DM];     // head-major, rope applied
__device__ __nv_bfloat16 g_ql[MROWS*DM];
__device__ __nv_bfloat16 g_kh[MROWS*DM];
__device__ __nv_bfloat16 g_kl[MROWS*DM];
__device__ __nv_bfloat16 g_vh[MROWS*DM];
__device__ __nv_bfloat16 g_vl[MROWS*DM];
__device__ float2 g_tab[SEQ*32];             // (cos, sin) per (s, pair)

// ===========================================================================
// Common PTX helpers
// ===========================================================================
__device__ __forceinline__ void mma_bf16(float c[4], const unsigned a[4], unsigned b0, unsigned b1)
{
    asm volatile(
        "mma.sync.aligned.m16n8k16.row.col.f32.bf16.bf16.f32 "
        "{%0,%1,%2,%3}, {%4,%5,%6,%7}, {%8,%9}, {%0,%1,%2,%3};\n"
        : "+f"(c[0]), "+f"(c[1]), "+f"(c[2]), "+f"(c[3])
        : "r"(a[0]), "r"(a[1]), "r"(a[2]), "r"(a[3]), "r"(b0), "r"(b1));
}
__device__ __forceinline__ void cp16(unsigned saddr, const void* gptr)
{
    asm volatile("cp.async.cg.shared.global [%0], [%1], 16;\n" :: "r"(saddr), "l"(gptr));
}
#define CP_COMMIT() asm volatile("cp.async.commit_group;\n" ::: "memory")
#define LDSM4(r, addr) \
    asm volatile("ldmatrix.sync.aligned.m8n8.x4.shared.b16 {%0,%1,%2,%3}, [%4];" \
        : "=r"((r)[0]), "=r"((r)[1]), "=r"((r)[2]), "=r"((r)[3]) : "r"(addr))
#define LDSM4T(r, addr) \
    asm volatile("ldmatrix.sync.aligned.m8n8.x4.trans.shared.b16 {%0,%1,%2,%3}, [%4];" \
        : "=r"((r)[0]), "=r"((r)[1]), "=r"((r)[2]), "=r"((r)[3]) : "r"(addr))

__device__ __forceinline__ unsigned pack_bf16x2(float lo, float hi)
{
    __nv_bfloat162 p = __float22bfloat162_rn(make_float2(lo, hi));
    return *reinterpret_cast<unsigned*>(&p);
}

// ===========================================================================
// RoPE cos/sin table
// ===========================================================================
__global__ void rope_tab_kernel(float2* __restrict__ tab)
{
    int idx = blockIdx.x * blockDim.x + threadIdx.x;
    if (idx >= SEQ * 32) return;
    int s = idx >> 5, i = idx & 31;
    float theta = powf(10000.0f, -(float)(2 * i) * (1.0f / 64.0f));
    float sn, cs;
    sincosf((float)s * theta, &sn, &cs);
    tab[idx] = make_float2(cs, sn);
}

// ===========================================================================
// Fused split of ALL inputs+weights
// ===========================================================================
__global__ void split_all_kernel(
    const float* __restrict__ Q, const float* __restrict__ K, const float* __restrict__ V,
    const float* __restrict__ Wq, const float* __restrict__ Wk,
    const float* __restrict__ Wv, const float* __restrict__ Wo,
    __nv_bfloat16* __restrict__ xh, __nv_bfloat16* __restrict__ xl,
    __nv_bfloat16* __restrict__ wh, __nv_bfloat16* __restrict__ wl)
{
    int idx = blockIdx.x * blockDim.x + threadIdx.x;
    const int NIN = 3 * NA4;
    const float* src;
    __nv_bfloat16 *hi, *lo;
    int r;
    if (idx < NIN) {
        int i = idx >> 20;
        r = idx & (NA4 - 1);
        src = (i == 0) ? Q : (i == 1) ? K : V;
        hi = xh + (size_t)i * (MROWS * DM);
        lo = xl + (size_t)i * (MROWS * DM);
    } else {
        int t = idx - NIN;
        if (t >= 4 * NB4) return;
        int j = t >> 18;
        r = t & (NB4 - 1);
        src = (j == 0) ? Wq : (j == 1) ? Wk : (j == 2) ? Wv : Wo;
        hi = wh + (size_t)j * (DM * DM);
        lo = wl + (size_t)j * (DM * DM);
    }
    float4 v = reinterpret_cast<const float4*>(src)[r];
    float h0 = __bfloat162float(__float2bfloat16_rn(v.x));
    float h1 = __bfloat162float(__float2bfloat16_rn(v.y));
    float h2 = __bfloat162float(__float2bfloat16_rn(v.z));
    float h3 = __bfloat162float(__float2bfloat16_rn(v.w));
    uint2 hw, lw;
    hw.x = pack_bf16x2(h0, h1);
    hw.y = pack_bf16x2(h2, h3);
    lw.x = pack_bf16x2(v.x - h0, v.y - h1);
    lw.y = pack_bf16x2(v.z - h2, v.w - h3);
    reinterpret_cast<uint2*>(hi)[r] = hw;
    reinterpret_cast<uint2*>(lo)[r] = lw;
}

// ===========================================================================
// GEMM mainloop body (shared by QKV-batched and Wo kernels).
// 3-stage cp.async ring, 96 KB smem, 2 CTAs/SM.
// ===========================================================================
#define BUF_BYTES   16384
#define STAGE_BYTES 32768
#define NSTAGE      3
#define KCHUNKS     16
#define NT          (3*KCHUNKS)
#define GEMM_SMEM   (NSTAGE*STAGE_BYTES)   // 98304

struct GemmCore {
    unsigned sbase;
    int tid, lane, warp, wm, wn, bm, bn, q, g;
    unsigned dst_off[4];
    size_t   a_off[4], b_off[4];
    int a_rowterm[2], akb;
    int b_rowterm[4], bkb;

    __device__ __forceinline__ void init(unsigned sb, int bm_, int bn_, int K) {
        sbase = sb;
        tid  = threadIdx.x;
        lane = tid & 31;
        warp = tid >> 5;
        wm = warp >> 1; wn = warp & 1;
        bm = bm_; bn = bn_;
        q = lane & 7; g = lane >> 3;
        #pragma unroll
        for (int i = 0; i < 4; i++) {
            int idx = tid + i * 256;
            int r   = idx >> 3;
            int ch  = idx & 7;
            dst_off[i] = (unsigned)(r * 128 + ((ch * 16) ^ ((r & 7) << 4)));
            a_off[i]   = (size_t)(bm + r) * K + ch * 8;
            b_off[i]   = (size_t)(bn + r) * K + ch * 8;
        }
        int row_a = (g & 1) * 8 + q;
        akb = (g >> 1) * 16;
        #pragma unroll
        for (int mt = 0; mt < 2; mt++)
            a_rowterm[mt] = (wm * 32 + mt * 16 + row_a) * 128;
        int row_b = (g >> 1) * 8 + q;
        bkb = (g & 1) * 16;
        #pragma unroll
        for (int p = 0; p < 4; p++)
            b_rowterm[p] = (wn * 64 + p * 16 + row_b) * 128;
    }

    __device__ __forceinline__ void issue(int t, int st,
        const __nv_bfloat16* Ah, const __nv_bfloat16* Al,
        const __nv_bfloat16* Bh, const __nv_bfloat16* Bl) {
        int ph = t >> 4;
        int kt = t & 15;
        const __nv_bfloat16* Ap = (ph == 2) ? Al : Ah;
        const __nv_bfloat16* Bp = (ph == 1) ? Bl : Bh;
        unsigned aS = sbase + st * STAGE_BYTES;
        unsigned bS = aS + BUF_BYTES;
        size_t kofs = (size_t)kt * 64;
        #pragma unroll
        for (int i = 0; i < 4; i++) {
            cp16(aS + dst_off[i], Ap + a_off[i] + kofs);
            cp16(bS + dst_off[i], Bp + b_off[i] + kofs);
        }
        CP_COMMIT();
    }

    __device__ __forceinline__ void mainloop(float acc[2][8][4],
        const __nv_bfloat16* Ah, const __nv_bfloat16* Al,
        const __nv_bfloat16* Bh, const __nv_bfloat16* Bl) {
        issue(0, 0, Ah, Al, Bh, Bl);
        issue(1, 1, Ah, Al, Bh, Bl);
        for (int t = 0; t < NT; t++) {
            const int st = t % NSTAGE;
            if (t < NT - 1) asm volatile("cp.async.wait_group 1;\n" ::: "memory");
            else            asm volatile("cp.async.wait_group 0;\n" ::: "memory");
            __syncthreads();
            if (t + 2 < NT) issue(t + 2, (t + 2) % NSTAGE, Ah, Al, Bh, Bl);

            unsigned aS = sbase + st * STAGE_BYTES;
            unsigned bS = aS + BUF_BYTES;
            #pragma unroll
            for (int ks = 0; ks < 4; ks++) {
                unsigned af[2][4];
                #pragma unroll
                for (int mt = 0; mt < 2; mt++)
                    LDSM4(af[mt], aS + a_rowterm[mt] + ((ks * 32 + akb) ^ (q << 4)));
                unsigned bf_[4][4];
                #pragma unroll
                for (int p = 0; p < 4; p++)
                    LDSM4(bf_[p], bS + b_rowterm[p] + ((ks * 32 + bkb) ^ (q << 4)));
                #pragma unroll
                for (int mt = 0; mt < 2; mt++)
                    #pragma unroll
                    for (int nt = 0; nt < 8; nt++) {
                        const unsigned* bp = bf_[nt >> 1];
                        if (nt & 1) mma_bf16(acc[mt][nt], af[mt], bp[2], bp[3]);
                        else        mma_bf16(acc[mt][nt], af[mt], bp[0], bp[1]);
                    }
            }
        }
    }
};

// ===========================================================================
// QKV batched GEMM: blockIdx.z in {0=Q,1=K,2=V}. Rope for z<2; head-major
// hi/lo split epilogue.
// ===========================================================================
__global__ void __launch_bounds__(256, 2) gemm_qkv(
    const __nv_bfloat16* __restrict__ xh, const __nv_bfloat16* __restrict__ xl,
    const __nv_bfloat16* __restrict__ wh, const __nv_bfloat16* __restrict__ wl,
    const float2* __restrict__ tab,
    __nv_bfloat16* __restrict__ qh, __nv_bfloat16* __restrict__ ql,
    __nv_bfloat16* __restrict__ kh, __nv_bfloat16* __restrict__ kl,
    __nv_bfloat16* __restrict__ vh, __nv_bfloat16* __restrict__ vl)
{
    extern __shared__ __align__(1024) char smem[];
    const int z = blockIdx.z;
    const size_t XN = (size_t)MROWS * DM;
    const size_t WN = (size_t)DM * DM;
    const __nv_bfloat16* Ah = xh + (size_t)z * XN;
    const __nv_bfloat16* Al = xl + (size_t)z * XN;
    const __nv_bfloat16* Bh = wh + (size_t)z * WN;
    const __nv_bfloat16* Bl = wl + (size_t)z * WN;
    __nv_bfloat16* Ch = (z == 0) ? qh : (z == 1) ? kh : vh;
    __nv_bfloat16* Cl = (z == 0) ? ql : (z == 1) ? kl : vl;

    GemmCore core;
    core.init((unsigned)__cvta_generic_to_shared(smem),
              blockIdx.y * 128, blockIdx.x * 128, DM);

    float acc[2][8][4];
    #pragma unroll
    for (int mt = 0; mt < 2; mt++)
        #pragma unroll
        for (int nt = 0; nt < 8; nt++)
            #pragma unroll
            for (int r = 0; r < 4; r++) acc[mt][nt][r] = 0.f;

    core.mainloop(acc, Ah, Al, Bh, Bl);

    const int lr = core.lane >> 2;
    const int lc = (core.lane & 3) * 2;
    const bool do_rope = (z < 2);
    #pragma unroll
    for (int mt = 0; mt < 2; mt++) {
        #pragma unroll
        for (int nt = 0; nt < 8; nt++) {
            int row = core.bm + core.wm * 32 + mt * 16 + lr;
            int col = core.bn + core.wn * 64 + nt * 8 + lc;
            float x0 = acc[mt][nt][0], y0 = acc[mt][nt][1];
            float x1 = acc[mt][nt][2], y1 = acc[mt][nt][3];
            int s0 = row & (SEQ - 1);
            int s1 = (row + 8) & (SEQ - 1);
            int bb = row >> 11;
            int hh = col >> 6;
            int dd = col & 63;
            size_t base = (size_t)(bb * NH + hh) * SEQ;
            size_t e0 = (base + s0) * HD + dd;
            size_t e1 = (base + s1) * HD + dd;
            if (do_rope) {
                float2 cs0 = tab[s0 * 32 + (dd >> 1)];
                float2 cs1 = tab[s1 * 32 + (dd >> 1)];
                float rx = x0 * cs0.x - y0 * cs0.y;
                float ry = y0 * cs0.x + x0 * cs0.y;
                x0 = rx; y0 = ry;
                rx = x1 * cs1.x - y1 * cs1.y;
                ry = y1 * cs1.x + x1 * cs1.y;
                x1 = rx; y1 = ry;
            }
            float hx0 = __bfloat162float(__float2bfloat16_rn(x0));
            float hy0 = __bfloat162float(__float2bfloat16_rn(y0));
            float hx1 = __bfloat162float(__float2bfloat16_rn(x1));
            float hy1 = __bfloat162float(__float2bfloat16_rn(y1));
            *reinterpret_cast<unsigned*>(Ch + e0) = pack_bf16x2(hx0, hy0);
            *reinterpret_cast<unsigned*>(Cl + e0) = pack_bf16x2(x0 - hx0, y0 - hy0);
            *reinterpret_cast<unsigned*>(Ch + e1) = pack_bf16x2(hx1, hy1);
            *reinterpret_cast<unsigned*>(Cl + e1) = pack_bf16x2(x1 - hx1, y1 - hy1);
        }
    }
}

// ===========================================================================
// Wo GEMM: fp32 output + bias.
// ===========================================================================
__global__ void __launch_bounds__(256, 2) gemm_out(
    const __nv_bfloat16* __restrict__ Ah, const __nv_bfloat16* __restrict__ Al,
    const __nv_bfloat16* __restrict__ Bh, const __nv_bfloat16* __restrict__ Bl,
    const float* __restrict__ bias, float* __restrict__ Cf)
{
    extern __shared__ __align__(1024) char smem[];
    GemmCore core;
    core.init((unsigned)__cvta_generic_to_shared(smem),
              blockIdx.y * 128, blockIdx.x * 128, DM);

    float acc[2][8][4];
    #pragma unroll
    for (int mt = 0; mt < 2; mt++)
        #pragma unroll
        for (int nt = 0; nt < 8; nt++)
            #pragma unroll
            for (int r = 0; r < 4; r++) acc[mt][nt][r] = 0.f;

    core.mainloop(acc, Ah, Al, Bh, Bl);

    const int lr = core.lane >> 2;
    const int lc = (core.lane & 3) * 2;
    #pragma unroll
    for (int mt = 0; mt < 2; mt++) {
        #pragma unroll
        for (int nt = 0; nt < 8; nt++) {
            int row = core.bm + core.wm * 32 + mt * 16 + lr;
            int col = core.bn + core.wn * 64 + nt * 8 + lc;
            float b0 = bias[col], b1 = bias[col + 1];
            *reinterpret_cast<float2*>(&Cf[(size_t)row * DM + col]) =
                make_float2(acc[mt][nt][0] + b0, acc[mt][nt][1] + b1);
            *reinterpret_cast<float2*>(&Cf[(size_t)(row + 8) * DM + col]) =
                make_float2(acc[mt][nt][2] + b0, acc[mt][nt][3] + b1);
        }
    }
}

// ===========================================================================
// Tensor-core causal flash attention, bf16x3, 3-stage ring, 1 CTA/SM,
// software-pipelined: S(kt+1) is computed between softmax/pack(kt) and PV(kt)
// so softmax never waits on freshly-issued MMA chains.
// ===========================================================================
#define AT_STAGE  33024
#define AT_SMEM   (32768 + 3*AT_STAGE)   // 131840

__global__ void __launch_bounds__(256) attn_tc_kernel(
    const __nv_bfloat16* __restrict__ qh, const __nv_bfloat16* __restrict__ ql,
    const __nv_bfloat16* __restrict__ kh, const __nv_bfloat16* __restrict__ kl,
    const __nv_bfloat16* __restrict__ vh, const __nv_bfloat16* __restrict__ vl,
    const int* __restrict__ am,
    __nv_bfloat16* __restrict__ coh, __nv_bfloat16* __restrict__ col_)
{
    extern __shared__ __align__(1024) char smem[];
    const unsigned sb  = (unsigned)__cvta_generic_to_shared(smem);
    const unsigned sQh = sb, sQl = sb + 16384;

    const int tid  = threadIdx.x;
    const int lane = tid & 31;
    const int w    = tid >> 5;
    const int q    = lane & 7;
    const int g    = lane >> 3;
    const int qt   = (gridDim.x - 1) - blockIdx.x;   // heavy tiles first
    const int h = blockIdx.y, b = blockIdx.z;
    const int qb   = qt * 128;
    const size_t headbase = (size_t)(b * NH + h) * SEQ;

    // Q tile load (group 0)
    #pragma unroll
    for (int i = 0; i < 4; i++) {
        int idx = tid + i * 256;
        int r = idx >> 3, ch = idx & 7;
        unsigned dst = (unsigned)(r * 128 + ((ch * 16) ^ ((r & 7) << 4)));
        size_t gidx = (headbase + qb + r) * HD + ch * 8;
        cp16(sQh + dst, qh + gidx);
        cp16(sQl + dst, ql + gidx);
    }
    CP_COMMIT();

    const int nkt = qt * 2 + 2;

    auto issue = [&](int kt, int st) {
        unsigned s0 = sb + 32768 + st * AT_STAGE;
        #pragma unroll
        for (int i = 0; i < 8; i++) {
            int idx = tid + i * 256;
            int buf = idx >> 9;
            int r   = (idx & 511) >> 3;
            int ch  = idx & 7;
            unsigned dst = s0 + buf * 8192 +
                           (unsigned)(r * 128 + ((ch * 16) ^ ((r & 7) << 4)));
            size_t gidx = (headbase + kt * 64 + r) * HD + ch * 8;
            const __nv_bfloat16* src = (buf == 0) ? kh : (buf == 1) ? kl
                                      : (buf == 2) ? vh : vl;
            cp16(dst, src + gidx);
        }
        if (tid < 16) cp16(s0 + 32768, am + b * SEQ + kt * 64 + tid * 4);
        CP_COMMIT();
    };

    issue(0, 0);
    issue(1, 1);
    if (2 < nkt) issue(2, 2); else CP_COMMIT();

    float o[8][4];
    #pragma unroll
    for (int j = 0; j < 8; j++)
        #pragma unroll
        for (int r = 0; r < 4; r++) o[j][r] = 0.f;
    float m0 = -1e30f, m1 = -1e30f, l0 = 0.f, l1 = 0.f;

    unsigned qhf[4][4], qlf[4][4];
    float sc_[8][4];

    const int row0 = qb + w * 16 + (lane >> 2);
    const int row1 = row0 + 8;
    const int c2   = 2 * (lane & 3);

    // S = QK^T for tile kt2 into sc_ (stage kt2%3 must be valid & visible)
    auto computeS = [&](int kt2) {
        unsigned sK  = sb + 32768 + (kt2 % 3) * AT_STAGE;
        unsigned sKl = sK + 8192;
        #pragma unroll
        for (int j = 0; j < 8; j++)
            #pragma unroll
            for (int r = 0; r < 4; r++) sc_[j][r] = 0.f;
        #pragma unroll
        for (int ks = 0; ks < 4; ks++) {
            unsigned kb = ((unsigned)(ks * 32 + (g & 1) * 16)) ^ (unsigned)(q << 4);
            #pragma unroll
            for (int p = 0; p < 4; p++) {
                unsigned rowoff = (unsigned)((p * 16 + (g >> 1) * 8 + q) * 128);
                unsigned kf[4], kf2[4];
                LDSM4(kf,  sK  + rowoff + kb);
                LDSM4(kf2, sKl + rowoff + kb);
                mma_bf16(sc_[2*p],   qhf[ks], kf[0],  kf[1]);
                mma_bf16(sc_[2*p+1], qhf[ks], kf[2],  kf[3]);
                mma_bf16(sc_[2*p],   qlf[ks], kf[0],  kf[1]);
                mma_bf16(sc_[2*p+1], qlf[ks], kf[2],  kf[3]);
                mma_bf16(sc_[2*p],   qhf[ks], kf2[0], kf2[1]);
                mma_bf16(sc_[2*p+1], qhf[ks], kf2[2], kf2[3]);
            }
        }
    };

    // Prologue: Q + tile0 ready (groups: {Q, t0, t1, t2}; wait_group 2 -> Q,t0 done)
    asm volatile("cp.async.wait_group 2;\n" ::: "memory");
    __syncthreads();
    #pragma unroll
    for (int ks = 0; ks < 4; ks++) {
        unsigned ab = (unsigned)((w * 16 + (g & 1) * 8 + q) * 128) +
                      ((unsigned)(ks * 32 + (g >> 1) * 16) ^ (unsigned)(q << 4));
        LDSM4(qhf[ks], sQh + ab);
        LDSM4(qlf[ks], sQl + ab);
    }
    computeS(0);

    for (int kt = 0; kt < nkt; kt++) {
        const int st = kt % 3;
        unsigned sV0 = sb + 32768 + st * AT_STAGE;
        unsigned sVh = sV0 + 16384;
        unsigned sVl = sV0 + 24576;
        const int2* mp = reinterpret_cast<const int2*>(smem + 32768 + st * AT_STAGE + 32768);

        // ---- scale + causal + padding mask (tile kt, in sc_) ----
        #pragma unroll
        for (int j = 0; j < 8; j++) {
            int c0 = kt * 64 + 8 * j + c2;
            int2 mk = mp[4 * j + (lane & 3)];
            sc_[j][0] = (c0     <= row0 && mk.x) ? sc_[j][0] * 0.125f : -1e30f;
            sc_[j][1] = (c0 + 1 <= row0 && mk.y) ? sc_[j][1] * 0.125f : -1e30f;
            sc_[j][2] = (c0     <= row1 && mk.x) ? sc_[j][2] * 0.125f : -1e30f;
            sc_[j][3] = (c0 + 1 <= row1 && mk.y) ? sc_[j][3] * 0.125f : -1e30f;
        }

        // ---- online softmax ----
        float mx0 = -1e30f, mx1 = -1e30f;
        #pragma unroll
        for (int j = 0; j < 8; j++) {
            mx0 = fmaxf(mx0, fmaxf(sc_[j][0], sc_[j][1]));
            mx1 = fmaxf(mx1, fmaxf(sc_[j][2], sc_[j][3]));
        }
        mx0 = fmaxf(mx0, __shfl_xor_sync(0xffffffffu, mx0, 1));
        mx0 = fmaxf(mx0, __shfl_xor_sync(0xffffffffu, mx0, 2));
        mx1 = fmaxf(mx1, __shfl_xor_sync(0xffffffffu, mx1, 1));
        mx1 = fmaxf(mx1, __shfl_xor_sync(0xffffffffu, mx1, 2));
        float mn0 = fmaxf(m0, mx0), mn1 = fmaxf(m1, mx1);
        float a0 = __expf(m0 - mn0), a1 = __expf(m1 - mn1);
        m0 = mn0; m1 = mn1;
        float s0s = 0.f, s1s = 0.f;
        #pragma unroll
        for (int j = 0; j < 8; j++) {
            sc_[j][0] = __expf(sc_[j][0] - mn0);
            sc_[j][1] = __expf(sc_[j][1] - mn0);
            sc_[j][2] = __expf(sc_[j][2] - mn1);
            sc_[j][3] = __expf(sc_[j][3] - mn1);
            s0s += sc_[j][0] + sc_[j][1];
            s1s += sc_[j][2] + sc_[j][3];
        }
        s0s += __shfl_xor_sync(0xffffffffu, s0s, 1);
        s0s += __shfl_xor_sync(0xffffffffu, s0s, 2);
        s1s += __shfl_xor_sync(0xffffffffu, s1s, 1);
        s1s += __shfl_xor_sync(0xffffffffu, s1s, 2);
        l0 = l0 * a0 + s0s;
        l1 = l1 * a1 + s1s;
        #pragma unroll
        for (int j = 0; j < 8; j++) {
            o[j][0] *= a0; o[j][1] *= a0;
            o[j][2] *= a1; o[j][3] *= a1;
        }

        // ---- pack P (hi/lo) from sc_ ----
        unsigned pkh[4][4], pkl[4][4];
        #pragma unroll
        for (int ks = 0; ks < 4; ks++) {
            float a0h0 = __bfloat162float(__float2bfloat16_rn(sc_[2*ks][0]));
            float a0h1 = __bfloat162float(__float2bfloat16_rn(sc_[2*ks][1]));
            float a1h0 = __bfloat162float(__float2bfloat16_rn(sc_[2*ks][2]));
            float a1h1 = __bfloat162float(__float2bfloat16_rn(sc_[2*ks][3]));
            float b0h0 = __bfloat162float(__float2bfloat16_rn(sc_[2*ks+1][0]));
            float b0h1 = __bfloat162float(__float2bfloat16_rn(sc_[2*ks+1][1]));
            float b1h0 = __bfloat162float(__float2bfloat16_rn(sc_[2*ks+1][2]));
            float b1h1 = __bfloat162float(__float2bfloat16_rn(sc_[2*ks+1][3]));
            pkh[ks][0] = pack_bf16x2(a0h0, a0h1);
            pkh[ks][1] = pack_bf16x2(a1h0, a1h1);
            pkh[ks][2] = pack_bf16x2(b0h0, b0h1);
            pkh[ks][3] = pack_bf16x2(b1h0, b1h1);
            pkl[ks][0] = pack_bf16x2(sc_[2*ks][0] - a0h0,   sc_[2*ks][1] - a0h1);
            pkl[ks][1] = pack_bf16x2(sc_[2*ks][2] - a1h0,   sc_[2*ks][3] - a1h1);
            pkl[ks][2] = pack_bf16x2(sc_[2*ks+1][0] - b0h0, sc_[2*ks+1][1] - b0h1);
            pkl[ks][3] = pack_bf16x2(sc_[2*ks+1][2] - b1h0, sc_[2*ks+1][3] - b1h1);
        }

        // ---- pipelined S for tile kt+1 (sc_ is dead; stage kt+1 ensured) ----
        if (kt + 1 < nkt) {
            asm volatile("cp.async.wait_group 1;\n" ::: "memory");
            __syncthreads();
            computeS(kt + 1);
        }

        // ---- O += Ph*Vh + Pl*Vh + Ph*Vl (tile kt) ----
        #pragma unroll
        for (int ks = 0; ks < 4; ks++) {
            int sl = ks * 16 + (lane & 15);
            unsigned vrowh = sVh + (unsigned)(sl * 128);
            unsigned vrowl = sVl + (unsigned)(sl * 128);
            unsigned swz   = (unsigned)((sl & 7) << 4);
            #pragma unroll
            for (int j = 0; j < 4; j++) {
                unsigned coff = ((unsigned)((2*j + (lane >> 4)) * 16)) ^ swz;
                unsigned vfh[4], vfl[4];
                LDSM4T(vfh, vrowh + coff);
                LDSM4T(vfl, vrowl + coff);
                mma_bf16(o[2*j],   pkh[ks], vfh[0], vfh[1]);
                mma_bf16(o[2*j+1], pkh[ks], vfh[2], vfh[3]);
                mma_bf16(o[2*j],   pkl[ks], vfh[0], vfh[1]);
                mma_bf16(o[2*j+1], pkl[ks], vfh[2], vfh[3]);
                mma_bf16(o[2*j],   pkh[ks], vfl[0], vfl[1]);
                mma_bf16(o[2*j+1], pkh[ks], vfl[2], vfl[3]);
            }
        }

        // Stage kt fully consumed; refill it for kt+3 (keep group count uniform).
        __syncthreads();
        if (kt + 3 < nkt) issue(kt + 3, st); else CP_COMMIT();
    }

    asm volatile("cp.async.wait_group 0;\n" ::: "memory");

    // ---- normalize + hi/lo split + store (row-major for Wo GEMM) ----
    float i0 = (l0 > 0.f) ? 1.f / l0 : 0.f;
    float i1 = (l1 > 0.f) ? 1.f / l1 : 0.f;
    size_t gr0 = (size_t)(b * SEQ + row0) * DM + h * HD;
    size_t gr1 = (size_t)(b * SEQ + row1) * DM + h * HD;
    #pragma unroll
    for (int j = 0; j < 8; j++) {
        int d = 8 * j + c2;
        float x0 = o[j][0] * i0, y0 = o[j][1] * i0;
        float x1 = o[j][2] * i1, y1 = o[j][3] * i1;
        float hx0 = __bfloat162float(__float2bfloat16_rn(x0));
        float hy0 = __bfloat162float(__float2bfloat16_rn(y0));
        float hx1 = __bfloat162float(__float2bfloat16_rn(x1));
        float hy1 = __bfloat162float(__float2bfloat16_rn(y1));
        *reinterpret_cast<unsigned*>(coh  + gr0 + d) = pack_bf16x2(hx0, hy0);
        *reinterpret_cast<unsigned*>(col_ + gr0 + d) = pack_bf16x2(x0 - hx0, y0 - hy0);
        *reinterpret_cast<unsigned*>(coh  + gr1 + d) = pack_bf16x2(hx1, hy1);
        *reinterpret_cast<unsigned*>(col_ + gr1 + d) = pack_bf16x2(x1 - hx1, y1 - hy1);
    }
}

// ---------------------------------------------------------------------------
extern "C" void kernel_launch(void* const* d_in, const int* in_sizes, int n_in,
                              void* d_out, int out_size)
{
    const float* Q  = (const float*)d_in[0];
    const float* K  = (const float*)d_in[1];
    const float* V  = (const float*)d_in[2];
    const int*   am = (const int*)  d_in[3];
    const float* Wq = (const float*)d_in[4];
    const float* Wk = (const float*)d_in[5];
    const float* Wv = (const float*)d_in[6];
    const float* Wo = (const float*)d_in[7];
    const float* bo = (const float*)d_in[8];
    float* out = (float*)d_out;

    __nv_bfloat16 *xh, *xl, *wh, *wl, *ah, *al, *qqh, *qql, *kkh, *kkl, *vvh, *vvl;
    float2* tab;
    cudaGetSymbolAddress((void**)&xh,  g_xh);
    cudaGetSymbolAddress((void**)&xl,  g_xl);
    cudaGetSymbolAddress((void**)&wh,  g_wh);
    cudaGetSymbolAddress((void**)&wl,  g_wl);
    cudaGetSymbolAddress((void**)&ah,  g_ah);
    cudaGetSymbolAddress((void**)&al,  g_al);
    cudaGetSymbolAddress((void**)&qqh, g_qh);
    cudaGetSymbolAddress((void**)&qql, g_ql);
    cudaGetSymbolAddress((void**)&kkh, g_kh);
    cudaGetSymbolAddress((void**)&kkl, g_kl);
    cudaGetSymbolAddress((void**)&vvh, g_vh);
    cudaGetSymbolAddress((void**)&vvl, g_vl);
    cudaGetSymbolAddress((void**)&tab, g_tab);

    const int n_split = 3 * NA4 + 4 * NB4;
    const size_t WN = (size_t)DM * DM;

    cudaFuncSetAttribute(gemm_qkv,
                         cudaFuncAttributeMaxDynamicSharedMemorySize, GEMM_SMEM);
    cudaFuncSetAttribute(gemm_out,
                         cudaFuncAttributeMaxDynamicSharedMemorySize, GEMM_SMEM);
    cudaFuncSetAttribute(attn_tc_kernel,
                         cudaFuncAttributeMaxDynamicSharedMemorySize, AT_SMEM);

    rope_tab_kernel<<<(SEQ * 32 + 255) / 256, 256>>>(tab);
    split_all_kernel<<<(n_split + 255) / 256, 256>>>(
        Q, K, V, Wq, Wk, Wv, Wo, xh, xl, wh, wl);

    // Batched Q/K/V projections (z selects matrix; rope for z<2)
    gemm_qkv<<<dim3(DM / 128, MROWS / 128, 3), 256, GEMM_SMEM>>>(
        xh, xl, wh, wl, tab, qqh, qql, kkh, kkl, vvh, vvl);

    // Tensor-core flash attention -> ctx split
    attn_tc_kernel<<<dim3(SEQ / 128, NH, BATCH), 256, AT_SMEM>>>(
        qqh, qql, kkh, kkl, vvh, vvl, am, ah, al);

    // Output projection
    gemm_out<<<dim3(DM / 128, MROWS / 128), 256, GEMM_SMEM>>>(
        ah, al, wh + 3*WN, wl + 3*WN, bo, out);
}